// round 12
// baseline (speedup 1.0000x reference)
#include <cuda_runtime.h>
#include <cuda_bf16.h>
#include <math.h>
#include <stdint.h>

// ---------------- problem constants ----------------
#define BATCH 2
#define SEQ   2048
#define DIM   2048
#define NH    16
#define HDIM  48
#define LAT   256
#define NLH   8
#define ROWS  (BATCH*SEQ)          // 4096
#define QW    (NH*HDIM)            // 768
#define KVW   (NLH*HDIM)           // 384
#define KVW2  (2*KVW)              // 768 (k|v concat)
#define QKVW  (QW+LAT)             // 1024 (q|kv concat)

// ---------------- scratch ----------------
__device__ float g_qkv  [ROWS * QKVW];   // [q | kv_latent] fp32
__device__ float g_kvout[ROWS * KVW2];   // [k|v] fp32

__device__ __nv_bfloat16 g_xh [ROWS * DIM], g_xl [ROWS * DIM];
__device__ __nv_bfloat16 g_kvh[ROWS * LAT], g_kvl[ROWS * LAT];
__device__ __nv_bfloat16 g_ah [ROWS * QW],  g_al [ROWS * QW];
// transposed bf16 split weights
__device__ __nv_bfloat16 g_wqkv_h[QKVW * DIM], g_wqkv_l[QKVW * DIM];   // [Wq^T ; Wkv^T]
__device__ __nv_bfloat16 g_wkv2_h[KVW2 * LAT], g_wkv2_l[KVW2 * LAT];   // [Wk^T ; Wv^T]
__device__ __nv_bfloat16 g_wo_h [DIM * QW],  g_wo_l [DIM * QW];
// attention layouts:  K: [b][kvh][t][hd]   Vt: [b][kvh][hd][t]
__device__ __nv_bfloat16 g_akh[BATCH*NLH*SEQ*HDIM], g_akl[BATCH*NLH*SEQ*HDIM];
__device__ __nv_bfloat16 g_avh[BATCH*NLH*HDIM*SEQ], g_avl[BATCH*NLH*HDIM*SEQ];

// ---------------- helpers ----------------
__device__ __forceinline__ uint32_t smem_u32(const void* p) {
    uint32_t a;
    asm("{ .reg .u64 t; cvta.to.shared.u64 t, %1; cvt.u32.u64 %0, t; }" : "=r"(a) : "l"(p));
    return a;
}

#define CP16(dst, src) \
    asm volatile("cp.async.cg.shared.global [%0], [%1], 16;" :: "r"(dst), "l"(src) : "memory")
#define CP_COMMIT() asm volatile("cp.async.commit_group;" ::: "memory")
#define CP_WAIT0()  asm volatile("cp.async.wait_group 0;" ::: "memory")
#define CP_WAIT1()  asm volatile("cp.async.wait_group 1;" ::: "memory")
#define CP_WAIT2()  asm volatile("cp.async.wait_group 2;" ::: "memory")

#define LDSM4(r0, r1, r2, r3, addr) \
    asm volatile("ldmatrix.sync.aligned.m8n8.x4.shared.b16 {%0,%1,%2,%3}, [%4];" \
        : "=r"(r0), "=r"(r1), "=r"(r2), "=r"(r3) : "r"(addr))

__device__ __forceinline__ void mma16816(float* c, const uint32_t* a, const uint32_t* b) {
    asm volatile(
        "mma.sync.aligned.m16n8k16.row.col.f32.bf16.bf16.f32 "
        "{%0,%1,%2,%3}, {%4,%5,%6,%7}, {%8,%9}, {%0,%1,%2,%3};"
        : "+f"(c[0]), "+f"(c[1]), "+f"(c[2]), "+f"(c[3])
        : "r"(a[0]), "r"(a[1]), "r"(a[2]), "r"(a[3]), "r"(b[0]), "r"(b[1]));
}

__device__ __forceinline__ void split2(float x, float y, uint32_t& h, uint32_t& l) {
    __nv_bfloat162 hb = __floats2bfloat162_rn(x, y);
    h = *reinterpret_cast<uint32_t*>(&hb);
    float hx = __bfloat162float(__low2bfloat16(hb));
    float hy = __bfloat162float(__high2bfloat16(hb));
    __nv_bfloat162 lb = __floats2bfloat162_rn(x - hx, y - hy);
    l = *reinterpret_cast<uint32_t*>(&lb);
}

__device__ __forceinline__ float exp2_fast(float x) {
    float r;
    asm("ex2.approx.ftz.f32 %0, %1;" : "=f"(r) : "f"(x));
    return r;
}

// ---------------- common GEMM tile constants ----------------
#define GM 128
#define GK 32
#define ROWB 80

// ===== 256-thread 128x128 GEMM (C ld passed as 'ldc') =====
#define GN 128
#define T_A  (128 * ROWB)
#define OFF_AH 0
#define OFF_AL (T_A)
#define OFF_BH (2*T_A)
#define OFF_BL (3*T_A)
#define STAGE  (4*T_A)
#define SMEM_GEMM (2*STAGE)

__device__ __forceinline__ void stage_load(
    const char* Ah, const char* Al, const char* Bh, const char* Bl,
    uint32_t sbase, int tid, int m0, int n0, int k0, int K)
{
    #pragma unroll
    for (int u = 0; u < 2; u++) {
        const int s   = tid * 2 + u;
        const int row = s >> 2;
        const int cc  = s & 3;
        const uint32_t so = row * ROWB + cc * 16;
        const size_t gA = ((size_t)(m0 + row) * K + k0) * 2 + cc * 16;
        const size_t gB = ((size_t)(n0 + row) * K + k0) * 2 + cc * 16;
        CP16(sbase + OFF_AH + so, Ah + gA);
        CP16(sbase + OFF_AL + so, Al + gA);
        CP16(sbase + OFF_BH + so, Bh + gB);
        CP16(sbase + OFF_BL + so, Bl + gB);
    }
}

__global__ __launch_bounds__(256, 2)
void gemm_mma(const __nv_bfloat16* __restrict__ Ahi, const __nv_bfloat16* __restrict__ Alo,
              const __nv_bfloat16* __restrict__ Bhi, const __nv_bfloat16* __restrict__ Blo,
              float* __restrict__ C, int K, int ldc) {
    extern __shared__ char smem[];
    const uint32_t sb = smem_u32(smem);
    const int tid = threadIdx.x;
    const int wid = tid >> 5, lid = tid & 31;
    const int wm = wid >> 2;
    const int wn = wid & 3;
    const int g = lid >> 2, ctg = lid & 3;
    const int mat = lid >> 3, mr = lid & 7;
    const int m0 = blockIdx.y * GM;
    const int n0 = blockIdx.x * GN;

    float acc[4][4][4];
    #pragma unroll
    for (int i = 0; i < 4; i++)
        #pragma unroll
        for (int j = 0; j < 4; j++)
            #pragma unroll
            for (int t = 0; t < 4; t++) acc[i][j][t] = 0.0f;

    const int nch = K / GK;
    stage_load((const char*)Ahi, (const char*)Alo, (const char*)Bhi, (const char*)Blo,
               sb, tid, m0, n0, 0, K);
    CP_COMMIT();

    const uint32_t aoff = (uint32_t)((wm * 64 + ((mat & 1) << 3) + mr) * ROWB + ((mat >> 1) << 4));
    const uint32_t boff = (uint32_t)((wn * 32 + ((mat >> 1) << 3) + mr) * ROWB + ((mat & 1) << 4));

    for (int c = 0; c < nch; c++) {
        if (c + 1 < nch) {
            stage_load((const char*)Ahi, (const char*)Alo, (const char*)Bhi, (const char*)Blo,
                       sb + ((c + 1) & 1) * STAGE, tid, m0, n0, (c + 1) * GK, K);
            CP_COMMIT();
            CP_WAIT1();
        } else {
            CP_WAIT0();
        }
        __syncthreads();

        const uint32_t sAh = sb + (c & 1) * STAGE + OFF_AH;
        const uint32_t sAl = sb + (c & 1) * STAGE + OFF_AL;
        const uint32_t sBh = sb + (c & 1) * STAGE + OFF_BH;
        const uint32_t sBl = sb + (c & 1) * STAGE + OFF_BL;

        #pragma unroll
        for (int ks = 0; ks < 2; ks++) {
            uint32_t bh[4][2], bl[4][2];
            #pragma unroll
            for (int jp = 0; jp < 2; jp++) {
                const uint32_t ba = boff + jp * 16 * ROWB + ks * 32;
                LDSM4(bh[2*jp][0], bh[2*jp][1], bh[2*jp+1][0], bh[2*jp+1][1], sBh + ba);
                LDSM4(bl[2*jp][0], bl[2*jp][1], bl[2*jp+1][0], bl[2*jp+1][1], sBl + ba);
            }
            #pragma unroll
            for (int i = 0; i < 4; i++) {
                const uint32_t aa = aoff + i * 16 * ROWB + ks * 32;
                uint32_t ah[4], al[4];
                LDSM4(ah[0], ah[1], ah[2], ah[3], sAh + aa);
                LDSM4(al[0], al[1], al[2], al[3], sAl + aa);
                #pragma unroll
                for (int j = 0; j < 4; j++) {
                    mma16816(acc[i][j], ah, bh[j]);
                    mma16816(acc[i][j], ah, bl[j]);
                    mma16816(acc[i][j], al, bh[j]);
                }
            }
        }
        __syncthreads();
    }

    #pragma unroll
    for (int i = 0; i < 4; i++) {
        const int r0 = m0 + wm * 64 + i * 16 + g;
        #pragma unroll
        for (int j = 0; j < 4; j++) {
            const int c0 = n0 + wn * 32 + j * 8 + ctg * 2;
            float2 v0 = make_float2(acc[i][j][0], acc[i][j][1]);
            float2 v1 = make_float2(acc[i][j][2], acc[i][j][3]);
            *(float2*)(C + (size_t)r0 * ldc + c0)       = v0;
            *(float2*)(C + (size_t)(r0 + 8) * ldc + c0) = v1;
        }
    }
}

// ===== 512-thread 128x256 GEMM (C ld passed as 'ldc') =====
#define G2N 256
#define OFF2_AH 0
#define OFF2_AL (128*ROWB)                 // 10240
#define OFF2_BH (2*128*ROWB)               // 20480
#define OFF2_BL (2*128*ROWB + 256*ROWB)    // 40960
#define STAGE2  (61440)
#define SMEM_GEMM2 (2*STAGE2)              // 122880

__device__ __forceinline__ void stage_load2(
    const char* Ah, const char* Al, const char* Bh, const char* Bl,
    uint32_t sbase, int tid, int m0, int n0, int k0, int K)
{
    {
        const int row = tid >> 2;
        const int cc  = tid & 3;
        const uint32_t so = row * ROWB + cc * 16;
        const size_t gA = ((size_t)(m0 + row) * K + k0) * 2 + cc * 16;
        CP16(sbase + OFF2_AH + so, Ah + gA);
        CP16(sbase + OFF2_AL + so, Al + gA);
    }
    #pragma unroll
    for (int u = 0; u < 2; u++) {
        const int s   = tid * 2 + u;
        const int row = s >> 2;
        const int cc  = s & 3;
        const uint32_t so = row * ROWB + cc * 16;
        const size_t gB = ((size_t)(n0 + row) * K + k0) * 2 + cc * 16;
        CP16(sbase + OFF2_BH + so, Bh + gB);
        CP16(sbase + OFF2_BL + so, Bl + gB);
    }
}

__global__ __launch_bounds__(512, 1)
void gemm_mma2(const __nv_bfloat16* __restrict__ Ahi, const __nv_bfloat16* __restrict__ Alo,
               const __nv_bfloat16* __restrict__ Bhi, const __nv_bfloat16* __restrict__ Blo,
               float* __restrict__ C, int K, int ldc) {
    extern __shared__ char smem[];
    const uint32_t sb = smem_u32(smem);
    const int tid = threadIdx.x;
    const int wid = tid >> 5, lid = tid & 31;
    const int wm = wid >> 3;
    const int wn = wid & 7;
    const int g = lid >> 2, ctg = lid & 3;
    const int mat = lid >> 3, mr = lid & 7;
    const int m0 = blockIdx.y * GM;
    const int n0 = blockIdx.x * G2N;

    float acc[4][4][4];
    #pragma unroll
    for (int i = 0; i < 4; i++)
        #pragma unroll
        for (int j = 0; j < 4; j++)
            #pragma unroll
            for (int t = 0; t < 4; t++) acc[i][j][t] = 0.0f;

    const int nch = K / GK;
    stage_load2((const char*)Ahi, (const char*)Alo, (const char*)Bhi, (const char*)Blo,
                sb, tid, m0, n0, 0, K);
    CP_COMMIT();

    const uint32_t aoff = (uint32_t)((wm * 64 + ((mat & 1) << 3) + mr) * ROWB + ((mat >> 1) << 4));
    const uint32_t boff = (uint32_t)((wn * 32 + ((mat >> 1) << 3) + mr) * ROWB + ((mat & 1) << 4));

    for (int c = 0; c < nch; c++) {
        if (c + 1 < nch) {
            stage_load2((const char*)Ahi, (const char*)Alo, (const char*)Bhi, (const char*)Blo,
                        sb + ((c + 1) & 1) * STAGE2, tid, m0, n0, (c + 1) * GK, K);
            CP_COMMIT();
            CP_WAIT1();
        } else {
            CP_WAIT0();
        }
        __syncthreads();

        const uint32_t sAh = sb + (c & 1) * STAGE2 + OFF2_AH;
        const uint32_t sAl = sb + (c & 1) * STAGE2 + OFF2_AL;
        const uint32_t sBh = sb + (c & 1) * STAGE2 + OFF2_BH;
        const uint32_t sBl = sb + (c & 1) * STAGE2 + OFF2_BL;

        #pragma unroll
        for (int ks = 0; ks < 2; ks++) {
            uint32_t bh[4][2], bl[4][2];
            #pragma unroll
            for (int jp = 0; jp < 2; jp++) {
                const uint32_t ba = boff + jp * 16 * ROWB + ks * 32;
                LDSM4(bh[2*jp][0], bh[2*jp][1], bh[2*jp+1][0], bh[2*jp+1][1], sBh + ba);
                LDSM4(bl[2*jp][0], bl[2*jp][1], bl[2*jp+1][0], bl[2*jp+1][1], sBl + ba);
            }
            #pragma unroll
            for (int i = 0; i < 4; i++) {
                const uint32_t aa = aoff + i * 16 * ROWB + ks * 32;
                uint32_t ah[4], al[4];
                LDSM4(ah[0], ah[1], ah[2], ah[3], sAh + aa);
                LDSM4(al[0], al[1], al[2], al[3], sAl + aa);
                #pragma unroll
                for (int j = 0; j < 4; j++) {
                    mma16816(acc[i][j], ah, bh[j]);
                    mma16816(acc[i][j], ah, bl[j]);
                    mma16816(acc[i][j], al, bh[j]);
                }
            }
        }
        __syncthreads();
    }

    #pragma unroll
    for (int i = 0; i < 4; i++) {
        const int r0 = m0 + wm * 64 + i * 16 + g;
        #pragma unroll
        for (int j = 0; j < 4; j++) {
            const int c0 = n0 + wn * 32 + j * 8 + ctg * 2;
            float2 v0 = make_float2(acc[i][j][0], acc[i][j][1]);
            float2 v1 = make_float2(acc[i][j][2], acc[i][j][3]);
            *(float2*)(C + (size_t)r0 * ldc + c0)       = v0;
            *(float2*)(C + (size_t)(r0 + 8) * ldc + c0) = v1;
        }
    }
}

// ---------------- fp32 -> bf16 hi/lo split ----------------
__global__ __launch_bounds__(256)
void split_act(const float* __restrict__ in, __nv_bfloat16* __restrict__ hi,
               __nv_bfloat16* __restrict__ lo, int n4) {
    int i = blockIdx.x * 256 + threadIdx.x;
    if (i >= n4) return;
    float4 v = ((const float4*)in)[i];
    uint32_t h0, l0, h1, l1;
    split2(v.x, v.y, h0, l0);
    split2(v.z, v.w, h1, l1);
    ((uint32_t*)hi)[2 * i]     = h0;
    ((uint32_t*)hi)[2 * i + 1] = h1;
    ((uint32_t*)lo)[2 * i]     = l0;
    ((uint32_t*)lo)[2 * i + 1] = l1;
}

// ---------------- W[K,N] fp32 -> Wt[N,K] bf16 hi/lo ----------------
__global__ __launch_bounds__(256)
void transpose_split(const float* __restrict__ W, __nv_bfloat16* __restrict__ th,
                     __nv_bfloat16* __restrict__ tl, int K, int N) {
    __shared__ float ts[32][33];
    const int tx = threadIdx.x;
    const int ty = threadIdx.y;
    const int x0 = blockIdx.x * 32;
    const int y0 = blockIdx.y * 32;
    #pragma unroll
    for (int j = ty; j < 32; j += 8)
        ts[j][tx] = W[(size_t)(y0 + j) * N + x0 + tx];
    __syncthreads();
    #pragma unroll
    for (int j = ty; j < 32; j += 8) {
        float v = ts[tx][j];
        __nv_bfloat16 h = __float2bfloat16(v);
        __nv_bfloat16 l = __float2bfloat16(v - __bfloat162float(h));
        size_t o = (size_t)(x0 + j) * K + y0 + tx;
        th[o] = h;
        tl[o] = l;
    }
}

// ---------------- fused RMSNorm + bf16 split (warp-shuffle reduction) ------
__global__ __launch_bounds__(256)
void rmsnorm_split(const float* __restrict__ qkv, const float* __restrict__ w,
                   __nv_bfloat16* __restrict__ oh, __nv_bfloat16* __restrict__ ol) {
    const int row = blockIdx.x;
    const int tid = threadIdx.x;
    const int wid = tid >> 5, lane = tid & 31;
    float v = qkv[(size_t)row * QKVW + QW + tid];
    float s = v * v;
    #pragma unroll
    for (int d = 16; d > 0; d >>= 1) s += __shfl_xor_sync(0xffffffffu, s, d);
    __shared__ float ws[8];
    if (lane == 0) ws[wid] = s;
    __syncthreads();
    float tot = ws[0] + ws[1] + ws[2] + ws[3] + ws[4] + ws[5] + ws[6] + ws[7];
    float inv = rsqrtf(tot * (1.0f / LAT) + 1e-5f);
    float r = v * inv * w[tid];
    __nv_bfloat16 h = __float2bfloat16(r);
    __nv_bfloat16 l = __float2bfloat16(r - __bfloat162float(h));
    oh[(size_t)row * LAT + tid] = h;
    ol[(size_t)row * LAT + tid] = l;
}

// ---------------- merged K/V reorg (single pass over kvout) ----------------
__global__ __launch_bounds__(256)
void reorg_kv(const float* __restrict__ kvin,
              __nv_bfloat16* __restrict__ kh, __nv_bfloat16* __restrict__ kl,
              __nv_bfloat16* __restrict__ vh, __nv_bfloat16* __restrict__ vl) {
    __shared__ float vs[64][HDIM + 1];
    const int bkvh = blockIdx.y;
    const int b = bkvh / NLH, kvh = bkvh % NLH;
    const int t0 = blockIdx.x * 64;
    for (int i = threadIdx.x; i < 64 * HDIM; i += 256) {
        const int t = i / HDIM, hd = i % HDIM;
        const size_t src = ((size_t)(b * SEQ + t0 + t)) * KVW2 + kvh * HDIM + hd;
        float kvval = kvin[src];
        __nv_bfloat16 h = __float2bfloat16(kvval);
        __nv_bfloat16 l = __float2bfloat16(kvval - __bfloat162float(h));
        size_t o = ((size_t)bkvh * SEQ + t0 + t) * HDIM + hd;
        kh[o] = h; kl[o] = l;
        vs[t][hd] = kvin[src + KVW];
    }
    __syncthreads();
    for (int i = threadIdx.x; i < 64 * HDIM; i += 256) {
        const int hd = i / 64, t = i % 64;
        float v = vs[t][hd];
        __nv_bfloat16 h = __float2bfloat16(v);
        __nv_bfloat16 l = __float2bfloat16(v - __bfloat162float(h));
        size_t o = ((size_t)bkvh * HDIM + hd) * SEQ + t0 + t;
        vh[o] = h; vl[o] = l;
    }
}

// ---------------- tensor-core causal flash attention (3-stage pipe) --------
#define KROWB 112
#define VROWB 144
#define A_KH 0
#define A_KL 7168
#define A_VH 14336
#define A_VL 21248
#define A_STAGE 28160
#define SMEM_ATT (3*A_STAGE)   // 84480

__device__ __forceinline__ void attn_stage(
    uint32_t sbase, const __nv_bfloat16* kb, const __nv_bfloat16* kbl,
    const __nv_bfloat16* vb, const __nv_bfloat16* vbl, int tid)
{
    #pragma unroll
    for (int t = 0; t < 6; t++) {
        const int c = tid + t * 256;
        const int arr = c / 384;
        const int idx = c - arr * 384;
        if (arr < 2) {
            const int r = idx / 6, qd = idx - r * 6;
            const uint32_t so = (arr == 0 ? A_KH : A_KL) + r * KROWB + qd * 16;
            const __nv_bfloat16* gp = (arr == 0 ? kb : kbl) + r * HDIM + qd * 8;
            CP16(sbase + so, gp);
        } else {
            const int r = idx / 8, qd = idx - r * 8;
            const uint32_t so = (arr == 2 ? A_VH : A_VL) + r * VROWB + qd * 16;
            const __nv_bfloat16* gp = (arr == 2 ? vb : vbl) + (size_t)r * SEQ + qd * 8;
            CP16(sbase + so, gp);
        }
    }
}

__global__ __launch_bounds__(256, 2)
void attn_mma(const float* __restrict__ q,
              const __nv_bfloat16* __restrict__ kh, const __nv_bfloat16* __restrict__ kl,
              const __nv_bfloat16* __restrict__ vth, const __nv_bfloat16* __restrict__ vtl,
              __nv_bfloat16* __restrict__ oah, __nv_bfloat16* __restrict__ oal) {
    extern __shared__ char smem[];
    const uint32_t sb = smem_u32(smem);

    const int qt = gridDim.x - 1 - blockIdx.x;        // longest first
    const int bh = blockIdx.y;
    const int b = bh / NH, hq = bh % NH;
    const int bkvh = b * NLH + hq / (NH / NLH);
    const int tid = threadIdx.x;
    const int wid = tid >> 5, lid = tid & 31;
    const int g = lid >> 2, cq = lid & 3;
    const int mat = lid >> 3, mr = lid & 7;
    const int qbase = qt * 128 + wid * 16;
    const float scale = rsqrtf((float)HDIM) * 1.44269504088896340736f;

    uint32_t aqh[3][4], aql[3][4];
    {
        const float* qp0 = q + ((size_t)(b * SEQ + qbase + g)) * QKVW + hq * HDIM;
        const float* qp1 = q + ((size_t)(b * SEQ + qbase + g + 8)) * QKVW + hq * HDIM;
        #pragma unroll
        for (int kk = 0; kk < 3; kk++) {
            float2 f0 = *(const float2*)(qp0 + kk * 16 + 2 * cq);
            float2 f1 = *(const float2*)(qp1 + kk * 16 + 2 * cq);
            float2 f2 = *(const float2*)(qp0 + kk * 16 + 2 * cq + 8);
            float2 f3 = *(const float2*)(qp1 + kk * 16 + 2 * cq + 8);
            split2(f0.x * scale, f0.y * scale, aqh[kk][0], aql[kk][0]);
            split2(f1.x * scale, f1.y * scale, aqh[kk][1], aql[kk][1]);
            split2(f2.x * scale, f2.y * scale, aqh[kk][2], aql[kk][2]);
            split2(f3.x * scale, f3.y * scale, aqh[kk][3], aql[kk][3]);
        }
    }

    float o[6][4];
    #pragma unroll
    for (int jn = 0; jn < 6; jn++)
        #pragma unroll
        for (int t = 0; t < 4; t++) o[jn][t] = 0.0f;
    float m0 = -1e30f, m1 = -1e30f, l0 = 0.0f, l1 = 0.0f;

    const __nv_bfloat16* kB  = kh  + (size_t)bkvh * SEQ * HDIM;
    const __nv_bfloat16* kBl = kl  + (size_t)bkvh * SEQ * HDIM;
    const __nv_bfloat16* vB  = vth + (size_t)bkvh * HDIM * SEQ;
    const __nv_bfloat16* vBl = vtl + (size_t)bkvh * HDIM * SEQ;

    const uint32_t kboff = (uint32_t)((((mat >> 1) << 3) + mr) * KROWB + ((mat & 1) << 4));
    const uint32_t vboff = (uint32_t)((((mat >> 1) << 3) + mr) * VROWB + ((mat & 1) << 4));

    const int nkt = 2 * qt + 2;
    attn_stage(sb, kB, kBl, vB, vBl, tid);
    CP_COMMIT();
    attn_stage(sb + A_STAGE, kB + 64 * HDIM, kBl + 64 * HDIM, vB + 64, vBl + 64, tid);
    CP_COMMIT();

    int buf = 0;
    for (int kt = 0; kt < nkt; kt++) {
        if (kt + 2 < nkt) {
            const int nb = (buf + 2) % 3;
            attn_stage(sb + nb * A_STAGE,
                       kB + (kt + 2) * 64 * HDIM, kBl + (kt + 2) * 64 * HDIM,
                       vB + (kt + 2) * 64, vBl + (kt + 2) * 64, tid);
            CP_COMMIT();
            CP_WAIT2();
        } else if (kt + 1 < nkt) {
            CP_WAIT1();
        } else {
            CP_WAIT0();
        }
        __syncthreads();

        const bool full_skip = (kt * 64 > qbase + 15);
        if (!full_skip) {
            const uint32_t st = sb + buf * A_STAGE;
            const uint32_t sKh = st + A_KH, sKl = st + A_KL;
            const uint32_t sVh = st + A_VH, sVl = st + A_VL;

            float p[8][4];
            #pragma unroll
            for (int j = 0; j < 8; j++)
                p[j][0] = p[j][1] = p[j][2] = p[j][3] = 0.0f;
            #pragma unroll
            for (int kk = 0; kk < 3; kk++) {
                #pragma unroll
                for (int jp = 0; jp < 4; jp++) {
                    const uint32_t ba = kboff + jp * 16 * KROWB + kk * 32;
                    uint32_t bh2[2][2], bl2[2][2];
                    LDSM4(bh2[0][0], bh2[0][1], bh2[1][0], bh2[1][1], sKh + ba);
                    LDSM4(bl2[0][0], bl2[0][1], bl2[1][0], bl2[1][1], sKl + ba);
                    mma16816(p[2*jp],   aqh[kk], bh2[0]);
                    mma16816(p[2*jp],   aqh[kk], bl2[0]);
                    mma16816(p[2*jp],   aql[kk], bh2[0]);
                    mma16816(p[2*jp+1], aqh[kk], bh2[1]);
                    mma16816(p[2*jp+1], aqh[kk], bl2[1]);
                    mma16816(p[2*jp+1], aql[kk], bh2[1]);
                }
            }

            if (kt * 64 + 63 > qbase) {
                const int qr0 = qbase + g;
                #pragma unroll
                for (int j = 0; j < 8; j++) {
                    const int key0 = kt * 64 + j * 8 + 2 * cq;
                    if (key0 > qr0)         p[j][0] = -1e30f;
                    if (key0 + 1 > qr0)     p[j][1] = -1e30f;
                    if (key0 > qr0 + 8)     p[j][2] = -1e30f;
                    if (key0 + 1 > qr0 + 8) p[j][3] = -1e30f;
                }
            }

            float mx0 = -1e30f, mx1 = -1e30f;
            #pragma unroll
            for (int j = 0; j < 8; j++) {
                mx0 = fmaxf(mx0, fmaxf(p[j][0], p[j][1]));
                mx1 = fmaxf(mx1, fmaxf(p[j][2], p[j][3]));
            }
            mx0 = fmaxf(mx0, __shfl_xor_sync(0xffffffffu, mx0, 1));
            mx0 = fmaxf(mx0, __shfl_xor_sync(0xffffffffu, mx0, 2));
            mx1 = fmaxf(mx1, __shfl_xor_sync(0xffffffffu, mx1, 1));
            mx1 = fmaxf(mx1, __shfl_xor_sync(0xffffffffu, mx1, 2));
            const float mn0 = fmaxf(m0, mx0), mn1 = fmaxf(m1, mx1);
            const float cr0 = exp2_fast(m0 - mn0), cr1 = exp2_fast(m1 - mn1);
            m0 = mn0; m1 = mn1;
            l0 *= cr0; l1 *= cr1;
            #pragma unroll
            for (int jn = 0; jn < 6; jn++) {
                o[jn][0] *= cr0; o[jn][1] *= cr0;
                o[jn][2] *= cr1; o[jn][3] *= cr1;
            }
            #pragma unroll
            for (int j = 0; j < 8; j++) {
                p[j][0] = exp2_fast(p[j][0] - m0);
                p[j][1] = exp2_fast(p[j][1] - m0);
                p[j][2] = exp2_fast(p[j][2] - m1);
                p[j][3] = exp2_fast(p[j][3] - m1);
                l0 += p[j][0] + p[j][1];
                l1 += p[j][2] + p[j][3];
            }

            #pragma unroll
            for (int kc = 0; kc < 4; kc++) {
                uint32_t aPh[4], aPl[4];
                split2(p[2 * kc][0],     p[2 * kc][1],     aPh[0], aPl[0]);
                split2(p[2 * kc][2],     p[2 * kc][3],     aPh[1], aPl[1]);
                split2(p[2 * kc + 1][0], p[2 * kc + 1][1], aPh[2], aPl[2]);
                split2(p[2 * kc + 1][2], p[2 * kc + 1][3], aPh[3], aPl[3]);
                #pragma unroll
                for (int jp = 0; jp < 3; jp++) {
                    const uint32_t ba = vboff + jp * 16 * VROWB + kc * 32;
                    uint32_t bh2[2][2], bl2[2][2];
                    LDSM4(bh2[0][0], bh2[0][1], bh2[1][0], bh2[1][1], sVh + ba);
                    LDSM4(bl2[0][0], bl2[0][1], bl2[1][0], bl2[1][1], sVl + ba);
                    mma16816(o[2*jp],   aPh, bh2[0]);
                    mma16816(o[2*jp],   aPh, bl2[0]);
                    mma16816(o[2*jp],   aPl, bh2[0]);
                    mma16816(o[2*jp+1], aPh, bh2[1]);
                    mma16816(o[2*jp+1], aPh, bl2[1]);
                    mma16816(o[2*jp+1], aPl, bh2[1]);
                }
            }
        }
        __syncthreads();
        buf = (buf + 1 == 3) ? 0 : (buf + 1);
    }

    l0 += __shfl_xor_sync(0xffffffffu, l0, 1);
    l0 += __shfl_xor_sync(0xffffffffu, l0, 2);
    l1 += __shfl_xor_sync(0xffffffffu, l1, 1);
    l1 += __shfl_xor_sync(0xffffffffu, l1, 2);
    const float inv0 = 1.0f / l0, inv1 = 1.0f / l1;

    const size_t base0 = ((size_t)(b * SEQ + qbase + g)) * QW + hq * HDIM;
    const size_t base1 = ((size_t)(b * SEQ + qbase + g + 8)) * QW + hq * HDIM;
    #pragma unroll
    for (int jn = 0; jn < 6; jn++) {
        uint32_t hb, lb;
        split2(o[jn][0] * inv0, o[jn][1] * inv0, hb, lb);
        *(uint32_t*)&oah[base0 + jn * 8 + 2 * cq] = hb;
        *(uint32_t*)&oal[base0 + jn * 8 + 2 * cq] = lb;
        split2(o[jn][2] * inv1, o[jn][3] * inv1, hb, lb);
        *(uint32_t*)&oah[base1 + jn * 8 + 2 * cq] = hb;
        *(uint32_t*)&oal[base1 + jn * 8 + 2 * cq] = lb;
    }
}

// ---------------- launch ----------------
extern "C" void kernel_launch(void* const* d_in, const int* in_sizes, int n_in,
                              void* d_out, int out_size) {
    const float* x      = (const float*)d_in[0];
    const float* Wq     = (const float*)d_in[2];
    const float* Wkv    = (const float*)d_in[3];
    const float* w_norm = (const float*)d_in[4];
    const float* Wk     = (const float*)d_in[5];
    const float* Wv     = (const float*)d_in[6];
    const float* Wo     = (const float*)d_in[7];
    float* out = (float*)d_out;

    float *qkv, *kvout;
    cudaGetSymbolAddress((void**)&qkv,   g_qkv);
    cudaGetSymbolAddress((void**)&kvout, g_kvout);

    __nv_bfloat16 *xh, *xl, *kvh, *kvl, *ah, *al;
    __nv_bfloat16 *wqkvh, *wqkvl, *wk2h, *wk2l, *woh, *wol;
    __nv_bfloat16 *akh, *akl, *avh, *avl;
    cudaGetSymbolAddress((void**)&xh,  g_xh);     cudaGetSymbolAddress((void**)&xl,  g_xl);
    cudaGetSymbolAddress((void**)&kvh, g_kvh);    cudaGetSymbolAddress((void**)&kvl, g_kvl);
    cudaGetSymbolAddress((void**)&ah,  g_ah);     cudaGetSymbolAddress((void**)&al,  g_al);
    cudaGetSymbolAddress((void**)&wqkvh, g_wqkv_h); cudaGetSymbolAddress((void**)&wqkvl, g_wqkv_l);
    cudaGetSymbolAddress((void**)&wk2h, g_wkv2_h);  cudaGetSymbolAddress((void**)&wk2l, g_wkv2_l);
    cudaGetSymbolAddress((void**)&woh, g_wo_h);   cudaGetSymbolAddress((void**)&wol, g_wo_l);
    cudaGetSymbolAddress((void**)&akh, g_akh);    cudaGetSymbolAddress((void**)&akl, g_akl);
    cudaGetSymbolAddress((void**)&avh, g_avh);    cudaGetSymbolAddress((void**)&avl, g_avl);

    static cudaStream_t s2 = 0;
    static cudaEvent_t evRoot = 0, evW = 0, evX = 0, evKVD = 0, evWo = 0;
    if (!s2) {
        cudaFuncSetAttribute(gemm_mma,  cudaFuncAttributeMaxDynamicSharedMemorySize, SMEM_GEMM);
        cudaFuncSetAttribute(gemm_mma2, cudaFuncAttributeMaxDynamicSharedMemorySize, SMEM_GEMM2);
        cudaFuncSetAttribute(attn_mma,  cudaFuncAttributeMaxDynamicSharedMemorySize, SMEM_ATT);
        cudaStreamCreateWithFlags(&s2, cudaStreamNonBlocking);
        cudaEventCreateWithFlags(&evRoot, cudaEventDisableTiming);
        cudaEventCreateWithFlags(&evW, cudaEventDisableTiming);
        cudaEventCreateWithFlags(&evX, cudaEventDisableTiming);
        cudaEventCreateWithFlags(&evKVD, cudaEventDisableTiming);
        cudaEventCreateWithFlags(&evWo, cudaEventDisableTiming);
    }

    dim3 t256(256);
    dim3 ttr(32, 8);

    // fork: weight transposes on s2, x split on main
    cudaEventRecord(evRoot, 0);
    cudaStreamWaitEvent(s2, evRoot, 0);

    transpose_split<<<dim3(QW / 32,  DIM / 32), ttr, 0, s2>>>(Wq,  wqkvh, wqkvl, DIM, QW);
    transpose_split<<<dim3(LAT / 32, DIM / 32), ttr, 0, s2>>>(Wkv, wqkvh + (size_t)QW * DIM,
                                                              wqkvl + (size_t)QW * DIM, DIM, LAT);
    cudaEventRecord(evW, s2);
    transpose_split<<<dim3(KVW / 32, LAT / 32), ttr, 0, s2>>>(Wk, wk2h, wk2l, LAT, KVW);
    transpose_split<<<dim3(KVW / 32, LAT / 32), ttr, 0, s2>>>(Wv, wk2h + (size_t)KVW * LAT,
                                                              wk2l + (size_t)KVW * LAT, LAT, KVW);

    split_act<<<(ROWS * DIM / 4 + 255) / 256, t256>>>(x, xh, xl, ROWS * DIM / 4);
    cudaEventRecord(evX, 0);

    // ---- CONCURRENT qkv column halves ----
    // s2: kv columns (small: 64 CTAs @256thr) then the whole kv chain
    cudaStreamWaitEvent(s2, evX, 0);
    gemm_mma<<<dim3(LAT / GN, ROWS / GM), t256, SMEM_GEMM, s2>>>(
        xh, xl, wqkvh + (size_t)QW * DIM, wqkvl + (size_t)QW * DIM, qkv + QW, DIM, QKVW);
    rmsnorm_split<<<ROWS, LAT, 0, s2>>>(qkv, w_norm, kvh, kvl);
    gemm_mma<<<dim3(KVW2 / GN, ROWS / GM), t256, SMEM_GEMM, s2>>>(
        kvh, kvl, wk2h, wk2l, kvout, LAT, KVW2);
    reorg_kv<<<dim3(SEQ / 64, BATCH * NLH), t256, 0, s2>>>(kvout, akh, akl, avh, avl);
    cudaEventRecord(evKVD, s2);
    // s2: Wo transpose after the kv chain (needed only at the very end)
    transpose_split<<<dim3(DIM / 32, QW / 32), ttr, 0, s2>>>(Wo, woh, wol, QW, DIM);
    cudaEventRecord(evWo, s2);

    // main: q columns (big: 96 CTAs @512thr) — runs concurrently with s2 kv chain
    cudaStreamWaitEvent(0, evW, 0);
    gemm_mma2<<<dim3(QW / G2N, ROWS / GM), 512, SMEM_GEMM2>>>(
        xh, xl, wqkvh, wqkvl, qkv, DIM, QKVW);

    // attention needs q (main) + k/v (s2)
    cudaStreamWaitEvent(0, evKVD, 0);
    attn_mma<<<dim3(SEQ / 128, BATCH * NH), t256, SMEM_ATT>>>(qkv, akh, akl, avh, avl, ah, al);

    // out = att @ Wo
    cudaStreamWaitEvent(0, evWo, 0);
    gemm_mma2<<<dim3(DIM / G2N, ROWS / GM), 512, SMEM_GEMM2>>>(ah, al, woh, wol, out, QW, DIM);
}

// round 13
// speedup vs baseline: 1.1139x; 1.1139x over previous
#include <cuda_runtime.h>
#include <cuda_bf16.h>
#include <cuda_fp16.h>
#include <math.h>
#include <stdint.h>

// ---------------- problem constants ----------------
#define BATCH 2
#define SEQ   2048
#define DIM   2048
#define NH    16
#define HDIM  48
#define LAT   256
#define NLH   8
#define ROWS  (BATCH*SEQ)          // 4096
#define QW    (NH*HDIM)            // 768
#define KVW   (NLH*HDIM)           // 384
#define KVW2  (2*KVW)              // 768 (k|v concat)
#define QKVW  (QW+LAT)             // 1024 (q|kv concat)

// ---------------- scratch ----------------
__device__ float g_qkv  [ROWS * QKVW];   // [q | kv_latent] fp32
__device__ float g_kvout[ROWS * KVW2];   // [k|v] fp32

__device__ __nv_bfloat16 g_xh [ROWS * DIM], g_xl [ROWS * DIM];
__device__ __nv_bfloat16 g_kvh[ROWS * LAT], g_kvl[ROWS * LAT];
__device__ __nv_bfloat16 g_ah [ROWS * QW],  g_al [ROWS * QW];
// transposed bf16 split weights
__device__ __nv_bfloat16 g_wqkv_h[QKVW * DIM], g_wqkv_l[QKVW * DIM];   // [Wq^T ; Wkv^T]
__device__ __nv_bfloat16 g_wkv2_h[KVW2 * LAT], g_wkv2_l[KVW2 * LAT];   // [Wk^T ; Wv^T]
__device__ __nv_bfloat16 g_wo_h [DIM * QW],  g_wo_l [DIM * QW];
// attention layouts:  K: [b][kvh][t][hd] bf16 hi/lo   Vt: [b][kvh][hd][t] fp16 single
__device__ __nv_bfloat16 g_akh[BATCH*NLH*SEQ*HDIM], g_akl[BATCH*NLH*SEQ*HDIM];
__device__ __half        g_avh[BATCH*NLH*HDIM*SEQ];

// ---------------- helpers ----------------
__device__ __forceinline__ uint32_t smem_u32(const void* p) {
    uint32_t a;
    asm("{ .reg .u64 t; cvta.to.shared.u64 t, %1; cvt.u32.u64 %0, t; }" : "=r"(a) : "l"(p));
    return a;
}

#define CP16(dst, src) \
    asm volatile("cp.async.cg.shared.global [%0], [%1], 16;" :: "r"(dst), "l"(src) : "memory")
#define CP_COMMIT() asm volatile("cp.async.commit_group;" ::: "memory")
#define CP_WAIT0()  asm volatile("cp.async.wait_group 0;" ::: "memory")
#define CP_WAIT1()  asm volatile("cp.async.wait_group 1;" ::: "memory")
#define CP_WAIT2()  asm volatile("cp.async.wait_group 2;" ::: "memory")

#define LDSM4(r0, r1, r2, r3, addr) \
    asm volatile("ldmatrix.sync.aligned.m8n8.x4.shared.b16 {%0,%1,%2,%3}, [%4];" \
        : "=r"(r0), "=r"(r1), "=r"(r2), "=r"(r3) : "r"(addr))

__device__ __forceinline__ void mma16816(float* c, const uint32_t* a, const uint32_t* b) {
    asm volatile(
        "mma.sync.aligned.m16n8k16.row.col.f32.bf16.bf16.f32 "
        "{%0,%1,%2,%3}, {%4,%5,%6,%7}, {%8,%9}, {%0,%1,%2,%3};"
        : "+f"(c[0]), "+f"(c[1]), "+f"(c[2]), "+f"(c[3])
        : "r"(a[0]), "r"(a[1]), "r"(a[2]), "r"(a[3]), "r"(b[0]), "r"(b[1]));
}

__device__ __forceinline__ void mma16816h(float* c, const uint32_t* a, const uint32_t* b) {
    asm volatile(
        "mma.sync.aligned.m16n8k16.row.col.f32.f16.f16.f32 "
        "{%0,%1,%2,%3}, {%4,%5,%6,%7}, {%8,%9}, {%0,%1,%2,%3};"
        : "+f"(c[0]), "+f"(c[1]), "+f"(c[2]), "+f"(c[3])
        : "r"(a[0]), "r"(a[1]), "r"(a[2]), "r"(a[3]), "r"(b[0]), "r"(b[1]));
}

__device__ __forceinline__ void split2(float x, float y, uint32_t& h, uint32_t& l) {
    __nv_bfloat162 hb = __floats2bfloat162_rn(x, y);
    h = *reinterpret_cast<uint32_t*>(&hb);
    float hx = __bfloat162float(__low2bfloat16(hb));
    float hy = __bfloat162float(__high2bfloat16(hb));
    __nv_bfloat162 lb = __floats2bfloat162_rn(x - hx, y - hy);
    l = *reinterpret_cast<uint32_t*>(&lb);
}

__device__ __forceinline__ uint32_t packh2(float x, float y) {
    __half2 h = __floats2half2_rn(x, y);
    return *reinterpret_cast<uint32_t*>(&h);
}

__device__ __forceinline__ float exp2_fast(float x) {
    float r;
    asm("ex2.approx.ftz.f32 %0, %1;" : "=f"(r) : "f"(x));
    return r;
}

// ---------------- common GEMM tile constants ----------------
#define GM 128
#define GK 32
#define ROWB 80

// ===== 256-thread 128x128 GEMM =====
#define GN 128
#define T_A  (128 * ROWB)
#define OFF_AH 0
#define OFF_AL (T_A)
#define OFF_BH (2*T_A)
#define OFF_BL (3*T_A)
#define STAGE  (4*T_A)
#define SMEM_GEMM (2*STAGE)

__device__ __forceinline__ void stage_load(
    const char* Ah, const char* Al, const char* Bh, const char* Bl,
    uint32_t sbase, int tid, int m0, int n0, int k0, int K)
{
    #pragma unroll
    for (int u = 0; u < 2; u++) {
        const int s   = tid * 2 + u;
        const int row = s >> 2;
        const int cc  = s & 3;
        const uint32_t so = row * ROWB + cc * 16;
        const size_t gA = ((size_t)(m0 + row) * K + k0) * 2 + cc * 16;
        const size_t gB = ((size_t)(n0 + row) * K + k0) * 2 + cc * 16;
        CP16(sbase + OFF_AH + so, Ah + gA);
        CP16(sbase + OFF_AL + so, Al + gA);
        CP16(sbase + OFF_BH + so, Bh + gB);
        CP16(sbase + OFF_BL + so, Bl + gB);
    }
}

__global__ __launch_bounds__(256, 2)
void gemm_mma(const __nv_bfloat16* __restrict__ Ahi, const __nv_bfloat16* __restrict__ Alo,
              const __nv_bfloat16* __restrict__ Bhi, const __nv_bfloat16* __restrict__ Blo,
              float* __restrict__ C, int K, int ldc) {
    extern __shared__ char smem[];
    const uint32_t sb = smem_u32(smem);
    const int tid = threadIdx.x;
    const int wid = tid >> 5, lid = tid & 31;
    const int wm = wid >> 2;
    const int wn = wid & 3;
    const int g = lid >> 2, ctg = lid & 3;
    const int mat = lid >> 3, mr = lid & 7;
    const int m0 = blockIdx.y * GM;
    const int n0 = blockIdx.x * GN;

    float acc[4][4][4];
    #pragma unroll
    for (int i = 0; i < 4; i++)
        #pragma unroll
        for (int j = 0; j < 4; j++)
            #pragma unroll
            for (int t = 0; t < 4; t++) acc[i][j][t] = 0.0f;

    const int nch = K / GK;
    stage_load((const char*)Ahi, (const char*)Alo, (const char*)Bhi, (const char*)Blo,
               sb, tid, m0, n0, 0, K);
    CP_COMMIT();

    const uint32_t aoff = (uint32_t)((wm * 64 + ((mat & 1) << 3) + mr) * ROWB + ((mat >> 1) << 4));
    const uint32_t boff = (uint32_t)((wn * 32 + ((mat >> 1) << 3) + mr) * ROWB + ((mat & 1) << 4));

    for (int c = 0; c < nch; c++) {
        if (c + 1 < nch) {
            stage_load((const char*)Ahi, (const char*)Alo, (const char*)Bhi, (const char*)Blo,
                       sb + ((c + 1) & 1) * STAGE, tid, m0, n0, (c + 1) * GK, K);
            CP_COMMIT();
            CP_WAIT1();
        } else {
            CP_WAIT0();
        }
        __syncthreads();

        const uint32_t sAh = sb + (c & 1) * STAGE + OFF_AH;
        const uint32_t sAl = sb + (c & 1) * STAGE + OFF_AL;
        const uint32_t sBh = sb + (c & 1) * STAGE + OFF_BH;
        const uint32_t sBl = sb + (c & 1) * STAGE + OFF_BL;

        #pragma unroll
        for (int ks = 0; ks < 2; ks++) {
            uint32_t bh[4][2], bl[4][2];
            #pragma unroll
            for (int jp = 0; jp < 2; jp++) {
                const uint32_t ba = boff + jp * 16 * ROWB + ks * 32;
                LDSM4(bh[2*jp][0], bh[2*jp][1], bh[2*jp+1][0], bh[2*jp+1][1], sBh + ba);
                LDSM4(bl[2*jp][0], bl[2*jp][1], bl[2*jp+1][0], bl[2*jp+1][1], sBl + ba);
            }
            #pragma unroll
            for (int i = 0; i < 4; i++) {
                const uint32_t aa = aoff + i * 16 * ROWB + ks * 32;
                uint32_t ah[4], al[4];
                LDSM4(ah[0], ah[1], ah[2], ah[3], sAh + aa);
                LDSM4(al[0], al[1], al[2], al[3], sAl + aa);
                #pragma unroll
                for (int j = 0; j < 4; j++) {
                    mma16816(acc[i][j], ah, bh[j]);
                    mma16816(acc[i][j], ah, bl[j]);
                    mma16816(acc[i][j], al, bh[j]);
                }
            }
        }
        __syncthreads();
    }

    #pragma unroll
    for (int i = 0; i < 4; i++) {
        const int r0 = m0 + wm * 64 + i * 16 + g;
        #pragma unroll
        for (int j = 0; j < 4; j++) {
            const int c0 = n0 + wn * 32 + j * 8 + ctg * 2;
            float2 v0 = make_float2(acc[i][j][0], acc[i][j][1]);
            float2 v1 = make_float2(acc[i][j][2], acc[i][j][3]);
            *(float2*)(C + (size_t)r0 * ldc + c0)       = v0;
            *(float2*)(C + (size_t)(r0 + 8) * ldc + c0) = v1;
        }
    }
}

// ===== 512-thread 128x256 GEMM =====
#define G2N 256
#define OFF2_AH 0
#define OFF2_AL (128*ROWB)
#define OFF2_BH (2*128*ROWB)
#define OFF2_BL (2*128*ROWB + 256*ROWB)
#define STAGE2  (61440)
#define SMEM_GEMM2 (2*STAGE2)

__device__ __forceinline__ void stage_load2(
    const char* Ah, const char* Al, const char* Bh, const char* Bl,
    uint32_t sbase, int tid, int m0, int n0, int k0, int K)
{
    {
        const int row = tid >> 2;
        const int cc  = tid & 3;
        const uint32_t so = row * ROWB + cc * 16;
        const size_t gA = ((size_t)(m0 + row) * K + k0) * 2 + cc * 16;
        CP16(sbase + OFF2_AH + so, Ah + gA);
        CP16(sbase + OFF2_AL + so, Al + gA);
    }
    #pragma unroll
    for (int u = 0; u < 2; u++) {
        const int s   = tid * 2 + u;
        const int row = s >> 2;
        const int cc  = s & 3;
        const uint32_t so = row * ROWB + cc * 16;
        const size_t gB = ((size_t)(n0 + row) * K + k0) * 2 + cc * 16;
        CP16(sbase + OFF2_BH + so, Bh + gB);
        CP16(sbase + OFF2_BL + so, Bl + gB);
    }
}

__global__ __launch_bounds__(512, 1)
void gemm_mma2(const __nv_bfloat16* __restrict__ Ahi, const __nv_bfloat16* __restrict__ Alo,
               const __nv_bfloat16* __restrict__ Bhi, const __nv_bfloat16* __restrict__ Blo,
               float* __restrict__ C, int K, int ldc) {
    extern __shared__ char smem[];
    const uint32_t sb = smem_u32(smem);
    const int tid = threadIdx.x;
    const int wid = tid >> 5, lid = tid & 31;
    const int wm = wid >> 3;
    const int wn = wid & 7;
    const int g = lid >> 2, ctg = lid & 3;
    const int mat = lid >> 3, mr = lid & 7;
    const int m0 = blockIdx.y * GM;
    const int n0 = blockIdx.x * G2N;

    float acc[4][4][4];
    #pragma unroll
    for (int i = 0; i < 4; i++)
        #pragma unroll
        for (int j = 0; j < 4; j++)
            #pragma unroll
            for (int t = 0; t < 4; t++) acc[i][j][t] = 0.0f;

    const int nch = K / GK;
    stage_load2((const char*)Ahi, (const char*)Alo, (const char*)Bhi, (const char*)Blo,
                sb, tid, m0, n0, 0, K);
    CP_COMMIT();

    const uint32_t aoff = (uint32_t)((wm * 64 + ((mat & 1) << 3) + mr) * ROWB + ((mat >> 1) << 4));
    const uint32_t boff = (uint32_t)((wn * 32 + ((mat >> 1) << 3) + mr) * ROWB + ((mat & 1) << 4));

    for (int c = 0; c < nch; c++) {
        if (c + 1 < nch) {
            stage_load2((const char*)Ahi, (const char*)Alo, (const char*)Bhi, (const char*)Blo,
                        sb + ((c + 1) & 1) * STAGE2, tid, m0, n0, (c + 1) * GK, K);
            CP_COMMIT();
            CP_WAIT1();
        } else {
            CP_WAIT0();
        }
        __syncthreads();

        const uint32_t sAh = sb + (c & 1) * STAGE2 + OFF2_AH;
        const uint32_t sAl = sb + (c & 1) * STAGE2 + OFF2_AL;
        const uint32_t sBh = sb + (c & 1) * STAGE2 + OFF2_BH;
        const uint32_t sBl = sb + (c & 1) * STAGE2 + OFF2_BL;

        #pragma unroll
        for (int ks = 0; ks < 2; ks++) {
            uint32_t bh[4][2], bl[4][2];
            #pragma unroll
            for (int jp = 0; jp < 2; jp++) {
                const uint32_t ba = boff + jp * 16 * ROWB + ks * 32;
                LDSM4(bh[2*jp][0], bh[2*jp][1], bh[2*jp+1][0], bh[2*jp+1][1], sBh + ba);
                LDSM4(bl[2*jp][0], bl[2*jp][1], bl[2*jp+1][0], bl[2*jp+1][1], sBl + ba);
            }
            #pragma unroll
            for (int i = 0; i < 4; i++) {
                const uint32_t aa = aoff + i * 16 * ROWB + ks * 32;
                uint32_t ah[4], al[4];
                LDSM4(ah[0], ah[1], ah[2], ah[3], sAh + aa);
                LDSM4(al[0], al[1], al[2], al[3], sAl + aa);
                #pragma unroll
                for (int j = 0; j < 4; j++) {
                    mma16816(acc[i][j], ah, bh[j]);
                    mma16816(acc[i][j], ah, bl[j]);
                    mma16816(acc[i][j], al, bh[j]);
                }
            }
        }
        __syncthreads();
    }

    #pragma unroll
    for (int i = 0; i < 4; i++) {
        const int r0 = m0 + wm * 64 + i * 16 + g;
        #pragma unroll
        for (int j = 0; j < 4; j++) {
            const int c0 = n0 + wn * 32 + j * 8 + ctg * 2;
            float2 v0 = make_float2(acc[i][j][0], acc[i][j][1]);
            float2 v1 = make_float2(acc[i][j][2], acc[i][j][3]);
            *(float2*)(C + (size_t)r0 * ldc + c0)       = v0;
            *(float2*)(C + (size_t)(r0 + 8) * ldc + c0) = v1;
        }
    }
}

// ---------------- fp32 -> bf16 hi/lo split ----------------
__global__ __launch_bounds__(256)
void split_act(const float* __restrict__ in, __nv_bfloat16* __restrict__ hi,
               __nv_bfloat16* __restrict__ lo, int n4) {
    int i = blockIdx.x * 256 + threadIdx.x;
    if (i >= n4) return;
    float4 v = ((const float4*)in)[i];
    uint32_t h0, l0, h1, l1;
    split2(v.x, v.y, h0, l0);
    split2(v.z, v.w, h1, l1);
    ((uint32_t*)hi)[2 * i]     = h0;
    ((uint32_t*)hi)[2 * i + 1] = h1;
    ((uint32_t*)lo)[2 * i]     = l0;
    ((uint32_t*)lo)[2 * i + 1] = l1;
}

// ---------------- W[K,N] fp32 -> Wt[N,K] bf16 hi/lo ----------------
__global__ __launch_bounds__(256)
void transpose_split(const float* __restrict__ W, __nv_bfloat16* __restrict__ th,
                     __nv_bfloat16* __restrict__ tl, int K, int N) {
    __shared__ float ts[32][33];
    const int tx = threadIdx.x;
    const int ty = threadIdx.y;
    const int x0 = blockIdx.x * 32;
    const int y0 = blockIdx.y * 32;
    #pragma unroll
    for (int j = ty; j < 32; j += 8)
        ts[j][tx] = W[(size_t)(y0 + j) * N + x0 + tx];
    __syncthreads();
    #pragma unroll
    for (int j = ty; j < 32; j += 8) {
        float v = ts[tx][j];
        __nv_bfloat16 h = __float2bfloat16(v);
        __nv_bfloat16 l = __float2bfloat16(v - __bfloat162float(h));
        size_t o = (size_t)(x0 + j) * K + y0 + tx;
        th[o] = h;
        tl[o] = l;
    }
}

// ---------------- fused RMSNorm + bf16 split ----------------
__global__ __launch_bounds__(256)
void rmsnorm_split(const float* __restrict__ qkv, const float* __restrict__ w,
                   __nv_bfloat16* __restrict__ oh, __nv_bfloat16* __restrict__ ol) {
    const int row = blockIdx.x;
    const int tid = threadIdx.x;
    const int wid = tid >> 5, lane = tid & 31;
    float v = qkv[(size_t)row * QKVW + QW + tid];
    float s = v * v;
    #pragma unroll
    for (int d = 16; d > 0; d >>= 1) s += __shfl_xor_sync(0xffffffffu, s, d);
    __shared__ float ws[8];
    if (lane == 0) ws[wid] = s;
    __syncthreads();
    float tot = ws[0] + ws[1] + ws[2] + ws[3] + ws[4] + ws[5] + ws[6] + ws[7];
    float inv = rsqrtf(tot * (1.0f / LAT) + 1e-5f);
    float r = v * inv * w[tid];
    __nv_bfloat16 h = __float2bfloat16(r);
    __nv_bfloat16 l = __float2bfloat16(r - __bfloat162float(h));
    oh[(size_t)row * LAT + tid] = h;
    ol[(size_t)row * LAT + tid] = l;
}

// ---------------- merged K/V reorg (V -> fp16 single) ----------------
__global__ __launch_bounds__(256)
void reorg_kv(const float* __restrict__ kvin,
              __nv_bfloat16* __restrict__ kh, __nv_bfloat16* __restrict__ kl,
              __half* __restrict__ vh) {
    __shared__ float vs[64][HDIM + 1];
    const int bkvh = blockIdx.y;
    const int b = bkvh / NLH, kvh = bkvh % NLH;
    const int t0 = blockIdx.x * 64;
    for (int i = threadIdx.x; i < 64 * HDIM; i += 256) {
        const int t = i / HDIM, hd = i % HDIM;
        const size_t src = ((size_t)(b * SEQ + t0 + t)) * KVW2 + kvh * HDIM + hd;
        float kvval = kvin[src];
        __nv_bfloat16 h = __float2bfloat16(kvval);
        __nv_bfloat16 l = __float2bfloat16(kvval - __bfloat162float(h));
        size_t o = ((size_t)bkvh * SEQ + t0 + t) * HDIM + hd;
        kh[o] = h; kl[o] = l;
        vs[t][hd] = kvin[src + KVW];
    }
    __syncthreads();
    for (int i = threadIdx.x; i < 64 * HDIM; i += 256) {
        const int hd = i / 64, t = i % 64;
        size_t o = ((size_t)bkvh * HDIM + hd) * SEQ + t0 + t;
        vh[o] = __float2half(vs[t][hd]);
    }
}

// ---------------- tensor-core causal flash attention ----------------
// K: bf16 hi/lo; V: fp16 single (PV in one fp16 MMA per fragment)
#define KROWB 112
#define VROWB 144
#define A_KH 0
#define A_KL 7168
#define A_VH 14336
#define A_STAGE 21248            // 14336 + 48*144
#define SMEM_ATT (3*A_STAGE)     // 63744

__device__ __forceinline__ void attn_stage(
    uint32_t sbase, const __nv_bfloat16* kb, const __nv_bfloat16* kbl,
    const __half* vb, int tid)
{
    // 1152 16B chunks: KH 384, KL 384, VH 384
    #pragma unroll
    for (int t = 0; t < 5; t++) {
        const int c = tid + t * 256;
        if (c >= 1152) break;
        const int arr = c / 384;
        const int idx = c - arr * 384;
        if (arr < 2) {
            const int r = idx / 6, qd = idx - r * 6;
            const uint32_t so = (arr == 0 ? A_KH : A_KL) + r * KROWB + qd * 16;
            const __nv_bfloat16* gp = (arr == 0 ? kb : kbl) + r * HDIM + qd * 8;
            CP16(sbase + so, gp);
        } else {
            const int r = idx >> 3, qd = idx & 7;
            const uint32_t so = A_VH + r * VROWB + qd * 16;
            const __half* gp = vb + (size_t)r * SEQ + qd * 8;
            CP16(sbase + so, gp);
        }
    }
}

__global__ __launch_bounds__(256, 2)
void attn_mma(const float* __restrict__ q,
              const __nv_bfloat16* __restrict__ kh, const __nv_bfloat16* __restrict__ kl,
              const __half* __restrict__ vth,
              __nv_bfloat16* __restrict__ oah, __nv_bfloat16* __restrict__ oal) {
    extern __shared__ char smem[];
    const uint32_t sb = smem_u32(smem);

    const int qt = gridDim.x - 1 - blockIdx.x;        // longest first
    const int bh = blockIdx.y;
    const int b = bh / NH, hq = bh % NH;
    const int bkvh = b * NLH + hq / (NH / NLH);
    const int tid = threadIdx.x;
    const int wid = tid >> 5, lid = tid & 31;
    const int g = lid >> 2, cq = lid & 3;
    const int mat = lid >> 3, mr = lid & 7;
    const int qbase = qt * 128 + wid * 16;
    const float scale = rsqrtf((float)HDIM) * 1.44269504088896340736f;

    uint32_t aqh[3][4], aql[3][4];
    {
        const float* qp0 = q + ((size_t)(b * SEQ + qbase + g)) * QKVW + hq * HDIM;
        const float* qp1 = q + ((size_t)(b * SEQ + qbase + g + 8)) * QKVW + hq * HDIM;
        #pragma unroll
        for (int kk = 0; kk < 3; kk++) {
            float2 f0 = *(const float2*)(qp0 + kk * 16 + 2 * cq);
            float2 f1 = *(const float2*)(qp1 + kk * 16 + 2 * cq);
            float2 f2 = *(const float2*)(qp0 + kk * 16 + 2 * cq + 8);
            float2 f3 = *(const float2*)(qp1 + kk * 16 + 2 * cq + 8);
            split2(f0.x * scale, f0.y * scale, aqh[kk][0], aql[kk][0]);
            split2(f1.x * scale, f1.y * scale, aqh[kk][1], aql[kk][1]);
            split2(f2.x * scale, f2.y * scale, aqh[kk][2], aql[kk][2]);
            split2(f3.x * scale, f3.y * scale, aqh[kk][3], aql[kk][3]);
        }
    }

    float o[6][4];
    #pragma unroll
    for (int jn = 0; jn < 6; jn++)
        #pragma unroll
        for (int t = 0; t < 4; t++) o[jn][t] = 0.0f;
    float m0 = -1e30f, m1 = -1e30f, l0 = 0.0f, l1 = 0.0f;

    const __nv_bfloat16* kB  = kh  + (size_t)bkvh * SEQ * HDIM;
    const __nv_bfloat16* kBl = kl  + (size_t)bkvh * SEQ * HDIM;
    const __half*        vB  = vth + (size_t)bkvh * HDIM * SEQ;

    const uint32_t kboff = (uint32_t)((((mat >> 1) << 3) + mr) * KROWB + ((mat & 1) << 4));
    const uint32_t vboff = (uint32_t)((((mat >> 1) << 3) + mr) * VROWB + ((mat & 1) << 4));

    const int nkt = 2 * qt + 2;
    attn_stage(sb, kB, kBl, vB, tid);
    CP_COMMIT();
    attn_stage(sb + A_STAGE, kB + 64 * HDIM, kBl + 64 * HDIM, vB + 64, tid);
    CP_COMMIT();

    int buf = 0;
    for (int kt = 0; kt < nkt; kt++) {
        if (kt + 2 < nkt) {
            const int nb = (buf + 2) % 3;
            attn_stage(sb + nb * A_STAGE,
                       kB + (kt + 2) * 64 * HDIM, kBl + (kt + 2) * 64 * HDIM,
                       vB + (kt + 2) * 64, tid);
            CP_COMMIT();
            CP_WAIT2();
        } else if (kt + 1 < nkt) {
            CP_WAIT1();
        } else {
            CP_WAIT0();
        }
        __syncthreads();

        const bool full_skip = (kt * 64 > qbase + 15);
        if (!full_skip) {
            const uint32_t st = sb + buf * A_STAGE;
            const uint32_t sKh = st + A_KH, sKl = st + A_KL;
            const uint32_t sVh = st + A_VH;

            float p[8][4];
            #pragma unroll
            for (int j = 0; j < 8; j++)
                p[j][0] = p[j][1] = p[j][2] = p[j][3] = 0.0f;
            #pragma unroll
            for (int kk = 0; kk < 3; kk++) {
                #pragma unroll
                for (int jp = 0; jp < 4; jp++) {
                    const uint32_t ba = kboff + jp * 16 * KROWB + kk * 32;
                    uint32_t bh2[2][2], bl2[2][2];
                    LDSM4(bh2[0][0], bh2[0][1], bh2[1][0], bh2[1][1], sKh + ba);
                    LDSM4(bl2[0][0], bl2[0][1], bl2[1][0], bl2[1][1], sKl + ba);
                    mma16816(p[2*jp],   aqh[kk], bh2[0]);
                    mma16816(p[2*jp],   aqh[kk], bl2[0]);
                    mma16816(p[2*jp],   aql[kk], bh2[0]);
                    mma16816(p[2*jp+1], aqh[kk], bh2[1]);
                    mma16816(p[2*jp+1], aqh[kk], bl2[1]);
                    mma16816(p[2*jp+1], aql[kk], bh2[1]);
                }
            }

            if (kt * 64 + 63 > qbase) {
                const int qr0 = qbase + g;
                #pragma unroll
                for (int j = 0; j < 8; j++) {
                    const int key0 = kt * 64 + j * 8 + 2 * cq;
                    if (key0 > qr0)         p[j][0] = -1e30f;
                    if (key0 + 1 > qr0)     p[j][1] = -1e30f;
                    if (key0 > qr0 + 8)     p[j][2] = -1e30f;
                    if (key0 + 1 > qr0 + 8) p[j][3] = -1e30f;
                }
            }

            float mx0 = -1e30f, mx1 = -1e30f;
            #pragma unroll
            for (int j = 0; j < 8; j++) {
                mx0 = fmaxf(mx0, fmaxf(p[j][0], p[j][1]));
                mx1 = fmaxf(mx1, fmaxf(p[j][2], p[j][3]));
            }
            mx0 = fmaxf(mx0, __shfl_xor_sync(0xffffffffu, mx0, 1));
            mx0 = fmaxf(mx0, __shfl_xor_sync(0xffffffffu, mx0, 2));
            mx1 = fmaxf(mx1, __shfl_xor_sync(0xffffffffu, mx1, 1));
            mx1 = fmaxf(mx1, __shfl_xor_sync(0xffffffffu, mx1, 2));
            const float mn0 = fmaxf(m0, mx0), mn1 = fmaxf(m1, mx1);
            const float cr0 = exp2_fast(m0 - mn0), cr1 = exp2_fast(m1 - mn1);
            m0 = mn0; m1 = mn1;
            l0 *= cr0; l1 *= cr1;
            #pragma unroll
            for (int jn = 0; jn < 6; jn++) {
                o[jn][0] *= cr0; o[jn][1] *= cr0;
                o[jn][2] *= cr1; o[jn][3] *= cr1;
            }
            #pragma unroll
            for (int j = 0; j < 8; j++) {
                p[j][0] = exp2_fast(p[j][0] - m0);
                p[j][1] = exp2_fast(p[j][1] - m0);
                p[j][2] = exp2_fast(p[j][2] - m1);
                p[j][3] = exp2_fast(p[j][3] - m1);
                l0 += p[j][0] + p[j][1];
                l1 += p[j][2] + p[j][3];
            }

            // ---- O += P @ V  (single fp16 MMA per fragment) ----
            #pragma unroll
            for (int kc = 0; kc < 4; kc++) {
                uint32_t aP[4];
                aP[0] = packh2(p[2 * kc][0],     p[2 * kc][1]);
                aP[1] = packh2(p[2 * kc][2],     p[2 * kc][3]);
                aP[2] = packh2(p[2 * kc + 1][0], p[2 * kc + 1][1]);
                aP[3] = packh2(p[2 * kc + 1][2], p[2 * kc + 1][3]);
                #pragma unroll
                for (int jp = 0; jp < 3; jp++) {
                    const uint32_t ba = vboff + jp * 16 * VROWB + kc * 32;
                    uint32_t bv[2][2];
                    LDSM4(bv[0][0], bv[0][1], bv[1][0], bv[1][1], sVh + ba);
                    mma16816h(o[2*jp],   aP, bv[0]);
                    mma16816h(o[2*jp+1], aP, bv[1]);
                }
            }
        }
        __syncthreads();
        buf = (buf + 1 == 3) ? 0 : (buf + 1);
    }

    l0 += __shfl_xor_sync(0xffffffffu, l0, 1);
    l0 += __shfl_xor_sync(0xffffffffu, l0, 2);
    l1 += __shfl_xor_sync(0xffffffffu, l1, 1);
    l1 += __shfl_xor_sync(0xffffffffu, l1, 2);
    const float inv0 = 1.0f / l0, inv1 = 1.0f / l1;

    const size_t base0 = ((size_t)(b * SEQ + qbase + g)) * QW + hq * HDIM;
    const size_t base1 = ((size_t)(b * SEQ + qbase + g + 8)) * QW + hq * HDIM;
    #pragma unroll
    for (int jn = 0; jn < 6; jn++) {
        uint32_t hb, lb;
        split2(o[jn][0] * inv0, o[jn][1] * inv0, hb, lb);
        *(uint32_t*)&oah[base0 + jn * 8 + 2 * cq] = hb;
        *(uint32_t*)&oal[base0 + jn * 8 + 2 * cq] = lb;
        split2(o[jn][2] * inv1, o[jn][3] * inv1, hb, lb);
        *(uint32_t*)&oah[base1 + jn * 8 + 2 * cq] = hb;
        *(uint32_t*)&oal[base1 + jn * 8 + 2 * cq] = lb;
    }
}

// ---------------- launch (R11 schedule) ----------------
extern "C" void kernel_launch(void* const* d_in, const int* in_sizes, int n_in,
                              void* d_out, int out_size) {
    const float* x      = (const float*)d_in[0];
    const float* Wq     = (const float*)d_in[2];
    const float* Wkv    = (const float*)d_in[3];
    const float* w_norm = (const float*)d_in[4];
    const float* Wk     = (const float*)d_in[5];
    const float* Wv     = (const float*)d_in[6];
    const float* Wo     = (const float*)d_in[7];
    float* out = (float*)d_out;

    float *qkv, *kvout;
    cudaGetSymbolAddress((void**)&qkv,   g_qkv);
    cudaGetSymbolAddress((void**)&kvout, g_kvout);

    __nv_bfloat16 *xh, *xl, *kvh, *kvl, *ah, *al;
    __nv_bfloat16 *wqkvh, *wqkvl, *wk2h, *wk2l, *woh, *wol;
    __nv_bfloat16 *akh, *akl;
    __half *avh;
    cudaGetSymbolAddress((void**)&xh,  g_xh);     cudaGetSymbolAddress((void**)&xl,  g_xl);
    cudaGetSymbolAddress((void**)&kvh, g_kvh);    cudaGetSymbolAddress((void**)&kvl, g_kvl);
    cudaGetSymbolAddress((void**)&ah,  g_ah);     cudaGetSymbolAddress((void**)&al,  g_al);
    cudaGetSymbolAddress((void**)&wqkvh, g_wqkv_h); cudaGetSymbolAddress((void**)&wqkvl, g_wqkv_l);
    cudaGetSymbolAddress((void**)&wk2h, g_wkv2_h);  cudaGetSymbolAddress((void**)&wk2l, g_wkv2_l);
    cudaGetSymbolAddress((void**)&woh, g_wo_h);   cudaGetSymbolAddress((void**)&wol, g_wo_l);
    cudaGetSymbolAddress((void**)&akh, g_akh);    cudaGetSymbolAddress((void**)&akl, g_akl);
    cudaGetSymbolAddress((void**)&avh, g_avh);

    static cudaStream_t s2 = 0;
    static cudaEvent_t evRoot = 0, evW = 0, evWo = 0;
    if (!s2) {
        cudaFuncSetAttribute(gemm_mma,  cudaFuncAttributeMaxDynamicSharedMemorySize, SMEM_GEMM);
        cudaFuncSetAttribute(gemm_mma2, cudaFuncAttributeMaxDynamicSharedMemorySize, SMEM_GEMM2);
        cudaFuncSetAttribute(attn_mma,  cudaFuncAttributeMaxDynamicSharedMemorySize, SMEM_ATT);
        cudaStreamCreateWithFlags(&s2, cudaStreamNonBlocking);
        cudaEventCreateWithFlags(&evRoot, cudaEventDisableTiming);
        cudaEventCreateWithFlags(&evW, cudaEventDisableTiming);
        cudaEventCreateWithFlags(&evWo, cudaEventDisableTiming);
    }

    dim3 t256(256);
    dim3 ttr(32, 8);

    // fork: weight transposes on s2, x split on main
    cudaEventRecord(evRoot, 0);
    cudaStreamWaitEvent(s2, evRoot, 0);

    transpose_split<<<dim3(QW / 32,  DIM / 32), ttr, 0, s2>>>(Wq,  wqkvh, wqkvl, DIM, QW);
    transpose_split<<<dim3(LAT / 32, DIM / 32), ttr, 0, s2>>>(Wkv, wqkvh + (size_t)QW * DIM,
                                                              wqkvl + (size_t)QW * DIM, DIM, LAT);
    transpose_split<<<dim3(KVW / 32, LAT / 32), ttr, 0, s2>>>(Wk, wk2h, wk2l, LAT, KVW);
    transpose_split<<<dim3(KVW / 32, LAT / 32), ttr, 0, s2>>>(Wv, wk2h + (size_t)KVW * LAT,
                                                              wk2l + (size_t)KVW * LAT, LAT, KVW);
    cudaEventRecord(evW, s2);
    transpose_split<<<dim3(DIM / 32, QW / 32), ttr, 0, s2>>>(Wo, woh, wol, QW, DIM);
    cudaEventRecord(evWo, s2);

    split_act<<<(ROWS * DIM / 4 + 255) / 256, t256>>>(x, xh, xl, ROWS * DIM / 4);

    // join for qkv weights; [q | kv] = x @ [Wq | Wkv]  (wide-tile GEMM)
    cudaStreamWaitEvent(0, evW, 0);
    gemm_mma2<<<dim3(QKVW / G2N, ROWS / GM), 512, SMEM_GEMM2>>>(xh, xl, wqkvh, wqkvl, qkv, DIM, QKVW);

    rmsnorm_split<<<ROWS, LAT>>>(qkv, w_norm, kvh, kvl);
    gemm_mma<<<dim3(KVW2 / GN, ROWS / GM), t256, SMEM_GEMM>>>(kvh, kvl, wk2h, wk2l, kvout, LAT, KVW2);
    reorg_kv<<<dim3(SEQ / 64, BATCH * NLH), t256>>>(kvout, akh, akl, avh);

    attn_mma<<<dim3(SEQ / 128, BATCH * NH), t256, SMEM_ATT>>>(qkv, akh, akl, avh, ah, al);

    // join for Wo, then out = att @ Wo  (wide-tile GEMM)
    cudaStreamWaitEvent(0, evWo, 0);
    gemm_mma2<<<dim3(DIM / G2N, ROWS / GM), 512, SMEM_GEMM2>>>(ah, al, woh, wol, out, QW, DIM);
}

// round 14
// speedup vs baseline: 1.1836x; 1.0626x over previous
#include <cuda_runtime.h>
#include <cuda_bf16.h>
#include <cuda_fp16.h>
#include <math.h>
#include <stdint.h>

// ---------------- problem constants ----------------
#define BATCH 2
#define SEQ   2048
#define DIM   2048
#define NH    16
#define HDIM  48
#define LAT   256
#define NLH   8
#define ROWS  (BATCH*SEQ)          // 4096
#define QW    (NH*HDIM)            // 768
#define KVW   (NLH*HDIM)           // 384
#define KVW2  (2*KVW)              // 768 (k|v concat)
#define QKVW  (QW+LAT)             // 1024 (q|kv concat)

// ---------------- scratch ----------------
__device__ float g_qkv  [ROWS * QKVW];   // [q | kv_latent] fp32
__device__ float g_kvout[ROWS * KVW2];   // [k|v] fp32

__device__ __nv_bfloat16 g_xh [ROWS * DIM], g_xl [ROWS * DIM];
__device__ __nv_bfloat16 g_kvh[ROWS * LAT], g_kvl[ROWS * LAT];
__device__ __nv_bfloat16 g_ah [ROWS * QW],  g_al [ROWS * QW];
// transposed bf16 split weights
__device__ __nv_bfloat16 g_wqkv_h[QKVW * DIM], g_wqkv_l[QKVW * DIM];   // [Wq^T ; Wkv^T]
__device__ __nv_bfloat16 g_wkv2_h[KVW2 * LAT], g_wkv2_l[KVW2 * LAT];   // [Wk^T ; Wv^T]
__device__ __nv_bfloat16 g_wo_h [DIM * QW],  g_wo_l [DIM * QW];
// attention layouts (fp16 single): K: [b][kvh][t][hd]   Vt: [b][kvh][hd][t]
__device__ __half g_akh[BATCH*NLH*SEQ*HDIM];
__device__ __half g_avh[BATCH*NLH*HDIM*SEQ];

// ---------------- helpers ----------------
__device__ __forceinline__ uint32_t smem_u32(const void* p) {
    uint32_t a;
    asm("{ .reg .u64 t; cvta.to.shared.u64 t, %1; cvt.u32.u64 %0, t; }" : "=r"(a) : "l"(p));
    return a;
}

#define CP16(dst, src) \
    asm volatile("cp.async.cg.shared.global [%0], [%1], 16;" :: "r"(dst), "l"(src) : "memory")
#define CP_COMMIT() asm volatile("cp.async.commit_group;" ::: "memory")
#define CP_WAIT0()  asm volatile("cp.async.wait_group 0;" ::: "memory")
#define CP_WAIT1()  asm volatile("cp.async.wait_group 1;" ::: "memory")
#define CP_WAIT2()  asm volatile("cp.async.wait_group 2;" ::: "memory")

#define LDSM4(r0, r1, r2, r3, addr) \
    asm volatile("ldmatrix.sync.aligned.m8n8.x4.shared.b16 {%0,%1,%2,%3}, [%4];" \
        : "=r"(r0), "=r"(r1), "=r"(r2), "=r"(r3) : "r"(addr))

__device__ __forceinline__ void mma16816(float* c, const uint32_t* a, const uint32_t* b) {
    asm volatile(
        "mma.sync.aligned.m16n8k16.row.col.f32.bf16.bf16.f32 "
        "{%0,%1,%2,%3}, {%4,%5,%6,%7}, {%8,%9}, {%0,%1,%2,%3};"
        : "+f"(c[0]), "+f"(c[1]), "+f"(c[2]), "+f"(c[3])
        : "r"(a[0]), "r"(a[1]), "r"(a[2]), "r"(a[3]), "r"(b[0]), "r"(b[1]));
}

__device__ __forceinline__ void mma16816h(float* c, const uint32_t* a, const uint32_t* b) {
    asm volatile(
        "mma.sync.aligned.m16n8k16.row.col.f32.f16.f16.f32 "
        "{%0,%1,%2,%3}, {%4,%5,%6,%7}, {%8,%9}, {%0,%1,%2,%3};"
        : "+f"(c[0]), "+f"(c[1]), "+f"(c[2]), "+f"(c[3])
        : "r"(a[0]), "r"(a[1]), "r"(a[2]), "r"(a[3]), "r"(b[0]), "r"(b[1]));
}

__device__ __forceinline__ void split2(float x, float y, uint32_t& h, uint32_t& l) {
    __nv_bfloat162 hb = __floats2bfloat162_rn(x, y);
    h = *reinterpret_cast<uint32_t*>(&hb);
    float hx = __bfloat162float(__low2bfloat16(hb));
    float hy = __bfloat162float(__high2bfloat16(hb));
    __nv_bfloat162 lb = __floats2bfloat162_rn(x - hx, y - hy);
    l = *reinterpret_cast<uint32_t*>(&lb);
}

__device__ __forceinline__ uint32_t packh2(float x, float y) {
    __half2 h = __floats2half2_rn(x, y);
    return *reinterpret_cast<uint32_t*>(&h);
}

// fp16 hi/lo split of a float pair
__device__ __forceinline__ void splith2(float x, float y, uint32_t& h, uint32_t& l) {
    __half2 hb = __floats2half2_rn(x, y);
    h = *reinterpret_cast<uint32_t*>(&hb);
    float hx = __half2float(__low2half(hb));
    float hy = __half2float(__high2half(hb));
    __half2 lb = __floats2half2_rn(x - hx, y - hy);
    l = *reinterpret_cast<uint32_t*>(&lb);
}

__device__ __forceinline__ float exp2_fast(float x) {
    float r;
    asm("ex2.approx.ftz.f32 %0, %1;" : "=f"(r) : "f"(x));
    return r;
}

// ---------------- common GEMM tile constants ----------------
#define GM 128
#define GK 32
#define ROWB 80

// ===== 256-thread 128x128 GEMM =====
#define GN 128
#define T_A  (128 * ROWB)
#define OFF_AH 0
#define OFF_AL (T_A)
#define OFF_BH (2*T_A)
#define OFF_BL (3*T_A)
#define STAGE  (4*T_A)
#define SMEM_GEMM (2*STAGE)

__device__ __forceinline__ void stage_load(
    const char* Ah, const char* Al, const char* Bh, const char* Bl,
    uint32_t sbase, int tid, int m0, int n0, int k0, int K)
{
    #pragma unroll
    for (int u = 0; u < 2; u++) {
        const int s   = tid * 2 + u;
        const int row = s >> 2;
        const int cc  = s & 3;
        const uint32_t so = row * ROWB + cc * 16;
        const size_t gA = ((size_t)(m0 + row) * K + k0) * 2 + cc * 16;
        const size_t gB = ((size_t)(n0 + row) * K + k0) * 2 + cc * 16;
        CP16(sbase + OFF_AH + so, Ah + gA);
        CP16(sbase + OFF_AL + so, Al + gA);
        CP16(sbase + OFF_BH + so, Bh + gB);
        CP16(sbase + OFF_BL + so, Bl + gB);
    }
}

__global__ __launch_bounds__(256, 2)
void gemm_mma(const __nv_bfloat16* __restrict__ Ahi, const __nv_bfloat16* __restrict__ Alo,
              const __nv_bfloat16* __restrict__ Bhi, const __nv_bfloat16* __restrict__ Blo,
              float* __restrict__ C, int K, int ldc) {
    extern __shared__ char smem[];
    const uint32_t sb = smem_u32(smem);
    const int tid = threadIdx.x;
    const int wid = tid >> 5, lid = tid & 31;
    const int wm = wid >> 2;
    const int wn = wid & 3;
    const int g = lid >> 2, ctg = lid & 3;
    const int mat = lid >> 3, mr = lid & 7;
    const int m0 = blockIdx.y * GM;
    const int n0 = blockIdx.x * GN;

    float acc[4][4][4];
    #pragma unroll
    for (int i = 0; i < 4; i++)
        #pragma unroll
        for (int j = 0; j < 4; j++)
            #pragma unroll
            for (int t = 0; t < 4; t++) acc[i][j][t] = 0.0f;

    const int nch = K / GK;
    stage_load((const char*)Ahi, (const char*)Alo, (const char*)Bhi, (const char*)Blo,
               sb, tid, m0, n0, 0, K);
    CP_COMMIT();

    const uint32_t aoff = (uint32_t)((wm * 64 + ((mat & 1) << 3) + mr) * ROWB + ((mat >> 1) << 4));
    const uint32_t boff = (uint32_t)((wn * 32 + ((mat >> 1) << 3) + mr) * ROWB + ((mat & 1) << 4));

    for (int c = 0; c < nch; c++) {
        if (c + 1 < nch) {
            stage_load((const char*)Ahi, (const char*)Alo, (const char*)Bhi, (const char*)Blo,
                       sb + ((c + 1) & 1) * STAGE, tid, m0, n0, (c + 1) * GK, K);
            CP_COMMIT();
            CP_WAIT1();
        } else {
            CP_WAIT0();
        }
        __syncthreads();

        const uint32_t sAh = sb + (c & 1) * STAGE + OFF_AH;
        const uint32_t sAl = sb + (c & 1) * STAGE + OFF_AL;
        const uint32_t sBh = sb + (c & 1) * STAGE + OFF_BH;
        const uint32_t sBl = sb + (c & 1) * STAGE + OFF_BL;

        #pragma unroll
        for (int ks = 0; ks < 2; ks++) {
            uint32_t bh[4][2], bl[4][2];
            #pragma unroll
            for (int jp = 0; jp < 2; jp++) {
                const uint32_t ba = boff + jp * 16 * ROWB + ks * 32;
                LDSM4(bh[2*jp][0], bh[2*jp][1], bh[2*jp+1][0], bh[2*jp+1][1], sBh + ba);
                LDSM4(bl[2*jp][0], bl[2*jp][1], bl[2*jp+1][0], bl[2*jp+1][1], sBl + ba);
            }
            #pragma unroll
            for (int i = 0; i < 4; i++) {
                const uint32_t aa = aoff + i * 16 * ROWB + ks * 32;
                uint32_t ah[4], al[4];
                LDSM4(ah[0], ah[1], ah[2], ah[3], sAh + aa);
                LDSM4(al[0], al[1], al[2], al[3], sAl + aa);
                #pragma unroll
                for (int j = 0; j < 4; j++) {
                    mma16816(acc[i][j], ah, bh[j]);
                    mma16816(acc[i][j], ah, bl[j]);
                    mma16816(acc[i][j], al, bh[j]);
                }
            }
        }
        __syncthreads();
    }

    #pragma unroll
    for (int i = 0; i < 4; i++) {
        const int r0 = m0 + wm * 64 + i * 16 + g;
        #pragma unroll
        for (int j = 0; j < 4; j++) {
            const int c0 = n0 + wn * 32 + j * 8 + ctg * 2;
            float2 v0 = make_float2(acc[i][j][0], acc[i][j][1]);
            float2 v1 = make_float2(acc[i][j][2], acc[i][j][3]);
            *(float2*)(C + (size_t)r0 * ldc + c0)       = v0;
            *(float2*)(C + (size_t)(r0 + 8) * ldc + c0) = v1;
        }
    }
}

// ===== 512-thread 128x256 GEMM =====
#define G2N 256
#define OFF2_AH 0
#define OFF2_AL (128*ROWB)
#define OFF2_BH (2*128*ROWB)
#define OFF2_BL (2*128*ROWB + 256*ROWB)
#define STAGE2  (61440)
#define SMEM_GEMM2 (2*STAGE2)

__device__ __forceinline__ void stage_load2(
    const char* Ah, const char* Al, const char* Bh, const char* Bl,
    uint32_t sbase, int tid, int m0, int n0, int k0, int K)
{
    {
        const int row = tid >> 2;
        const int cc  = tid & 3;
        const uint32_t so = row * ROWB + cc * 16;
        const size_t gA = ((size_t)(m0 + row) * K + k0) * 2 + cc * 16;
        CP16(sbase + OFF2_AH + so, Ah + gA);
        CP16(sbase + OFF2_AL + so, Al + gA);
    }
    #pragma unroll
    for (int u = 0; u < 2; u++) {
        const int s   = tid * 2 + u;
        const int row = s >> 2;
        const int cc  = s & 3;
        const uint32_t so = row * ROWB + cc * 16;
        const size_t gB = ((size_t)(n0 + row) * K + k0) * 2 + cc * 16;
        CP16(sbase + OFF2_BH + so, Bh + gB);
        CP16(sbase + OFF2_BL + so, Bl + gB);
    }
}

__global__ __launch_bounds__(512, 1)
void gemm_mma2(const __nv_bfloat16* __restrict__ Ahi, const __nv_bfloat16* __restrict__ Alo,
               const __nv_bfloat16* __restrict__ Bhi, const __nv_bfloat16* __restrict__ Blo,
               float* __restrict__ C, int K, int ldc) {
    extern __shared__ char smem[];
    const uint32_t sb = smem_u32(smem);
    const int tid = threadIdx.x;
    const int wid = tid >> 5, lid = tid & 31;
    const int wm = wid >> 3;
    const int wn = wid & 7;
    const int g = lid >> 2, ctg = lid & 3;
    const int mat = lid >> 3, mr = lid & 7;
    const int m0 = blockIdx.y * GM;
    const int n0 = blockIdx.x * G2N;

    float acc[4][4][4];
    #pragma unroll
    for (int i = 0; i < 4; i++)
        #pragma unroll
        for (int j = 0; j < 4; j++)
            #pragma unroll
            for (int t = 0; t < 4; t++) acc[i][j][t] = 0.0f;

    const int nch = K / GK;
    stage_load2((const char*)Ahi, (const char*)Alo, (const char*)Bhi, (const char*)Blo,
                sb, tid, m0, n0, 0, K);
    CP_COMMIT();

    const uint32_t aoff = (uint32_t)((wm * 64 + ((mat & 1) << 3) + mr) * ROWB + ((mat >> 1) << 4));
    const uint32_t boff = (uint32_t)((wn * 32 + ((mat >> 1) << 3) + mr) * ROWB + ((mat & 1) << 4));

    for (int c = 0; c < nch; c++) {
        if (c + 1 < nch) {
            stage_load2((const char*)Ahi, (const char*)Alo, (const char*)Bhi, (const char*)Blo,
                        sb + ((c + 1) & 1) * STAGE2, tid, m0, n0, (c + 1) * GK, K);
            CP_COMMIT();
            CP_WAIT1();
        } else {
            CP_WAIT0();
        }
        __syncthreads();

        const uint32_t sAh = sb + (c & 1) * STAGE2 + OFF2_AH;
        const uint32_t sAl = sb + (c & 1) * STAGE2 + OFF2_AL;
        const uint32_t sBh = sb + (c & 1) * STAGE2 + OFF2_BH;
        const uint32_t sBl = sb + (c & 1) * STAGE2 + OFF2_BL;

        #pragma unroll
        for (int ks = 0; ks < 2; ks++) {
            uint32_t bh[4][2], bl[4][2];
            #pragma unroll
            for (int jp = 0; jp < 2; jp++) {
                const uint32_t ba = boff + jp * 16 * ROWB + ks * 32;
                LDSM4(bh[2*jp][0], bh[2*jp][1], bh[2*jp+1][0], bh[2*jp+1][1], sBh + ba);
                LDSM4(bl[2*jp][0], bl[2*jp][1], bl[2*jp+1][0], bl[2*jp+1][1], sBl + ba);
            }
            #pragma unroll
            for (int i = 0; i < 4; i++) {
                const uint32_t aa = aoff + i * 16 * ROWB + ks * 32;
                uint32_t ah[4], al[4];
                LDSM4(ah[0], ah[1], ah[2], ah[3], sAh + aa);
                LDSM4(al[0], al[1], al[2], al[3], sAl + aa);
                #pragma unroll
                for (int j = 0; j < 4; j++) {
                    mma16816(acc[i][j], ah, bh[j]);
                    mma16816(acc[i][j], ah, bl[j]);
                    mma16816(acc[i][j], al, bh[j]);
                }
            }
        }
        __syncthreads();
    }

    #pragma unroll
    for (int i = 0; i < 4; i++) {
        const int r0 = m0 + wm * 64 + i * 16 + g;
        #pragma unroll
        for (int j = 0; j < 4; j++) {
            const int c0 = n0 + wn * 32 + j * 8 + ctg * 2;
            float2 v0 = make_float2(acc[i][j][0], acc[i][j][1]);
            float2 v1 = make_float2(acc[i][j][2], acc[i][j][3]);
            *(float2*)(C + (size_t)r0 * ldc + c0)       = v0;
            *(float2*)(C + (size_t)(r0 + 8) * ldc + c0) = v1;
        }
    }
}

// ---------------- fp32 -> bf16 hi/lo split ----------------
__global__ __launch_bounds__(256)
void split_act(const float* __restrict__ in, __nv_bfloat16* __restrict__ hi,
               __nv_bfloat16* __restrict__ lo, int n4) {
    int i = blockIdx.x * 256 + threadIdx.x;
    if (i >= n4) return;
    float4 v = ((const float4*)in)[i];
    uint32_t h0, l0, h1, l1;
    split2(v.x, v.y, h0, l0);
    split2(v.z, v.w, h1, l1);
    ((uint32_t*)hi)[2 * i]     = h0;
    ((uint32_t*)hi)[2 * i + 1] = h1;
    ((uint32_t*)lo)[2 * i]     = l0;
    ((uint32_t*)lo)[2 * i + 1] = l1;
}

// ---------------- W[K,N] fp32 -> Wt[N,K] bf16 hi/lo ----------------
__global__ __launch_bounds__(256)
void transpose_split(const float* __restrict__ W, __nv_bfloat16* __restrict__ th,
                     __nv_bfloat16* __restrict__ tl, int K, int N) {
    __shared__ float ts[32][33];
    const int tx = threadIdx.x;
    const int ty = threadIdx.y;
    const int x0 = blockIdx.x * 32;
    const int y0 = blockIdx.y * 32;
    #pragma unroll
    for (int j = ty; j < 32; j += 8)
        ts[j][tx] = W[(size_t)(y0 + j) * N + x0 + tx];
    __syncthreads();
    #pragma unroll
    for (int j = ty; j < 32; j += 8) {
        float v = ts[tx][j];
        __nv_bfloat16 h = __float2bfloat16(v);
        __nv_bfloat16 l = __float2bfloat16(v - __bfloat162float(h));
        size_t o = (size_t)(x0 + j) * K + y0 + tx;
        th[o] = h;
        tl[o] = l;
    }
}

// ---------------- fused RMSNorm + bf16 split ----------------
__global__ __launch_bounds__(256)
void rmsnorm_split(const float* __restrict__ qkv, const float* __restrict__ w,
                   __nv_bfloat16* __restrict__ oh, __nv_bfloat16* __restrict__ ol) {
    const int row = blockIdx.x;
    const int tid = threadIdx.x;
    const int wid = tid >> 5, lane = tid & 31;
    float v = qkv[(size_t)row * QKVW + QW + tid];
    float s = v * v;
    #pragma unroll
    for (int d = 16; d > 0; d >>= 1) s += __shfl_xor_sync(0xffffffffu, s, d);
    __shared__ float ws[8];
    if (lane == 0) ws[wid] = s;
    __syncthreads();
    float tot = ws[0] + ws[1] + ws[2] + ws[3] + ws[4] + ws[5] + ws[6] + ws[7];
    float inv = rsqrtf(tot * (1.0f / LAT) + 1e-5f);
    float r = v * inv * w[tid];
    __nv_bfloat16 h = __float2bfloat16(r);
    __nv_bfloat16 l = __float2bfloat16(r - __bfloat162float(h));
    oh[(size_t)row * LAT + tid] = h;
    ol[(size_t)row * LAT + tid] = l;
}

// ---------------- merged K/V reorg (K,V -> fp16 single) ----------------
__global__ __launch_bounds__(256)
void reorg_kv(const float* __restrict__ kvin,
              __half* __restrict__ kh, __half* __restrict__ vh) {
    __shared__ float vs[64][HDIM + 1];
    const int bkvh = blockIdx.y;
    const int b = bkvh / NLH, kvh = bkvh % NLH;
    const int t0 = blockIdx.x * 64;
    for (int i = threadIdx.x; i < 64 * HDIM; i += 256) {
        const int t = i / HDIM, hd = i % HDIM;
        const size_t src = ((size_t)(b * SEQ + t0 + t)) * KVW2 + kvh * HDIM + hd;
        size_t o = ((size_t)bkvh * SEQ + t0 + t) * HDIM + hd;
        kh[o] = __float2half(kvin[src]);
        vs[t][hd] = kvin[src + KVW];
    }
    __syncthreads();
    for (int i = threadIdx.x; i < 64 * HDIM; i += 256) {
        const int hd = i / 64, t = i % 64;
        size_t o = ((size_t)bkvh * HDIM + hd) * SEQ + t0 + t;
        vh[o] = __float2half(vs[t][hd]);
    }
}

// ---------------- tensor-core causal flash attention ----------------
// Q: fp16 hi/lo (registers); K: fp16 single; V: fp16 single.
// QK: 2 fp16 MMAs per fragment, PV: 1 fp16 MMA per fragment.
#define KROWB 112
#define VROWB 144
#define A_KH 0
#define A_VH 7168                // 64*112
#define A_STAGE 14080            // 7168 + 48*144
#define SMEM_ATT (3*A_STAGE)     // 42240

__device__ __forceinline__ void attn_stage(
    uint32_t sbase, const __half* kb, const __half* vb, int tid)
{
    // 768 chunks: K 384 (64 rows x 6), V 384 (48 rows x 8)
    #pragma unroll
    for (int t = 0; t < 3; t++) {
        const int c = tid + t * 256;
        if (c < 384) {
            const int r = c / 6, qd = c - r * 6;
            CP16(sbase + A_KH + r * KROWB + qd * 16, kb + r * HDIM + qd * 8);
        } else {
            const int idx = c - 384;
            const int r = idx >> 3, qd = idx & 7;
            CP16(sbase + A_VH + r * VROWB + qd * 16, vb + (size_t)r * SEQ + qd * 8);
        }
    }
}

__global__ __launch_bounds__(256, 2)
void attn_mma(const float* __restrict__ q,
              const __half* __restrict__ kh, const __half* __restrict__ vth,
              __nv_bfloat16* __restrict__ oah, __nv_bfloat16* __restrict__ oal) {
    extern __shared__ char smem[];
    const uint32_t sb = smem_u32(smem);

    const int qt = gridDim.x - 1 - blockIdx.x;        // longest first
    const int bh = blockIdx.y;
    const int b = bh / NH, hq = bh % NH;
    const int bkvh = b * NLH + hq / (NH / NLH);
    const int tid = threadIdx.x;
    const int wid = tid >> 5, lid = tid & 31;
    const int g = lid >> 2, cq = lid & 3;
    const int mat = lid >> 3, mr = lid & 7;
    const int qbase = qt * 128 + wid * 16;
    const float scale = rsqrtf((float)HDIM) * 1.44269504088896340736f;

    // Q fragments as fp16 hi/lo (22-bit effective)
    uint32_t aqh[3][4], aql[3][4];
    {
        const float* qp0 = q + ((size_t)(b * SEQ + qbase + g)) * QKVW + hq * HDIM;
        const float* qp1 = q + ((size_t)(b * SEQ + qbase + g + 8)) * QKVW + hq * HDIM;
        #pragma unroll
        for (int kk = 0; kk < 3; kk++) {
            float2 f0 = *(const float2*)(qp0 + kk * 16 + 2 * cq);
            float2 f1 = *(const float2*)(qp1 + kk * 16 + 2 * cq);
            float2 f2 = *(const float2*)(qp0 + kk * 16 + 2 * cq + 8);
            float2 f3 = *(const float2*)(qp1 + kk * 16 + 2 * cq + 8);
            splith2(f0.x * scale, f0.y * scale, aqh[kk][0], aql[kk][0]);
            splith2(f1.x * scale, f1.y * scale, aqh[kk][1], aql[kk][1]);
            splith2(f2.x * scale, f2.y * scale, aqh[kk][2], aql[kk][2]);
            splith2(f3.x * scale, f3.y * scale, aqh[kk][3], aql[kk][3]);
        }
    }

    float o[6][4];
    #pragma unroll
    for (int jn = 0; jn < 6; jn++)
        #pragma unroll
        for (int t = 0; t < 4; t++) o[jn][t] = 0.0f;
    float m0 = -1e30f, m1 = -1e30f, l0 = 0.0f, l1 = 0.0f;

    const __half* kB = kh  + (size_t)bkvh * SEQ * HDIM;
    const __half* vB = vth + (size_t)bkvh * HDIM * SEQ;

    const uint32_t kboff = (uint32_t)((((mat >> 1) << 3) + mr) * KROWB + ((mat & 1) << 4));
    const uint32_t vboff = (uint32_t)((((mat >> 1) << 3) + mr) * VROWB + ((mat & 1) << 4));

    const int nkt = 2 * qt + 2;
    attn_stage(sb, kB, vB, tid);
    CP_COMMIT();
    attn_stage(sb + A_STAGE, kB + 64 * HDIM, vB + 64, tid);
    CP_COMMIT();

    int buf = 0;
    for (int kt = 0; kt < nkt; kt++) {
        if (kt + 2 < nkt) {
            const int nb = (buf + 2) % 3;
            attn_stage(sb + nb * A_STAGE, kB + (kt + 2) * 64 * HDIM, vB + (kt + 2) * 64, tid);
            CP_COMMIT();
            CP_WAIT2();
        } else if (kt + 1 < nkt) {
            CP_WAIT1();
        } else {
            CP_WAIT0();
        }
        __syncthreads();

        const bool full_skip = (kt * 64 > qbase + 15);
        if (!full_skip) {
            const uint32_t st = sb + buf * A_STAGE;
            const uint32_t sKh = st + A_KH;
            const uint32_t sVh = st + A_VH;

            // ---- scores (log2 domain): Qhi*K + Qlo*K ----
            float p[8][4];
            #pragma unroll
            for (int j = 0; j < 8; j++)
                p[j][0] = p[j][1] = p[j][2] = p[j][3] = 0.0f;
            #pragma unroll
            for (int kk = 0; kk < 3; kk++) {
                #pragma unroll
                for (int jp = 0; jp < 4; jp++) {
                    const uint32_t ba = kboff + jp * 16 * KROWB + kk * 32;
                    uint32_t bk[2][2];
                    LDSM4(bk[0][0], bk[0][1], bk[1][0], bk[1][1], sKh + ba);
                    mma16816h(p[2*jp],   aqh[kk], bk[0]);
                    mma16816h(p[2*jp],   aql[kk], bk[0]);
                    mma16816h(p[2*jp+1], aqh[kk], bk[1]);
                    mma16816h(p[2*jp+1], aql[kk], bk[1]);
                }
            }

            if (kt * 64 + 63 > qbase) {
                const int qr0 = qbase + g;
                #pragma unroll
                for (int j = 0; j < 8; j++) {
                    const int key0 = kt * 64 + j * 8 + 2 * cq;
                    if (key0 > qr0)         p[j][0] = -1e30f;
                    if (key0 + 1 > qr0)     p[j][1] = -1e30f;
                    if (key0 > qr0 + 8)     p[j][2] = -1e30f;
                    if (key0 + 1 > qr0 + 8) p[j][3] = -1e30f;
                }
            }

            float mx0 = -1e30f, mx1 = -1e30f;
            #pragma unroll
            for (int j = 0; j < 8; j++) {
                mx0 = fmaxf(mx0, fmaxf(p[j][0], p[j][1]));
                mx1 = fmaxf(mx1, fmaxf(p[j][2], p[j][3]));
            }
            mx0 = fmaxf(mx0, __shfl_xor_sync(0xffffffffu, mx0, 1));
            mx0 = fmaxf(mx0, __shfl_xor_sync(0xffffffffu, mx0, 2));
            mx1 = fmaxf(mx1, __shfl_xor_sync(0xffffffffu, mx1, 1));
            mx1 = fmaxf(mx1, __shfl_xor_sync(0xffffffffu, mx1, 2));
            const float mn0 = fmaxf(m0, mx0), mn1 = fmaxf(m1, mx1);
            const float cr0 = exp2_fast(m0 - mn0), cr1 = exp2_fast(m1 - mn1);
            m0 = mn0; m1 = mn1;
            l0 *= cr0; l1 *= cr1;
            #pragma unroll
            for (int jn = 0; jn < 6; jn++) {
                o[jn][0] *= cr0; o[jn][1] *= cr0;
                o[jn][2] *= cr1; o[jn][3] *= cr1;
            }
            #pragma unroll
            for (int j = 0; j < 8; j++) {
                p[j][0] = exp2_fast(p[j][0] - m0);
                p[j][1] = exp2_fast(p[j][1] - m0);
                p[j][2] = exp2_fast(p[j][2] - m1);
                p[j][3] = exp2_fast(p[j][3] - m1);
                l0 += p[j][0] + p[j][1];
                l1 += p[j][2] + p[j][3];
            }

            // ---- O += P @ V  (single fp16 MMA per fragment) ----
            #pragma unroll
            for (int kc = 0; kc < 4; kc++) {
                uint32_t aP[4];
                aP[0] = packh2(p[2 * kc][0],     p[2 * kc][1]);
                aP[1] = packh2(p[2 * kc][2],     p[2 * kc][3]);
                aP[2] = packh2(p[2 * kc + 1][0], p[2 * kc + 1][1]);
                aP[3] = packh2(p[2 * kc + 1][2], p[2 * kc + 1][3]);
                #pragma unroll
                for (int jp = 0; jp < 3; jp++) {
                    const uint32_t ba = vboff + jp * 16 * VROWB + kc * 32;
                    uint32_t bv[2][2];
                    LDSM4(bv[0][0], bv[0][1], bv[1][0], bv[1][1], sVh + ba);
                    mma16816h(o[2*jp],   aP, bv[0]);
                    mma16816h(o[2*jp+1], aP, bv[1]);
                }
            }
        }
        __syncthreads();
        buf = (buf + 1 == 3) ? 0 : (buf + 1);
    }

    l0 += __shfl_xor_sync(0xffffffffu, l0, 1);
    l0 += __shfl_xor_sync(0xffffffffu, l0, 2);
    l1 += __shfl_xor_sync(0xffffffffu, l1, 1);
    l1 += __shfl_xor_sync(0xffffffffu, l1, 2);
    const float inv0 = 1.0f / l0, inv1 = 1.0f / l1;

    const size_t base0 = ((size_t)(b * SEQ + qbase + g)) * QW + hq * HDIM;
    const size_t base1 = ((size_t)(b * SEQ + qbase + g + 8)) * QW + hq * HDIM;
    #pragma unroll
    for (int jn = 0; jn < 6; jn++) {
        uint32_t hb, lb;
        split2(o[jn][0] * inv0, o[jn][1] * inv0, hb, lb);
        *(uint32_t*)&oah[base0 + jn * 8 + 2 * cq] = hb;
        *(uint32_t*)&oal[base0 + jn * 8 + 2 * cq] = lb;
        split2(o[jn][2] * inv1, o[jn][3] * inv1, hb, lb);
        *(uint32_t*)&oah[base1 + jn * 8 + 2 * cq] = hb;
        *(uint32_t*)&oal[base1 + jn * 8 + 2 * cq] = lb;
    }
}

// ---------------- launch (R11 schedule) ----------------
extern "C" void kernel_launch(void* const* d_in, const int* in_sizes, int n_in,
                              void* d_out, int out_size) {
    const float* x      = (const float*)d_in[0];
    const float* Wq     = (const float*)d_in[2];
    const float* Wkv    = (const float*)d_in[3];
    const float* w_norm = (const float*)d_in[4];
    const float* Wk     = (const float*)d_in[5];
    const float* Wv     = (const float*)d_in[6];
    const float* Wo     = (const float*)d_in[7];
    float* out = (float*)d_out;

    float *qkv, *kvout;
    cudaGetSymbolAddress((void**)&qkv,   g_qkv);
    cudaGetSymbolAddress((void**)&kvout, g_kvout);

    __nv_bfloat16 *xh, *xl, *kvh, *kvl, *ah, *al;
    __nv_bfloat16 *wqkvh, *wqkvl, *wk2h, *wk2l, *woh, *wol;
    __half *akh, *avh;
    cudaGetSymbolAddress((void**)&xh,  g_xh);     cudaGetSymbolAddress((void**)&xl,  g_xl);
    cudaGetSymbolAddress((void**)&kvh, g_kvh);    cudaGetSymbolAddress((void**)&kvl, g_kvl);
    cudaGetSymbolAddress((void**)&ah,  g_ah);     cudaGetSymbolAddress((void**)&al,  g_al);
    cudaGetSymbolAddress((void**)&wqkvh, g_wqkv_h); cudaGetSymbolAddress((void**)&wqkvl, g_wqkv_l);
    cudaGetSymbolAddress((void**)&wk2h, g_wkv2_h);  cudaGetSymbolAddress((void**)&wk2l, g_wkv2_l);
    cudaGetSymbolAddress((void**)&woh, g_wo_h);   cudaGetSymbolAddress((void**)&wol, g_wo_l);
    cudaGetSymbolAddress((void**)&akh, g_akh);    cudaGetSymbolAddress((void**)&avh, g_avh);

    static cudaStream_t s2 = 0;
    static cudaEvent_t evRoot = 0, evW = 0, evWo = 0;
    if (!s2) {
        cudaFuncSetAttribute(gemm_mma,  cudaFuncAttributeMaxDynamicSharedMemorySize, SMEM_GEMM);
        cudaFuncSetAttribute(gemm_mma2, cudaFuncAttributeMaxDynamicSharedMemorySize, SMEM_GEMM2);
        cudaFuncSetAttribute(attn_mma,  cudaFuncAttributeMaxDynamicSharedMemorySize, SMEM_ATT);
        cudaStreamCreateWithFlags(&s2, cudaStreamNonBlocking);
        cudaEventCreateWithFlags(&evRoot, cudaEventDisableTiming);
        cudaEventCreateWithFlags(&evW, cudaEventDisableTiming);
        cudaEventCreateWithFlags(&evWo, cudaEventDisableTiming);
    }

    dim3 t256(256);
    dim3 ttr(32, 8);

    // fork: weight transposes on s2, x split on main
    cudaEventRecord(evRoot, 0);
    cudaStreamWaitEvent(s2, evRoot, 0);

    transpose_split<<<dim3(QW / 32,  DIM / 32), ttr, 0, s2>>>(Wq,  wqkvh, wqkvl, DIM, QW);
    transpose_split<<<dim3(LAT / 32, DIM / 32), ttr, 0, s2>>>(Wkv, wqkvh + (size_t)QW * DIM,
                                                              wqkvl + (size_t)QW * DIM, DIM, LAT);
    transpose_split<<<dim3(KVW / 32, LAT / 32), ttr, 0, s2>>>(Wk, wk2h, wk2l, LAT, KVW);
    transpose_split<<<dim3(KVW / 32, LAT / 32), ttr, 0, s2>>>(Wv, wk2h + (size_t)KVW * LAT,
                                                              wk2l + (size_t)KVW * LAT, LAT, KVW);
    cudaEventRecord(evW, s2);
    transpose_split<<<dim3(DIM / 32, QW / 32), ttr, 0, s2>>>(Wo, woh, wol, QW, DIM);
    cudaEventRecord(evWo, s2);

    split_act<<<(ROWS * DIM / 4 + 255) / 256, t256>>>(x, xh, xl, ROWS * DIM / 4);

    // join for qkv weights; [q | kv] = x @ [Wq | Wkv]  (wide-tile GEMM)
    cudaStreamWaitEvent(0, evW, 0);
    gemm_mma2<<<dim3(QKVW / G2N, ROWS / GM), 512, SMEM_GEMM2>>>(xh, xl, wqkvh, wqkvl, qkv, DIM, QKVW);

    rmsnorm_split<<<ROWS, LAT>>>(qkv, w_norm, kvh, kvl);
    gemm_mma<<<dim3(KVW2 / GN, ROWS / GM), t256, SMEM_GEMM>>>(kvh, kvl, wk2h, wk2l, kvout, LAT, KVW2);
    reorg_kv<<<dim3(SEQ / 64, BATCH * NLH), t256>>>(kvout, akh, avh);

    attn_mma<<<dim3(SEQ / 128, BATCH * NH), t256, SMEM_ATT>>>(qkv, akh, avh, ah, al);

    // join for Wo, then out = att @ Wo  (wide-tile GEMM)
    cudaStreamWaitEvent(0, evWo, 0);
    gemm_mma2<<<dim3(DIM / G2N, ROWS / GM), 512, SMEM_GEMM2>>>(ah, al, woh, wol, out, QW, DIM);
}

// round 15
// speedup vs baseline: 1.5202x; 1.2843x over previous
#include <cuda_runtime.h>
#include <cuda_bf16.h>
#include <cuda_fp16.h>
#include <math.h>
#include <stdint.h>

// ---------------- problem constants ----------------
#define BATCH 2
#define SEQ   2048
#define DIM   2048
#define NH    16
#define HDIM  48
#define LAT   256
#define NLH   8
#define ROWS  (BATCH*SEQ)          // 4096
#define QW    (NH*HDIM)            // 768
#define KVW   (NLH*HDIM)           // 384
#define KVW2  (2*KVW)              // 768 (k|v concat)
#define QKVW  (QW+LAT)             // 1024 (q|kv concat)

// ---------------- scratch ----------------
__device__ float g_qkv  [ROWS * QKVW];   // [q | kv_latent] fp32
__device__ float g_kvout[ROWS * KVW2];   // [k|v] fp32

// fp16 hi/lo activations
__device__ __half g_xh [ROWS * DIM], g_xl [ROWS * DIM];
__device__ __half g_kvh[ROWS * LAT], g_kvl[ROWS * LAT];
__device__ __half g_ah [ROWS * QW],  g_al [ROWS * QW];
// transposed fp16 weights (single precision copy)
__device__ __half g_wqkv[QKVW * DIM];    // [Wq^T ; Wkv^T]
__device__ __half g_wkv2[KVW2 * LAT];    // [Wk^T ; Wv^T]
__device__ __half g_wo  [DIM * QW];
// attention layouts (fp16 single): K: [b][kvh][t][hd]   Vt: [b][kvh][hd][t]
__device__ __half g_akh[BATCH*NLH*SEQ*HDIM];
__device__ __half g_avh[BATCH*NLH*HDIM*SEQ];

// ---------------- helpers ----------------
__device__ __forceinline__ uint32_t smem_u32(const void* p) {
    uint32_t a;
    asm("{ .reg .u64 t; cvta.to.shared.u64 t, %1; cvt.u32.u64 %0, t; }" : "=r"(a) : "l"(p));
    return a;
}

#define CP16(dst, src) \
    asm volatile("cp.async.cg.shared.global [%0], [%1], 16;" :: "r"(dst), "l"(src) : "memory")
#define CP_COMMIT() asm volatile("cp.async.commit_group;" ::: "memory")
#define CP_WAIT0()  asm volatile("cp.async.wait_group 0;" ::: "memory")
#define CP_WAIT1()  asm volatile("cp.async.wait_group 1;" ::: "memory")
#define CP_WAIT2()  asm volatile("cp.async.wait_group 2;" ::: "memory")

#define LDSM4(r0, r1, r2, r3, addr) \
    asm volatile("ldmatrix.sync.aligned.m8n8.x4.shared.b16 {%0,%1,%2,%3}, [%4];" \
        : "=r"(r0), "=r"(r1), "=r"(r2), "=r"(r3) : "r"(addr))

__device__ __forceinline__ void mma16816h(float* c, const uint32_t* a, const uint32_t* b) {
    asm volatile(
        "mma.sync.aligned.m16n8k16.row.col.f32.f16.f16.f32 "
        "{%0,%1,%2,%3}, {%4,%5,%6,%7}, {%8,%9}, {%0,%1,%2,%3};"
        : "+f"(c[0]), "+f"(c[1]), "+f"(c[2]), "+f"(c[3])
        : "r"(a[0]), "r"(a[1]), "r"(a[2]), "r"(a[3]), "r"(b[0]), "r"(b[1]));
}

__device__ __forceinline__ uint32_t packh2(float x, float y) {
    __half2 h = __floats2half2_rn(x, y);
    return *reinterpret_cast<uint32_t*>(&h);
}

// fp16 hi/lo split of a float pair
__device__ __forceinline__ void splith2(float x, float y, uint32_t& h, uint32_t& l) {
    __half2 hb = __floats2half2_rn(x, y);
    h = *reinterpret_cast<uint32_t*>(&hb);
    float hx = __half2float(__low2half(hb));
    float hy = __half2float(__high2half(hb));
    __half2 lb = __floats2half2_rn(x - hx, y - hy);
    l = *reinterpret_cast<uint32_t*>(&lb);
}

__device__ __forceinline__ float exp2_fast(float x) {
    float r;
    asm("ex2.approx.ftz.f32 %0, %1;" : "=f"(r) : "f"(x));
    return r;
}

// ---------------- common GEMM tile constants ----------------
#define GM 128
#define GK 32
#define ROWB 80

// ===== 256-thread 128x128 GEMM: A fp16 hi/lo, B fp16 single, 2 MMAs =====
#define GN 128
#define HT_A (128 * ROWB)          // 10240
#define HOFF_AH 0
#define HOFF_AL (HT_A)
#define HOFF_B  (2*HT_A)
#define HSTAGE  (3*HT_A)           // 30720
#define SMEM_GEMMH (2*HSTAGE)      // 61440

__device__ __forceinline__ void stage_load_h(
    const char* Ah, const char* Al, const char* B,
    uint32_t sbase, int tid, int m0, int n0, int k0, int K)
{
    #pragma unroll
    for (int u = 0; u < 2; u++) {
        const int s   = tid * 2 + u;
        const int row = s >> 2;
        const int cc  = s & 3;
        const uint32_t so = row * ROWB + cc * 16;
        const size_t gA = ((size_t)(m0 + row) * K + k0) * 2 + cc * 16;
        const size_t gB = ((size_t)(n0 + row) * K + k0) * 2 + cc * 16;
        CP16(sbase + HOFF_AH + so, Ah + gA);
        CP16(sbase + HOFF_AL + so, Al + gA);
        CP16(sbase + HOFF_B  + so, B + gB);
    }
}

__global__ __launch_bounds__(256, 2)
void gemm_h(const __half* __restrict__ Ahi, const __half* __restrict__ Alo,
            const __half* __restrict__ B,
            float* __restrict__ C, int K, int ldc) {
    extern __shared__ char smem[];
    const uint32_t sb = smem_u32(smem);
    const int tid = threadIdx.x;
    const int wid = tid >> 5, lid = tid & 31;
    const int wm = wid >> 2;
    const int wn = wid & 3;
    const int g = lid >> 2, ctg = lid & 3;
    const int mat = lid >> 3, mr = lid & 7;
    const int m0 = blockIdx.y * GM;
    const int n0 = blockIdx.x * GN;

    float acc[4][4][4];
    #pragma unroll
    for (int i = 0; i < 4; i++)
        #pragma unroll
        for (int j = 0; j < 4; j++)
            #pragma unroll
            for (int t = 0; t < 4; t++) acc[i][j][t] = 0.0f;

    const int nch = K / GK;
    stage_load_h((const char*)Ahi, (const char*)Alo, (const char*)B,
                 sb, tid, m0, n0, 0, K);
    CP_COMMIT();

    const uint32_t aoff = (uint32_t)((wm * 64 + ((mat & 1) << 3) + mr) * ROWB + ((mat >> 1) << 4));
    const uint32_t boff = (uint32_t)((wn * 32 + ((mat >> 1) << 3) + mr) * ROWB + ((mat & 1) << 4));

    for (int c = 0; c < nch; c++) {
        if (c + 1 < nch) {
            stage_load_h((const char*)Ahi, (const char*)Alo, (const char*)B,
                         sb + ((c + 1) & 1) * HSTAGE, tid, m0, n0, (c + 1) * GK, K);
            CP_COMMIT();
            CP_WAIT1();
        } else {
            CP_WAIT0();
        }
        __syncthreads();

        const uint32_t sAh = sb + (c & 1) * HSTAGE + HOFF_AH;
        const uint32_t sAl = sb + (c & 1) * HSTAGE + HOFF_AL;
        const uint32_t sB  = sb + (c & 1) * HSTAGE + HOFF_B;

        #pragma unroll
        for (int ks = 0; ks < 2; ks++) {
            uint32_t bk[4][2];
            #pragma unroll
            for (int jp = 0; jp < 2; jp++) {
                const uint32_t ba = boff + jp * 16 * ROWB + ks * 32;
                LDSM4(bk[2*jp][0], bk[2*jp][1], bk[2*jp+1][0], bk[2*jp+1][1], sB + ba);
            }
            #pragma unroll
            for (int i = 0; i < 4; i++) {
                const uint32_t aa = aoff + i * 16 * ROWB + ks * 32;
                uint32_t ah[4], al[4];
                LDSM4(ah[0], ah[1], ah[2], ah[3], sAh + aa);
                LDSM4(al[0], al[1], al[2], al[3], sAl + aa);
                #pragma unroll
                for (int j = 0; j < 4; j++) {
                    mma16816h(acc[i][j], ah, bk[j]);
                    mma16816h(acc[i][j], al, bk[j]);
                }
            }
        }
        __syncthreads();
    }

    #pragma unroll
    for (int i = 0; i < 4; i++) {
        const int r0 = m0 + wm * 64 + i * 16 + g;
        #pragma unroll
        for (int j = 0; j < 4; j++) {
            const int c0 = n0 + wn * 32 + j * 8 + ctg * 2;
            float2 v0 = make_float2(acc[i][j][0], acc[i][j][1]);
            float2 v1 = make_float2(acc[i][j][2], acc[i][j][3]);
            *(float2*)(C + (size_t)r0 * ldc + c0)       = v0;
            *(float2*)(C + (size_t)(r0 + 8) * ldc + c0) = v1;
        }
    }
}

// ===== 512-thread 128x256 GEMM: A fp16 hi/lo, B fp16 single =====
#define G2N 256
#define H2OFF_AH 0
#define H2OFF_AL (128*ROWB)            // 10240
#define H2OFF_B  (2*128*ROWB)          // 20480
#define H2STAGE  (2*128*ROWB + 256*ROWB)  // 40960
#define SMEM_GEMM2H (2*H2STAGE)        // 81920

__device__ __forceinline__ void stage_load2_h(
    const char* Ah, const char* Al, const char* B,
    uint32_t sbase, int tid, int m0, int n0, int k0, int K)
{
    {
        const int row = tid >> 2;
        const int cc  = tid & 3;
        const uint32_t so = row * ROWB + cc * 16;
        const size_t gA = ((size_t)(m0 + row) * K + k0) * 2 + cc * 16;
        CP16(sbase + H2OFF_AH + so, Ah + gA);
        CP16(sbase + H2OFF_AL + so, Al + gA);
    }
    #pragma unroll
    for (int u = 0; u < 2; u++) {
        const int s   = tid * 2 + u;
        const int row = s >> 2;
        const int cc  = s & 3;
        const uint32_t so = row * ROWB + cc * 16;
        const size_t gB = ((size_t)(n0 + row) * K + k0) * 2 + cc * 16;
        CP16(sbase + H2OFF_B + so, B + gB);
    }
}

__global__ __launch_bounds__(512, 1)
void gemm2_h(const __half* __restrict__ Ahi, const __half* __restrict__ Alo,
             const __half* __restrict__ B,
             float* __restrict__ C, int K, int ldc) {
    extern __shared__ char smem[];
    const uint32_t sb = smem_u32(smem);
    const int tid = threadIdx.x;
    const int wid = tid >> 5, lid = tid & 31;
    const int wm = wid >> 3;
    const int wn = wid & 7;
    const int g = lid >> 2, ctg = lid & 3;
    const int mat = lid >> 3, mr = lid & 7;
    const int m0 = blockIdx.y * GM;
    const int n0 = blockIdx.x * G2N;

    float acc[4][4][4];
    #pragma unroll
    for (int i = 0; i < 4; i++)
        #pragma unroll
        for (int j = 0; j < 4; j++)
            #pragma unroll
            for (int t = 0; t < 4; t++) acc[i][j][t] = 0.0f;

    const int nch = K / GK;
    stage_load2_h((const char*)Ahi, (const char*)Alo, (const char*)B,
                  sb, tid, m0, n0, 0, K);
    CP_COMMIT();

    const uint32_t aoff = (uint32_t)((wm * 64 + ((mat & 1) << 3) + mr) * ROWB + ((mat >> 1) << 4));
    const uint32_t boff = (uint32_t)((wn * 32 + ((mat >> 1) << 3) + mr) * ROWB + ((mat & 1) << 4));

    for (int c = 0; c < nch; c++) {
        if (c + 1 < nch) {
            stage_load2_h((const char*)Ahi, (const char*)Alo, (const char*)B,
                          sb + ((c + 1) & 1) * H2STAGE, tid, m0, n0, (c + 1) * GK, K);
            CP_COMMIT();
            CP_WAIT1();
        } else {
            CP_WAIT0();
        }
        __syncthreads();

        const uint32_t sAh = sb + (c & 1) * H2STAGE + H2OFF_AH;
        const uint32_t sAl = sb + (c & 1) * H2STAGE + H2OFF_AL;
        const uint32_t sB  = sb + (c & 1) * H2STAGE + H2OFF_B;

        #pragma unroll
        for (int ks = 0; ks < 2; ks++) {
            uint32_t bk[4][2];
            #pragma unroll
            for (int jp = 0; jp < 2; jp++) {
                const uint32_t ba = boff + jp * 16 * ROWB + ks * 32;
                LDSM4(bk[2*jp][0], bk[2*jp][1], bk[2*jp+1][0], bk[2*jp+1][1], sB + ba);
            }
            #pragma unroll
            for (int i = 0; i < 4; i++) {
                const uint32_t aa = aoff + i * 16 * ROWB + ks * 32;
                uint32_t ah[4], al[4];
                LDSM4(ah[0], ah[1], ah[2], ah[3], sAh + aa);
                LDSM4(al[0], al[1], al[2], al[3], sAl + aa);
                #pragma unroll
                for (int j = 0; j < 4; j++) {
                    mma16816h(acc[i][j], ah, bk[j]);
                    mma16816h(acc[i][j], al, bk[j]);
                }
            }
        }
        __syncthreads();
    }

    #pragma unroll
    for (int i = 0; i < 4; i++) {
        const int r0 = m0 + wm * 64 + i * 16 + g;
        #pragma unroll
        for (int j = 0; j < 4; j++) {
            const int c0 = n0 + wn * 32 + j * 8 + ctg * 2;
            float2 v0 = make_float2(acc[i][j][0], acc[i][j][1]);
            float2 v1 = make_float2(acc[i][j][2], acc[i][j][3]);
            *(float2*)(C + (size_t)r0 * ldc + c0)       = v0;
            *(float2*)(C + (size_t)(r0 + 8) * ldc + c0) = v1;
        }
    }
}

// ---------------- fp32 -> fp16 hi/lo split ----------------
__global__ __launch_bounds__(256)
void split_act(const float* __restrict__ in, __half* __restrict__ hi,
               __half* __restrict__ lo, int n4) {
    int i = blockIdx.x * 256 + threadIdx.x;
    if (i >= n4) return;
    float4 v = ((const float4*)in)[i];
    uint32_t h0, l0, h1, l1;
    splith2(v.x, v.y, h0, l0);
    splith2(v.z, v.w, h1, l1);
    ((uint32_t*)hi)[2 * i]     = h0;
    ((uint32_t*)hi)[2 * i + 1] = h1;
    ((uint32_t*)lo)[2 * i]     = l0;
    ((uint32_t*)lo)[2 * i + 1] = l1;
}

// ---------------- W[K,N] fp32 -> Wt[N,K] fp16 ----------------
__global__ __launch_bounds__(256)
void transpose_h(const float* __restrict__ W, __half* __restrict__ t16, int K, int N) {
    __shared__ float ts[32][33];
    const int tx = threadIdx.x;
    const int ty = threadIdx.y;
    const int x0 = blockIdx.x * 32;
    const int y0 = blockIdx.y * 32;
    #pragma unroll
    for (int j = ty; j < 32; j += 8)
        ts[j][tx] = W[(size_t)(y0 + j) * N + x0 + tx];
    __syncthreads();
    #pragma unroll
    for (int j = ty; j < 32; j += 8) {
        size_t o = (size_t)(x0 + j) * K + y0 + tx;
        t16[o] = __float2half(ts[tx][j]);
    }
}

// ---------------- fused RMSNorm + fp16 hi/lo split ----------------
__global__ __launch_bounds__(256)
void rmsnorm_split(const float* __restrict__ qkv, const float* __restrict__ w,
                   __half* __restrict__ oh, __half* __restrict__ ol) {
    const int row = blockIdx.x;
    const int tid = threadIdx.x;
    const int wid = tid >> 5, lane = tid & 31;
    float v = qkv[(size_t)row * QKVW + QW + tid];
    float s = v * v;
    #pragma unroll
    for (int d = 16; d > 0; d >>= 1) s += __shfl_xor_sync(0xffffffffu, s, d);
    __shared__ float ws[8];
    if (lane == 0) ws[wid] = s;
    __syncthreads();
    float tot = ws[0] + ws[1] + ws[2] + ws[3] + ws[4] + ws[5] + ws[6] + ws[7];
    float inv = rsqrtf(tot * (1.0f / LAT) + 1e-5f);
    float r = v * inv * w[tid];
    __half h = __float2half(r);
    __half l = __float2half(r - __half2float(h));
    oh[(size_t)row * LAT + tid] = h;
    ol[(size_t)row * LAT + tid] = l;
}

// ---------------- merged K/V reorg (K,V -> fp16 single) ----------------
__global__ __launch_bounds__(256)
void reorg_kv(const float* __restrict__ kvin,
              __half* __restrict__ kh, __half* __restrict__ vh) {
    __shared__ float vs[64][HDIM + 1];
    const int bkvh = blockIdx.y;
    const int b = bkvh / NLH, kvh = bkvh % NLH;
    const int t0 = blockIdx.x * 64;
    for (int i = threadIdx.x; i < 64 * HDIM; i += 256) {
        const int t = i / HDIM, hd = i % HDIM;
        const size_t src = ((size_t)(b * SEQ + t0 + t)) * KVW2 + kvh * HDIM + hd;
        size_t o = ((size_t)bkvh * SEQ + t0 + t) * HDIM + hd;
        kh[o] = __float2half(kvin[src]);
        vs[t][hd] = kvin[src + KVW];
    }
    __syncthreads();
    for (int i = threadIdx.x; i < 64 * HDIM; i += 256) {
        const int hd = i / 64, t = i % 64;
        size_t o = ((size_t)bkvh * HDIM + hd) * SEQ + t0 + t;
        vh[o] = __float2half(vs[t][hd]);
    }
}

// ---------------- tensor-core causal flash attention ----------------
// Q: fp16 hi/lo; K: fp16; V: fp16. QK 2 MMAs, PV 1 MMA per fragment.
#define KROWB 112
#define VROWB 144
#define A_KH 0
#define A_VH 7168
#define A_STAGE 14080
#define SMEM_ATT (3*A_STAGE)     // 42240

__device__ __forceinline__ void attn_stage(
    uint32_t sbase, const __half* kb, const __half* vb, int tid)
{
    #pragma unroll
    for (int t = 0; t < 3; t++) {
        const int c = tid + t * 256;
        if (c < 384) {
            const int r = c / 6, qd = c - r * 6;
            CP16(sbase + A_KH + r * KROWB + qd * 16, kb + r * HDIM + qd * 8);
        } else {
            const int idx = c - 384;
            const int r = idx >> 3, qd = idx & 7;
            CP16(sbase + A_VH + r * VROWB + qd * 16, vb + (size_t)r * SEQ + qd * 8);
        }
    }
}

__global__ __launch_bounds__(256, 2)
void attn_mma(const float* __restrict__ q,
              const __half* __restrict__ kh, const __half* __restrict__ vth,
              __half* __restrict__ oah, __half* __restrict__ oal) {
    extern __shared__ char smem[];
    const uint32_t sb = smem_u32(smem);

    const int qt = gridDim.x - 1 - blockIdx.x;        // longest first
    const int bh = blockIdx.y;
    const int b = bh / NH, hq = bh % NH;
    const int bkvh = b * NLH + hq / (NH / NLH);
    const int tid = threadIdx.x;
    const int wid = tid >> 5, lid = tid & 31;
    const int g = lid >> 2, cq = lid & 3;
    const int mat = lid >> 3, mr = lid & 7;
    const int qbase = qt * 128 + wid * 16;
    const float scale = rsqrtf((float)HDIM) * 1.44269504088896340736f;

    uint32_t aqh[3][4], aql[3][4];
    {
        const float* qp0 = q + ((size_t)(b * SEQ + qbase + g)) * QKVW + hq * HDIM;
        const float* qp1 = q + ((size_t)(b * SEQ + qbase + g + 8)) * QKVW + hq * HDIM;
        #pragma unroll
        for (int kk = 0; kk < 3; kk++) {
            float2 f0 = *(const float2*)(qp0 + kk * 16 + 2 * cq);
            float2 f1 = *(const float2*)(qp1 + kk * 16 + 2 * cq);
            float2 f2 = *(const float2*)(qp0 + kk * 16 + 2 * cq + 8);
            float2 f3 = *(const float2*)(qp1 + kk * 16 + 2 * cq + 8);
            splith2(f0.x * scale, f0.y * scale, aqh[kk][0], aql[kk][0]);
            splith2(f1.x * scale, f1.y * scale, aqh[kk][1], aql[kk][1]);
            splith2(f2.x * scale, f2.y * scale, aqh[kk][2], aql[kk][2]);
            splith2(f3.x * scale, f3.y * scale, aqh[kk][3], aql[kk][3]);
        }
    }

    float o[6][4];
    #pragma unroll
    for (int jn = 0; jn < 6; jn++)
        #pragma unroll
        for (int t = 0; t < 4; t++) o[jn][t] = 0.0f;
    float m0 = -1e30f, m1 = -1e30f, l0 = 0.0f, l1 = 0.0f;

    const __half* kB = kh  + (size_t)bkvh * SEQ * HDIM;
    const __half* vB = vth + (size_t)bkvh * HDIM * SEQ;

    const uint32_t kboff = (uint32_t)((((mat >> 1) << 3) + mr) * KROWB + ((mat & 1) << 4));
    const uint32_t vboff = (uint32_t)((((mat >> 1) << 3) + mr) * VROWB + ((mat & 1) << 4));

    const int nkt = 2 * qt + 2;
    attn_stage(sb, kB, vB, tid);
    CP_COMMIT();
    attn_stage(sb + A_STAGE, kB + 64 * HDIM, vB + 64, tid);
    CP_COMMIT();

    int buf = 0;
    for (int kt = 0; kt < nkt; kt++) {
        if (kt + 2 < nkt) {
            const int nb = (buf + 2) % 3;
            attn_stage(sb + nb * A_STAGE, kB + (kt + 2) * 64 * HDIM, vB + (kt + 2) * 64, tid);
            CP_COMMIT();
            CP_WAIT2();
        } else if (kt + 1 < nkt) {
            CP_WAIT1();
        } else {
            CP_WAIT0();
        }
        __syncthreads();

        const bool full_skip = (kt * 64 > qbase + 15);
        if (!full_skip) {
            const uint32_t st = sb + buf * A_STAGE;
            const uint32_t sKh = st + A_KH;
            const uint32_t sVh = st + A_VH;

            float p[8][4];
            #pragma unroll
            for (int j = 0; j < 8; j++)
                p[j][0] = p[j][1] = p[j][2] = p[j][3] = 0.0f;
            #pragma unroll
            for (int kk = 0; kk < 3; kk++) {
                #pragma unroll
                for (int jp = 0; jp < 4; jp++) {
                    const uint32_t ba = kboff + jp * 16 * KROWB + kk * 32;
                    uint32_t bk[2][2];
                    LDSM4(bk[0][0], bk[0][1], bk[1][0], bk[1][1], sKh + ba);
                    mma16816h(p[2*jp],   aqh[kk], bk[0]);
                    mma16816h(p[2*jp],   aql[kk], bk[0]);
                    mma16816h(p[2*jp+1], aqh[kk], bk[1]);
                    mma16816h(p[2*jp+1], aql[kk], bk[1]);
                }
            }

            if (kt * 64 + 63 > qbase) {
                const int qr0 = qbase + g;
                #pragma unroll
                for (int j = 0; j < 8; j++) {
                    const int key0 = kt * 64 + j * 8 + 2 * cq;
                    if (key0 > qr0)         p[j][0] = -1e30f;
                    if (key0 + 1 > qr0)     p[j][1] = -1e30f;
                    if (key0 > qr0 + 8)     p[j][2] = -1e30f;
                    if (key0 + 1 > qr0 + 8) p[j][3] = -1e30f;
                }
            }

            float mx0 = -1e30f, mx1 = -1e30f;
            #pragma unroll
            for (int j = 0; j < 8; j++) {
                mx0 = fmaxf(mx0, fmaxf(p[j][0], p[j][1]));
                mx1 = fmaxf(mx1, fmaxf(p[j][2], p[j][3]));
            }
            mx0 = fmaxf(mx0, __shfl_xor_sync(0xffffffffu, mx0, 1));
            mx0 = fmaxf(mx0, __shfl_xor_sync(0xffffffffu, mx0, 2));
            mx1 = fmaxf(mx1, __shfl_xor_sync(0xffffffffu, mx1, 1));
            mx1 = fmaxf(mx1, __shfl_xor_sync(0xffffffffu, mx1, 2));
            const float mn0 = fmaxf(m0, mx0), mn1 = fmaxf(m1, mx1);
            const float cr0 = exp2_fast(m0 - mn0), cr1 = exp2_fast(m1 - mn1);
            m0 = mn0; m1 = mn1;
            l0 *= cr0; l1 *= cr1;
            #pragma unroll
            for (int jn = 0; jn < 6; jn++) {
                o[jn][0] *= cr0; o[jn][1] *= cr0;
                o[jn][2] *= cr1; o[jn][3] *= cr1;
            }
            #pragma unroll
            for (int j = 0; j < 8; j++) {
                p[j][0] = exp2_fast(p[j][0] - m0);
                p[j][1] = exp2_fast(p[j][1] - m0);
                p[j][2] = exp2_fast(p[j][2] - m1);
                p[j][3] = exp2_fast(p[j][3] - m1);
                l0 += p[j][0] + p[j][1];
                l1 += p[j][2] + p[j][3];
            }

            #pragma unroll
            for (int kc = 0; kc < 4; kc++) {
                uint32_t aP[4];
                aP[0] = packh2(p[2 * kc][0],     p[2 * kc][1]);
                aP[1] = packh2(p[2 * kc][2],     p[2 * kc][3]);
                aP[2] = packh2(p[2 * kc + 1][0], p[2 * kc + 1][1]);
                aP[3] = packh2(p[2 * kc + 1][2], p[2 * kc + 1][3]);
                #pragma unroll
                for (int jp = 0; jp < 3; jp++) {
                    const uint32_t ba = vboff + jp * 16 * VROWB + kc * 32;
                    uint32_t bv[2][2];
                    LDSM4(bv[0][0], bv[0][1], bv[1][0], bv[1][1], sVh + ba);
                    mma16816h(o[2*jp],   aP, bv[0]);
                    mma16816h(o[2*jp+1], aP, bv[1]);
                }
            }
        }
        __syncthreads();
        buf = (buf + 1 == 3) ? 0 : (buf + 1);
    }

    l0 += __shfl_xor_sync(0xffffffffu, l0, 1);
    l0 += __shfl_xor_sync(0xffffffffu, l0, 2);
    l1 += __shfl_xor_sync(0xffffffffu, l1, 1);
    l1 += __shfl_xor_sync(0xffffffffu, l1, 2);
    const float inv0 = 1.0f / l0, inv1 = 1.0f / l1;

    const size_t base0 = ((size_t)(b * SEQ + qbase + g)) * QW + hq * HDIM;
    const size_t base1 = ((size_t)(b * SEQ + qbase + g + 8)) * QW + hq * HDIM;
    #pragma unroll
    for (int jn = 0; jn < 6; jn++) {
        uint32_t hb, lb;
        splith2(o[jn][0] * inv0, o[jn][1] * inv0, hb, lb);
        *(uint32_t*)&oah[base0 + jn * 8 + 2 * cq] = hb;
        *(uint32_t*)&oal[base0 + jn * 8 + 2 * cq] = lb;
        splith2(o[jn][2] * inv1, o[jn][3] * inv1, hb, lb);
        *(uint32_t*)&oah[base1 + jn * 8 + 2 * cq] = hb;
        *(uint32_t*)&oal[base1 + jn * 8 + 2 * cq] = lb;
    }
}

// ---------------- launch (R11 schedule) ----------------
extern "C" void kernel_launch(void* const* d_in, const int* in_sizes, int n_in,
                              void* d_out, int out_size) {
    const float* x      = (const float*)d_in[0];
    const float* Wq     = (const float*)d_in[2];
    const float* Wkv    = (const float*)d_in[3];
    const float* w_norm = (const float*)d_in[4];
    const float* Wk     = (const float*)d_in[5];
    const float* Wv     = (const float*)d_in[6];
    const float* Wo     = (const float*)d_in[7];
    float* out = (float*)d_out;

    float *qkv, *kvout;
    cudaGetSymbolAddress((void**)&qkv,   g_qkv);
    cudaGetSymbolAddress((void**)&kvout, g_kvout);

    __half *xh, *xl, *kvh, *kvl, *ah, *al;
    __half *wqkv, *wkv2, *wo;
    __half *akh, *avh;
    cudaGetSymbolAddress((void**)&xh,  g_xh);   cudaGetSymbolAddress((void**)&xl,  g_xl);
    cudaGetSymbolAddress((void**)&kvh, g_kvh);  cudaGetSymbolAddress((void**)&kvl, g_kvl);
    cudaGetSymbolAddress((void**)&ah,  g_ah);   cudaGetSymbolAddress((void**)&al,  g_al);
    cudaGetSymbolAddress((void**)&wqkv, g_wqkv);
    cudaGetSymbolAddress((void**)&wkv2, g_wkv2);
    cudaGetSymbolAddress((void**)&wo,   g_wo);
    cudaGetSymbolAddress((void**)&akh, g_akh);  cudaGetSymbolAddress((void**)&avh, g_avh);

    static cudaStream_t s2 = 0;
    static cudaEvent_t evRoot = 0, evW = 0, evWo = 0;
    if (!s2) {
        cudaFuncSetAttribute(gemm_h,   cudaFuncAttributeMaxDynamicSharedMemorySize, SMEM_GEMMH);
        cudaFuncSetAttribute(gemm2_h,  cudaFuncAttributeMaxDynamicSharedMemorySize, SMEM_GEMM2H);
        cudaFuncSetAttribute(attn_mma, cudaFuncAttributeMaxDynamicSharedMemorySize, SMEM_ATT);
        cudaStreamCreateWithFlags(&s2, cudaStreamNonBlocking);
        cudaEventCreateWithFlags(&evRoot, cudaEventDisableTiming);
        cudaEventCreateWithFlags(&evW, cudaEventDisableTiming);
        cudaEventCreateWithFlags(&evWo, cudaEventDisableTiming);
    }

    dim3 t256(256);
    dim3 ttr(32, 8);

    // fork: weight transposes on s2, x split on main
    cudaEventRecord(evRoot, 0);
    cudaStreamWaitEvent(s2, evRoot, 0);

    transpose_h<<<dim3(QW / 32,  DIM / 32), ttr, 0, s2>>>(Wq,  wqkv, DIM, QW);
    transpose_h<<<dim3(LAT / 32, DIM / 32), ttr, 0, s2>>>(Wkv, wqkv + (size_t)QW * DIM, DIM, LAT);
    transpose_h<<<dim3(KVW / 32, LAT / 32), ttr, 0, s2>>>(Wk, wkv2, LAT, KVW);
    transpose_h<<<dim3(KVW / 32, LAT / 32), ttr, 0, s2>>>(Wv, wkv2 + (size_t)KVW * LAT, LAT, KVW);
    cudaEventRecord(evW, s2);
    transpose_h<<<dim3(DIM / 32, QW / 32), ttr, 0, s2>>>(Wo, wo, QW, DIM);
    cudaEventRecord(evWo, s2);

    split_act<<<(ROWS * DIM / 4 + 255) / 256, t256>>>(x, xh, xl, ROWS * DIM / 4);

    // join for qkv weights; [q | kv] = x @ [Wq | Wkv]
    cudaStreamWaitEvent(0, evW, 0);
    gemm2_h<<<dim3(QKVW / G2N, ROWS / GM), 512, SMEM_GEMM2H>>>(xh, xl, wqkv, qkv, DIM, QKVW);

    rmsnorm_split<<<ROWS, LAT>>>(qkv, w_norm, kvh, kvl);
    gemm_h<<<dim3(KVW2 / GN, ROWS / GM), t256, SMEM_GEMMH>>>(kvh, kvl, wkv2, kvout, LAT, KVW2);
    reorg_kv<<<dim3(SEQ / 64, BATCH * NLH), t256>>>(kvout, akh, avh);

    attn_mma<<<dim3(SEQ / 128, BATCH * NH), t256, SMEM_ATT>>>(qkv, akh, avh, ah, al);

    // join for Wo, then out = att @ Wo
    cudaStreamWaitEvent(0, evWo, 0);
    gemm2_h<<<dim3(DIM / G2N, ROWS / GM), 512, SMEM_GEMM2H>>>(ah, al, wo, out, QW, DIM);
}

// round 16
// speedup vs baseline: 1.8867x; 1.2411x over previous
#include <cuda_runtime.h>
#include <cuda_bf16.h>
#include <cuda_fp16.h>
#include <math.h>
#include <stdint.h>

// ---------------- problem constants ----------------
#define BATCH 2
#define SEQ   2048
#define DIM   2048
#define NH    16
#define HDIM  48
#define LAT   256
#define NLH   8
#define ROWS  (BATCH*SEQ)          // 4096
#define QW    (NH*HDIM)            // 768
#define KVW   (NLH*HDIM)           // 384
#define KVW2  (2*KVW)              // 768 (k|v concat)
#define QKVW  (QW+LAT)             // 1024 (q|kv concat)

// ---------------- scratch ----------------
__device__ float g_qkv  [ROWS * QKVW];   // [q | kv_latent] fp32
__device__ float g_kvout[ROWS * KVW2];   // [k|v] fp32

__device__ __half g_x16[ROWS * DIM];                   // x single fp16
__device__ __half g_kvh[ROWS * LAT], g_kvl[ROWS * LAT]; // kv latent hi/lo
__device__ __half g_a16[ROWS * QW];                     // attention out single fp16
// transposed fp16 weights
__device__ __half g_wqkv[QKVW * DIM];    // [Wq^T ; Wkv^T]
__device__ __half g_wkv2[KVW2 * LAT];    // [Wk^T ; Wv^T]
__device__ __half g_wo  [DIM * QW];
// attention layouts (fp16 single): K: [b][kvh][t][hd]   Vt: [b][kvh][hd][t]
__device__ __half g_akh[BATCH*NLH*SEQ*HDIM];
__device__ __half g_avh[BATCH*NLH*HDIM*SEQ];

// ---------------- helpers ----------------
__device__ __forceinline__ uint32_t smem_u32(const void* p) {
    uint32_t a;
    asm("{ .reg .u64 t; cvta.to.shared.u64 t, %1; cvt.u32.u64 %0, t; }" : "=r"(a) : "l"(p));
    return a;
}

#define CP16(dst, src) \
    asm volatile("cp.async.cg.shared.global [%0], [%1], 16;" :: "r"(dst), "l"(src) : "memory")
#define CP_COMMIT() asm volatile("cp.async.commit_group;" ::: "memory")
#define CP_WAIT0()  asm volatile("cp.async.wait_group 0;" ::: "memory")
#define CP_WAIT1()  asm volatile("cp.async.wait_group 1;" ::: "memory")
#define CP_WAIT2()  asm volatile("cp.async.wait_group 2;" ::: "memory")

#define LDSM4(r0, r1, r2, r3, addr) \
    asm volatile("ldmatrix.sync.aligned.m8n8.x4.shared.b16 {%0,%1,%2,%3}, [%4];" \
        : "=r"(r0), "=r"(r1), "=r"(r2), "=r"(r3) : "r"(addr))

__device__ __forceinline__ void mma16816h(float* c, const uint32_t* a, const uint32_t* b) {
    asm volatile(
        "mma.sync.aligned.m16n8k16.row.col.f32.f16.f16.f32 "
        "{%0,%1,%2,%3}, {%4,%5,%6,%7}, {%8,%9}, {%0,%1,%2,%3};"
        : "+f"(c[0]), "+f"(c[1]), "+f"(c[2]), "+f"(c[3])
        : "r"(a[0]), "r"(a[1]), "r"(a[2]), "r"(a[3]), "r"(b[0]), "r"(b[1]));
}

__device__ __forceinline__ uint32_t packh2(float x, float y) {
    __half2 h = __floats2half2_rn(x, y);
    return *reinterpret_cast<uint32_t*>(&h);
}

__device__ __forceinline__ void splith2(float x, float y, uint32_t& h, uint32_t& l) {
    __half2 hb = __floats2half2_rn(x, y);
    h = *reinterpret_cast<uint32_t*>(&hb);
    float hx = __half2float(__low2half(hb));
    float hy = __half2float(__high2half(hb));
    __half2 lb = __floats2half2_rn(x - hx, y - hy);
    l = *reinterpret_cast<uint32_t*>(&lb);
}

__device__ __forceinline__ float exp2_fast(float x) {
    float r;
    asm("ex2.approx.ftz.f32 %0, %1;" : "=f"(r) : "f"(x));
    return r;
}

// ---------------- common GEMM tile constants ----------------
#define GM 128
#define GK 32
#define ROWB 80

// ===== 256-thread 128x128 GEMM: A fp16 hi/lo, B fp16, 2 MMAs (kv2) =====
#define GN 128
#define HT_A (128 * ROWB)
#define HOFF_AH 0
#define HOFF_AL (HT_A)
#define HOFF_B  (2*HT_A)
#define HSTAGE  (3*HT_A)           // 30720
#define SMEM_GEMMH (2*HSTAGE)      // 61440

__device__ __forceinline__ void stage_load_h(
    const char* Ah, const char* Al, const char* B,
    uint32_t sbase, int tid, int m0, int n0, int k0, int K)
{
    #pragma unroll
    for (int u = 0; u < 2; u++) {
        const int s   = tid * 2 + u;
        const int row = s >> 2;
        const int cc  = s & 3;
        const uint32_t so = row * ROWB + cc * 16;
        const size_t gA = ((size_t)(m0 + row) * K + k0) * 2 + cc * 16;
        const size_t gB = ((size_t)(n0 + row) * K + k0) * 2 + cc * 16;
        CP16(sbase + HOFF_AH + so, Ah + gA);
        CP16(sbase + HOFF_AL + so, Al + gA);
        CP16(sbase + HOFF_B  + so, B + gB);
    }
}

__global__ __launch_bounds__(256, 2)
void gemm_h(const __half* __restrict__ Ahi, const __half* __restrict__ Alo,
            const __half* __restrict__ B,
            float* __restrict__ C, int K, int ldc) {
    extern __shared__ char smem[];
    const uint32_t sb = smem_u32(smem);
    const int tid = threadIdx.x;
    const int wid = tid >> 5, lid = tid & 31;
    const int wm = wid >> 2;
    const int wn = wid & 3;
    const int g = lid >> 2, ctg = lid & 3;
    const int mat = lid >> 3, mr = lid & 7;
    const int m0 = blockIdx.y * GM;
    const int n0 = blockIdx.x * GN;

    float acc[4][4][4];
    #pragma unroll
    for (int i = 0; i < 4; i++)
        #pragma unroll
        for (int j = 0; j < 4; j++)
            #pragma unroll
            for (int t = 0; t < 4; t++) acc[i][j][t] = 0.0f;

    const int nch = K / GK;
    stage_load_h((const char*)Ahi, (const char*)Alo, (const char*)B,
                 sb, tid, m0, n0, 0, K);
    CP_COMMIT();

    const uint32_t aoff = (uint32_t)((wm * 64 + ((mat & 1) << 3) + mr) * ROWB + ((mat >> 1) << 4));
    const uint32_t boff = (uint32_t)((wn * 32 + ((mat >> 1) << 3) + mr) * ROWB + ((mat & 1) << 4));

    for (int c = 0; c < nch; c++) {
        if (c + 1 < nch) {
            stage_load_h((const char*)Ahi, (const char*)Alo, (const char*)B,
                         sb + ((c + 1) & 1) * HSTAGE, tid, m0, n0, (c + 1) * GK, K);
            CP_COMMIT();
            CP_WAIT1();
        } else {
            CP_WAIT0();
        }
        __syncthreads();

        const uint32_t sAh = sb + (c & 1) * HSTAGE + HOFF_AH;
        const uint32_t sAl = sb + (c & 1) * HSTAGE + HOFF_AL;
        const uint32_t sB  = sb + (c & 1) * HSTAGE + HOFF_B;

        #pragma unroll
        for (int ks = 0; ks < 2; ks++) {
            uint32_t bk[4][2];
            #pragma unroll
            for (int jp = 0; jp < 2; jp++) {
                const uint32_t ba = boff + jp * 16 * ROWB + ks * 32;
                LDSM4(bk[2*jp][0], bk[2*jp][1], bk[2*jp+1][0], bk[2*jp+1][1], sB + ba);
            }
            #pragma unroll
            for (int i = 0; i < 4; i++) {
                const uint32_t aa = aoff + i * 16 * ROWB + ks * 32;
                uint32_t ah[4], al[4];
                LDSM4(ah[0], ah[1], ah[2], ah[3], sAh + aa);
                LDSM4(al[0], al[1], al[2], al[3], sAl + aa);
                #pragma unroll
                for (int j = 0; j < 4; j++) {
                    mma16816h(acc[i][j], ah, bk[j]);
                    mma16816h(acc[i][j], al, bk[j]);
                }
            }
        }
        __syncthreads();
    }

    #pragma unroll
    for (int i = 0; i < 4; i++) {
        const int r0 = m0 + wm * 64 + i * 16 + g;
        #pragma unroll
        for (int j = 0; j < 4; j++) {
            const int c0 = n0 + wn * 32 + j * 8 + ctg * 2;
            float2 v0 = make_float2(acc[i][j][0], acc[i][j][1]);
            float2 v1 = make_float2(acc[i][j][2], acc[i][j][3]);
            *(float2*)(C + (size_t)r0 * ldc + c0)       = v0;
            *(float2*)(C + (size_t)(r0 + 8) * ldc + c0) = v1;
        }
    }
}

// ===== 512-thread 128x256 GEMM: A fp16 single, B fp16 single, 1 MMA =====
#define G2N 256
#define S1OFF_A 0
#define S1OFF_B (128*ROWB)             // 10240
#define S1STAGE (128*ROWB + 256*ROWB)  // 30720
#define SMEM_GEMM1 (2*S1STAGE)         // 61440

__device__ __forceinline__ void stage_load1(
    const char* A, const char* B,
    uint32_t sbase, int tid, int m0, int n0, int k0, int K)
{
    {
        const int row = tid >> 2;
        const int cc  = tid & 3;
        const uint32_t so = row * ROWB + cc * 16;
        const size_t gA = ((size_t)(m0 + row) * K + k0) * 2 + cc * 16;
        CP16(sbase + S1OFF_A + so, A + gA);
    }
    #pragma unroll
    for (int u = 0; u < 2; u++) {
        const int s   = tid * 2 + u;
        const int row = s >> 2;
        const int cc  = s & 3;
        const uint32_t so = row * ROWB + cc * 16;
        const size_t gB = ((size_t)(n0 + row) * K + k0) * 2 + cc * 16;
        CP16(sbase + S1OFF_B + so, B + gB);
    }
}

__global__ __launch_bounds__(512, 1)
void gemm1(const __half* __restrict__ A, const __half* __restrict__ B,
           float* __restrict__ C, int K, int ldc) {
    extern __shared__ char smem[];
    const uint32_t sb = smem_u32(smem);
    const int tid = threadIdx.x;
    const int wid = tid >> 5, lid = tid & 31;
    const int wm = wid >> 3;
    const int wn = wid & 7;
    const int g = lid >> 2, ctg = lid & 3;
    const int mat = lid >> 3, mr = lid & 7;
    const int m0 = blockIdx.y * GM;
    const int n0 = blockIdx.x * G2N;

    float acc[4][4][4];
    #pragma unroll
    for (int i = 0; i < 4; i++)
        #pragma unroll
        for (int j = 0; j < 4; j++)
            #pragma unroll
            for (int t = 0; t < 4; t++) acc[i][j][t] = 0.0f;

    const int nch = K / GK;
    stage_load1((const char*)A, (const char*)B, sb, tid, m0, n0, 0, K);
    CP_COMMIT();

    const uint32_t aoff = (uint32_t)((wm * 64 + ((mat & 1) << 3) + mr) * ROWB + ((mat >> 1) << 4));
    const uint32_t boff = (uint32_t)((wn * 32 + ((mat >> 1) << 3) + mr) * ROWB + ((mat & 1) << 4));

    for (int c = 0; c < nch; c++) {
        if (c + 1 < nch) {
            stage_load1((const char*)A, (const char*)B,
                        sb + ((c + 1) & 1) * S1STAGE, tid, m0, n0, (c + 1) * GK, K);
            CP_COMMIT();
            CP_WAIT1();
        } else {
            CP_WAIT0();
        }
        __syncthreads();

        const uint32_t sA = sb + (c & 1) * S1STAGE + S1OFF_A;
        const uint32_t sB = sb + (c & 1) * S1STAGE + S1OFF_B;

        #pragma unroll
        for (int ks = 0; ks < 2; ks++) {
            uint32_t bk[4][2];
            #pragma unroll
            for (int jp = 0; jp < 2; jp++) {
                const uint32_t ba = boff + jp * 16 * ROWB + ks * 32;
                LDSM4(bk[2*jp][0], bk[2*jp][1], bk[2*jp+1][0], bk[2*jp+1][1], sB + ba);
            }
            #pragma unroll
            for (int i = 0; i < 4; i++) {
                const uint32_t aa = aoff + i * 16 * ROWB + ks * 32;
                uint32_t ah[4];
                LDSM4(ah[0], ah[1], ah[2], ah[3], sA + aa);
                #pragma unroll
                for (int j = 0; j < 4; j++)
                    mma16816h(acc[i][j], ah, bk[j]);
            }
        }
        __syncthreads();
    }

    #pragma unroll
    for (int i = 0; i < 4; i++) {
        const int r0 = m0 + wm * 64 + i * 16 + g;
        #pragma unroll
        for (int j = 0; j < 4; j++) {
            const int c0 = n0 + wn * 32 + j * 8 + ctg * 2;
            float2 v0 = make_float2(acc[i][j][0], acc[i][j][1]);
            float2 v1 = make_float2(acc[i][j][2], acc[i][j][3]);
            *(float2*)(C + (size_t)r0 * ldc + c0)       = v0;
            *(float2*)(C + (size_t)(r0 + 8) * ldc + c0) = v1;
        }
    }
}

// ---------------- fp32 -> fp16 convert ----------------
__global__ __launch_bounds__(256)
void convert_h(const float* __restrict__ in, __half* __restrict__ o16, int n4) {
    int i = blockIdx.x * 256 + threadIdx.x;
    if (i >= n4) return;
    float4 v = ((const float4*)in)[i];
    ((uint32_t*)o16)[2 * i]     = packh2(v.x, v.y);
    ((uint32_t*)o16)[2 * i + 1] = packh2(v.z, v.w);
}

// ---------------- W[K,N] fp32 -> Wt[N,K] fp16 ----------------
__global__ __launch_bounds__(256)
void transpose_h(const float* __restrict__ W, __half* __restrict__ t16, int K, int N) {
    __shared__ float ts[32][33];
    const int tx = threadIdx.x;
    const int ty = threadIdx.y;
    const int x0 = blockIdx.x * 32;
    const int y0 = blockIdx.y * 32;
    #pragma unroll
    for (int j = ty; j < 32; j += 8)
        ts[j][tx] = W[(size_t)(y0 + j) * N + x0 + tx];
    __syncthreads();
    #pragma unroll
    for (int j = ty; j < 32; j += 8) {
        size_t o = (size_t)(x0 + j) * K + y0 + tx;
        t16[o] = __float2half(ts[tx][j]);
    }
}

// ---------------- fused RMSNorm + fp16 hi/lo split ----------------
__global__ __launch_bounds__(256)
void rmsnorm_split(const float* __restrict__ qkv, const float* __restrict__ w,
                   __half* __restrict__ oh, __half* __restrict__ ol) {
    const int row = blockIdx.x;
    const int tid = threadIdx.x;
    const int wid = tid >> 5, lane = tid & 31;
    float v = qkv[(size_t)row * QKVW + QW + tid];
    float s = v * v;
    #pragma unroll
    for (int d = 16; d > 0; d >>= 1) s += __shfl_xor_sync(0xffffffffu, s, d);
    __shared__ float ws[8];
    if (lane == 0) ws[wid] = s;
    __syncthreads();
    float tot = ws[0] + ws[1] + ws[2] + ws[3] + ws[4] + ws[5] + ws[6] + ws[7];
    float inv = rsqrtf(tot * (1.0f / LAT) + 1e-5f);
    float r = v * inv * w[tid];
    __half h = __float2half(r);
    __half l = __float2half(r - __half2float(h));
    oh[(size_t)row * LAT + tid] = h;
    ol[(size_t)row * LAT + tid] = l;
}

// ---------------- merged K/V reorg (K,V -> fp16 single) ----------------
__global__ __launch_bounds__(256)
void reorg_kv(const float* __restrict__ kvin,
              __half* __restrict__ kh, __half* __restrict__ vh) {
    __shared__ float vs[64][HDIM + 1];
    const int bkvh = blockIdx.y;
    const int b = bkvh / NLH, kvh = bkvh % NLH;
    const int t0 = blockIdx.x * 64;
    for (int i = threadIdx.x; i < 64 * HDIM; i += 256) {
        const int t = i / HDIM, hd = i % HDIM;
        const size_t src = ((size_t)(b * SEQ + t0 + t)) * KVW2 + kvh * HDIM + hd;
        size_t o = ((size_t)bkvh * SEQ + t0 + t) * HDIM + hd;
        kh[o] = __float2half(kvin[src]);
        vs[t][hd] = kvin[src + KVW];
    }
    __syncthreads();
    for (int i = threadIdx.x; i < 64 * HDIM; i += 256) {
        const int hd = i / 64, t = i % 64;
        size_t o = ((size_t)bkvh * HDIM + hd) * SEQ + t0 + t;
        vh[o] = __float2half(vs[t][hd]);
    }
}

// ---------------- tensor-core causal flash attention ----------------
// Q: fp16 hi/lo; K,V: fp16 single. QK 2 MMAs, PV 1 MMA per fragment.
// Output: single fp16 (feeds single-A Wo GEMM).
#define KROWB 112
#define VROWB 144
#define A_KH 0
#define A_VH 7168
#define A_STAGE 14080
#define SMEM_ATT (3*A_STAGE)     // 42240

__device__ __forceinline__ void attn_stage(
    uint32_t sbase, const __half* kb, const __half* vb, int tid)
{
    #pragma unroll
    for (int t = 0; t < 3; t++) {
        const int c = tid + t * 256;
        if (c < 384) {
            const int r = c / 6, qd = c - r * 6;
            CP16(sbase + A_KH + r * KROWB + qd * 16, kb + r * HDIM + qd * 8);
        } else {
            const int idx = c - 384;
            const int r = idx >> 3, qd = idx & 7;
            CP16(sbase + A_VH + r * VROWB + qd * 16, vb + (size_t)r * SEQ + qd * 8);
        }
    }
}

__global__ __launch_bounds__(256, 2)
void attn_mma(const float* __restrict__ q,
              const __half* __restrict__ kh, const __half* __restrict__ vth,
              __half* __restrict__ oa) {
    extern __shared__ char smem[];
    const uint32_t sb = smem_u32(smem);

    const int qt = gridDim.x - 1 - blockIdx.x;        // longest first
    const int bh = blockIdx.y;
    const int b = bh / NH, hq = bh % NH;
    const int bkvh = b * NLH + hq / (NH / NLH);
    const int tid = threadIdx.x;
    const int wid = tid >> 5, lid = tid & 31;
    const int g = lid >> 2, cq = lid & 3;
    const int mat = lid >> 3, mr = lid & 7;
    const int qbase = qt * 128 + wid * 16;
    const float scale = rsqrtf((float)HDIM) * 1.44269504088896340736f;

    uint32_t aqh[3][4], aql[3][4];
    {
        const float* qp0 = q + ((size_t)(b * SEQ + qbase + g)) * QKVW + hq * HDIM;
        const float* qp1 = q + ((size_t)(b * SEQ + qbase + g + 8)) * QKVW + hq * HDIM;
        #pragma unroll
        for (int kk = 0; kk < 3; kk++) {
            float2 f0 = *(const float2*)(qp0 + kk * 16 + 2 * cq);
            float2 f1 = *(const float2*)(qp1 + kk * 16 + 2 * cq);
            float2 f2 = *(const float2*)(qp0 + kk * 16 + 2 * cq + 8);
            float2 f3 = *(const float2*)(qp1 + kk * 16 + 2 * cq + 8);
            splith2(f0.x * scale, f0.y * scale, aqh[kk][0], aql[kk][0]);
            splith2(f1.x * scale, f1.y * scale, aqh[kk][1], aql[kk][1]);
            splith2(f2.x * scale, f2.y * scale, aqh[kk][2], aql[kk][2]);
            splith2(f3.x * scale, f3.y * scale, aqh[kk][3], aql[kk][3]);
        }
    }

    float o[6][4];
    #pragma unroll
    for (int jn = 0; jn < 6; jn++)
        #pragma unroll
        for (int t = 0; t < 4; t++) o[jn][t] = 0.0f;
    float m0 = -1e30f, m1 = -1e30f, l0 = 0.0f, l1 = 0.0f;

    const __half* kB = kh  + (size_t)bkvh * SEQ * HDIM;
    const __half* vB = vth + (size_t)bkvh * HDIM * SEQ;

    const uint32_t kboff = (uint32_t)((((mat >> 1) << 3) + mr) * KROWB + ((mat & 1) << 4));
    const uint32_t vboff = (uint32_t)((((mat >> 1) << 3) + mr) * VROWB + ((mat & 1) << 4));

    const int nkt = 2 * qt + 2;
    attn_stage(sb, kB, vB, tid);
    CP_COMMIT();
    attn_stage(sb + A_STAGE, kB + 64 * HDIM, vB + 64, tid);
    CP_COMMIT();

    int buf = 0;
    for (int kt = 0; kt < nkt; kt++) {
        if (kt + 2 < nkt) {
            const int nb = (buf + 2) % 3;
            attn_stage(sb + nb * A_STAGE, kB + (kt + 2) * 64 * HDIM, vB + (kt + 2) * 64, tid);
            CP_COMMIT();
            CP_WAIT2();
        } else if (kt + 1 < nkt) {
            CP_WAIT1();
        } else {
            CP_WAIT0();
        }
        __syncthreads();

        const bool full_skip = (kt * 64 > qbase + 15);
        if (!full_skip) {
            const uint32_t st = sb + buf * A_STAGE;
            const uint32_t sKh = st + A_KH;
            const uint32_t sVh = st + A_VH;

            float p[8][4];
            #pragma unroll
            for (int j = 0; j < 8; j++)
                p[j][0] = p[j][1] = p[j][2] = p[j][3] = 0.0f;
            #pragma unroll
            for (int kk = 0; kk < 3; kk++) {
                #pragma unroll
                for (int jp = 0; jp < 4; jp++) {
                    const uint32_t ba = kboff + jp * 16 * KROWB + kk * 32;
                    uint32_t bk[2][2];
                    LDSM4(bk[0][0], bk[0][1], bk[1][0], bk[1][1], sKh + ba);
                    mma16816h(p[2*jp],   aqh[kk], bk[0]);
                    mma16816h(p[2*jp],   aql[kk], bk[0]);
                    mma16816h(p[2*jp+1], aqh[kk], bk[1]);
                    mma16816h(p[2*jp+1], aql[kk], bk[1]);
                }
            }

            if (kt * 64 + 63 > qbase) {
                const int qr0 = qbase + g;
                #pragma unroll
                for (int j = 0; j < 8; j++) {
                    const int key0 = kt * 64 + j * 8 + 2 * cq;
                    if (key0 > qr0)         p[j][0] = -1e30f;
                    if (key0 + 1 > qr0)     p[j][1] = -1e30f;
                    if (key0 > qr0 + 8)     p[j][2] = -1e30f;
                    if (key0 + 1 > qr0 + 8) p[j][3] = -1e30f;
                }
            }

            float mx0 = -1e30f, mx1 = -1e30f;
            #pragma unroll
            for (int j = 0; j < 8; j++) {
                mx0 = fmaxf(mx0, fmaxf(p[j][0], p[j][1]));
                mx1 = fmaxf(mx1, fmaxf(p[j][2], p[j][3]));
            }
            mx0 = fmaxf(mx0, __shfl_xor_sync(0xffffffffu, mx0, 1));
            mx0 = fmaxf(mx0, __shfl_xor_sync(0xffffffffu, mx0, 2));
            mx1 = fmaxf(mx1, __shfl_xor_sync(0xffffffffu, mx1, 1));
            mx1 = fmaxf(mx1, __shfl_xor_sync(0xffffffffu, mx1, 2));
            const float mn0 = fmaxf(m0, mx0), mn1 = fmaxf(m1, mx1);
            const float cr0 = exp2_fast(m0 - mn0), cr1 = exp2_fast(m1 - mn1);
            m0 = mn0; m1 = mn1;
            l0 *= cr0; l1 *= cr1;
            #pragma unroll
            for (int jn = 0; jn < 6; jn++) {
                o[jn][0] *= cr0; o[jn][1] *= cr0;
                o[jn][2] *= cr1; o[jn][3] *= cr1;
            }
            #pragma unroll
            for (int j = 0; j < 8; j++) {
                p[j][0] = exp2_fast(p[j][0] - m0);
                p[j][1] = exp2_fast(p[j][1] - m0);
                p[j][2] = exp2_fast(p[j][2] - m1);
                p[j][3] = exp2_fast(p[j][3] - m1);
                l0 += p[j][0] + p[j][1];
                l1 += p[j][2] + p[j][3];
            }

            #pragma unroll
            for (int kc = 0; kc < 4; kc++) {
                uint32_t aP[4];
                aP[0] = packh2(p[2 * kc][0],     p[2 * kc][1]);
                aP[1] = packh2(p[2 * kc][2],     p[2 * kc][3]);
                aP[2] = packh2(p[2 * kc + 1][0], p[2 * kc + 1][1]);
                aP[3] = packh2(p[2 * kc + 1][2], p[2 * kc + 1][3]);
                #pragma unroll
                for (int jp = 0; jp < 3; jp++) {
                    const uint32_t ba = vboff + jp * 16 * VROWB + kc * 32;
                    uint32_t bv[2][2];
                    LDSM4(bv[0][0], bv[0][1], bv[1][0], bv[1][1], sVh + ba);
                    mma16816h(o[2*jp],   aP, bv[0]);
                    mma16816h(o[2*jp+1], aP, bv[1]);
                }
            }
        }
        __syncthreads();
        buf = (buf + 1 == 3) ? 0 : (buf + 1);
    }

    l0 += __shfl_xor_sync(0xffffffffu, l0, 1);
    l0 += __shfl_xor_sync(0xffffffffu, l0, 2);
    l1 += __shfl_xor_sync(0xffffffffu, l1, 1);
    l1 += __shfl_xor_sync(0xffffffffu, l1, 2);
    const float inv0 = 1.0f / l0, inv1 = 1.0f / l1;

    const size_t base0 = ((size_t)(b * SEQ + qbase + g)) * QW + hq * HDIM;
    const size_t base1 = ((size_t)(b * SEQ + qbase + g + 8)) * QW + hq * HDIM;
    #pragma unroll
    for (int jn = 0; jn < 6; jn++) {
        *(uint32_t*)&oa[base0 + jn * 8 + 2 * cq] = packh2(o[jn][0] * inv0, o[jn][1] * inv0);
        *(uint32_t*)&oa[base1 + jn * 8 + 2 * cq] = packh2(o[jn][2] * inv1, o[jn][3] * inv1);
    }
}

// ---------------- launch ----------------
extern "C" void kernel_launch(void* const* d_in, const int* in_sizes, int n_in,
                              void* d_out, int out_size) {
    const float* x      = (const float*)d_in[0];
    const float* Wq     = (const float*)d_in[2];
    const float* Wkv    = (const float*)d_in[3];
    const float* w_norm = (const float*)d_in[4];
    const float* Wk     = (const float*)d_in[5];
    const float* Wv     = (const float*)d_in[6];
    const float* Wo     = (const float*)d_in[7];
    float* out = (float*)d_out;

    float *qkv, *kvout;
    cudaGetSymbolAddress((void**)&qkv,   g_qkv);
    cudaGetSymbolAddress((void**)&kvout, g_kvout);

    __half *x16, *kvh, *kvl, *a16;
    __half *wqkv, *wkv2, *wo;
    __half *akh, *avh;
    cudaGetSymbolAddress((void**)&x16, g_x16);
    cudaGetSymbolAddress((void**)&kvh, g_kvh);  cudaGetSymbolAddress((void**)&kvl, g_kvl);
    cudaGetSymbolAddress((void**)&a16, g_a16);
    cudaGetSymbolAddress((void**)&wqkv, g_wqkv);
    cudaGetSymbolAddress((void**)&wkv2, g_wkv2);
    cudaGetSymbolAddress((void**)&wo,   g_wo);
    cudaGetSymbolAddress((void**)&akh, g_akh);  cudaGetSymbolAddress((void**)&avh, g_avh);

    static cudaStream_t s2 = 0;
    static cudaEvent_t evRoot = 0, evW = 0, evWo = 0;
    if (!s2) {
        cudaFuncSetAttribute(gemm_h,   cudaFuncAttributeMaxDynamicSharedMemorySize, SMEM_GEMMH);
        cudaFuncSetAttribute(gemm1,    cudaFuncAttributeMaxDynamicSharedMemorySize, SMEM_GEMM1);
        cudaFuncSetAttribute(attn_mma, cudaFuncAttributeMaxDynamicSharedMemorySize, SMEM_ATT);
        cudaStreamCreateWithFlags(&s2, cudaStreamNonBlocking);
        cudaEventCreateWithFlags(&evRoot, cudaEventDisableTiming);
        cudaEventCreateWithFlags(&evW, cudaEventDisableTiming);
        cudaEventCreateWithFlags(&evWo, cudaEventDisableTiming);
    }

    dim3 t256(256);
    dim3 ttr(32, 8);

    // fork: weight transposes on s2, x convert on main
    cudaEventRecord(evRoot, 0);
    cudaStreamWaitEvent(s2, evRoot, 0);

    transpose_h<<<dim3(QW / 32,  DIM / 32), ttr, 0, s2>>>(Wq,  wqkv, DIM, QW);
    transpose_h<<<dim3(LAT / 32, DIM / 32), ttr, 0, s2>>>(Wkv, wqkv + (size_t)QW * DIM, DIM, LAT);
    transpose_h<<<dim3(KVW / 32, LAT / 32), ttr, 0, s2>>>(Wk, wkv2, LAT, KVW);
    transpose_h<<<dim3(KVW / 32, LAT / 32), ttr, 0, s2>>>(Wv, wkv2 + (size_t)KVW * LAT, LAT, KVW);
    cudaEventRecord(evW, s2);
    transpose_h<<<dim3(DIM / 32, QW / 32), ttr, 0, s2>>>(Wo, wo, QW, DIM);
    cudaEventRecord(evWo, s2);

    convert_h<<<(ROWS * DIM / 4 + 255) / 256, t256>>>(x, x16, ROWS * DIM / 4);

    // join for qkv weights; [q | kv] = x @ [Wq | Wkv]  (single-A fp16 GEMM)
    cudaStreamWaitEvent(0, evW, 0);
    gemm1<<<dim3(QKVW / G2N, ROWS / GM), 512, SMEM_GEMM1>>>(x16, wqkv, qkv, DIM, QKVW);

    rmsnorm_split<<<ROWS, LAT>>>(qkv, w_norm, kvh, kvl);
    gemm_h<<<dim3(KVW2 / GN, ROWS / GM), t256, SMEM_GEMMH>>>(kvh, kvl, wkv2, kvout, LAT, KVW2);
    reorg_kv<<<dim3(SEQ / 64, BATCH * NLH), t256>>>(kvout, akh, avh);

    attn_mma<<<dim3(SEQ / 128, BATCH * NH), t256, SMEM_ATT>>>(qkv, akh, avh, a16);

    // join for Wo, then out = att @ Wo  (single-A fp16 GEMM)
    cudaStreamWaitEvent(0, evWo, 0);
    gemm1<<<dim3(DIM / G2N, ROWS / GM), 512, SMEM_GEMM1>>>(a16, wo, out, QW, DIM);
}

// round 17
// speedup vs baseline: 1.9302x; 1.0231x over previous
#include <cuda_runtime.h>
#include <cuda_bf16.h>
#include <cuda_fp16.h>
#include <math.h>
#include <stdint.h>

// ---------------- problem constants ----------------
#define BATCH 2
#define SEQ   2048
#define DIM   2048
#define NH    16
#define HDIM  48
#define LAT   256
#define NLH   8
#define ROWS  (BATCH*SEQ)          // 4096
#define QW    (NH*HDIM)            // 768
#define KVW   (NLH*HDIM)           // 384
#define KVW2  (2*KVW)              // 768 (k|v concat)
#define QKVW  (QW+LAT)             // 1024 (q|kv concat)

// ---------------- scratch ----------------
__device__ float g_qkv[ROWS * QKVW];     // q fp32 (cols 0..767); kv cols unused

__device__ __half g_x16[ROWS * DIM];                    // x fp16
__device__ __half g_kvh[ROWS * LAT], g_kvl[ROWS * LAT]; // latent fp16 hi/lo (post-rmsnorm)
__device__ __half g_a16[ROWS * QW];                     // attention out fp16
// transposed fp16 weights
__device__ __half g_wqkv[QKVW * DIM];
__device__ __half g_wkv2[KVW2 * LAT];
__device__ __half g_wo  [DIM * QW];
// attention layouts (fp16): K: [b][kvh][t][hd]   Vt: [b][kvh][hd][t]
__device__ __half g_akh[BATCH*NLH*SEQ*HDIM];
__device__ __half g_avh[BATCH*NLH*HDIM*SEQ];
__device__ float  g_wn32[LAT];   // unused placeholder (w_norm read direct)

// ---------------- helpers ----------------
__device__ __forceinline__ uint32_t smem_u32(const void* p) {
    uint32_t a;
    asm("{ .reg .u64 t; cvta.to.shared.u64 t, %1; cvt.u32.u64 %0, t; }" : "=r"(a) : "l"(p));
    return a;
}

#define CP16(dst, src) \
    asm volatile("cp.async.cg.shared.global [%0], [%1], 16;" :: "r"(dst), "l"(src) : "memory")
#define CP_COMMIT() asm volatile("cp.async.commit_group;" ::: "memory")
#define CP_WAIT0()  asm volatile("cp.async.wait_group 0;" ::: "memory")
#define CP_WAIT1()  asm volatile("cp.async.wait_group 1;" ::: "memory")
#define CP_WAIT2()  asm volatile("cp.async.wait_group 2;" ::: "memory")

#define LDSM4(r0, r1, r2, r3, addr) \
    asm volatile("ldmatrix.sync.aligned.m8n8.x4.shared.b16 {%0,%1,%2,%3}, [%4];" \
        : "=r"(r0), "=r"(r1), "=r"(r2), "=r"(r3) : "r"(addr))

__device__ __forceinline__ void mma16816h(float* c, const uint32_t* a, const uint32_t* b) {
    asm volatile(
        "mma.sync.aligned.m16n8k16.row.col.f32.f16.f16.f32 "
        "{%0,%1,%2,%3}, {%4,%5,%6,%7}, {%8,%9}, {%0,%1,%2,%3};"
        : "+f"(c[0]), "+f"(c[1]), "+f"(c[2]), "+f"(c[3])
        : "r"(a[0]), "r"(a[1]), "r"(a[2]), "r"(a[3]), "r"(b[0]), "r"(b[1]));
}

__device__ __forceinline__ uint32_t packh2(float x, float y) {
    __half2 h = __floats2half2_rn(x, y);
    return *reinterpret_cast<uint32_t*>(&h);
}

__device__ __forceinline__ void splith2(float x, float y, uint32_t& h, uint32_t& l) {
    __half2 hb = __floats2half2_rn(x, y);
    h = *reinterpret_cast<uint32_t*>(&hb);
    float hx = __half2float(__low2half(hb));
    float hy = __half2float(__high2half(hb));
    __half2 lb = __floats2half2_rn(x - hx, y - hy);
    l = *reinterpret_cast<uint32_t*>(&lb);
}

__device__ __forceinline__ float exp2_fast(float x) {
    float r;
    asm("ex2.approx.ftz.f32 %0, %1;" : "=f"(r) : "f"(x));
    return r;
}

// ---------------- common GEMM tile constants ----------------
#define GM 128
#define GK 32
#define ROWB 80

// ===== 512-thread 128x256 single-fp16 GEMM core (macroized mainloop) =====
#define G2N 256
#define S1OFF_A 0
#define S1OFF_B (128*ROWB)             // 10240
#define S1STAGE (128*ROWB + 256*ROWB)  // 30720
#define SMEM_GEMM1 (2*S1STAGE)         // 61440

__device__ __forceinline__ void stage_load1(
    const char* A, const char* B,
    uint32_t sbase, int tid, int m0, int n0, int k0, int K)
{
    {
        const int row = tid >> 2;
        const int cc  = tid & 3;
        const uint32_t so = row * ROWB + cc * 16;
        const size_t gA = ((size_t)(m0 + row) * K + k0) * 2 + cc * 16;
        CP16(sbase + S1OFF_A + so, A + gA);
    }
    #pragma unroll
    for (int u = 0; u < 2; u++) {
        const int s   = tid * 2 + u;
        const int row = s >> 2;
        const int cc  = s & 3;
        const uint32_t so = row * ROWB + cc * 16;
        const size_t gB = ((size_t)(n0 + row) * K + k0) * 2 + cc * 16;
        CP16(sbase + S1OFF_B + so, B + gB);
    }
}

// mainloop body shared by gemm1 / gemm_qkv
#define GEMM1_MAINLOOP(A_, B_, K_)                                              \
    const int nch = (K_) / GK;                                                  \
    stage_load1((const char*)(A_), (const char*)(B_), sb, tid, m0, n0, 0, K_);  \
    CP_COMMIT();                                                                \
    const uint32_t aoff = (uint32_t)((wm * 64 + ((mat & 1) << 3) + mr) * ROWB + ((mat >> 1) << 4)); \
    const uint32_t boff = (uint32_t)((wn * 32 + ((mat >> 1) << 3) + mr) * ROWB + ((mat & 1) << 4)); \
    for (int c = 0; c < nch; c++) {                                             \
        if (c + 1 < nch) {                                                      \
            stage_load1((const char*)(A_), (const char*)(B_),                   \
                        sb + ((c + 1) & 1) * S1STAGE, tid, m0, n0, (c + 1) * GK, K_); \
            CP_COMMIT();                                                        \
            CP_WAIT1();                                                         \
        } else {                                                                \
            CP_WAIT0();                                                         \
        }                                                                       \
        __syncthreads();                                                        \
        const uint32_t sA = sb + (c & 1) * S1STAGE + S1OFF_A;                   \
        const uint32_t sB = sb + (c & 1) * S1STAGE + S1OFF_B;                   \
        _Pragma("unroll")                                                       \
        for (int ks = 0; ks < 2; ks++) {                                        \
            uint32_t bk[4][2];                                                  \
            _Pragma("unroll")                                                   \
            for (int jp = 0; jp < 2; jp++) {                                    \
                const uint32_t ba = boff + jp * 16 * ROWB + ks * 32;            \
                LDSM4(bk[2*jp][0], bk[2*jp][1], bk[2*jp+1][0], bk[2*jp+1][1], sB + ba); \
            }                                                                   \
            _Pragma("unroll")                                                   \
            for (int i = 0; i < 4; i++) {                                       \
                const uint32_t aa = aoff + i * 16 * ROWB + ks * 32;             \
                uint32_t ah[4];                                                 \
                LDSM4(ah[0], ah[1], ah[2], ah[3], sA + aa);                     \
                _Pragma("unroll")                                               \
                for (int j = 0; j < 4; j++)                                     \
                    mma16816h(acc[i][j], ah, bk[j]);                            \
            }                                                                   \
        }                                                                       \
        __syncthreads();                                                        \
    }

__global__ __launch_bounds__(512, 1)
void gemm1(const __half* __restrict__ A, const __half* __restrict__ B,
           float* __restrict__ C, int K, int ldc) {
    extern __shared__ char smem[];
    const uint32_t sb = smem_u32(smem);
    const int tid = threadIdx.x;
    const int wid = tid >> 5, lid = tid & 31;
    const int wm = wid >> 3;
    const int wn = wid & 7;
    const int g = lid >> 2, ctg = lid & 3;
    const int mat = lid >> 3, mr = lid & 7;
    const int m0 = blockIdx.y * GM;
    const int n0 = blockIdx.x * G2N;

    float acc[4][4][4];
    #pragma unroll
    for (int i = 0; i < 4; i++)
        #pragma unroll
        for (int j = 0; j < 4; j++)
            #pragma unroll
            for (int t = 0; t < 4; t++) acc[i][j][t] = 0.0f;

    GEMM1_MAINLOOP(A, B, K)

    #pragma unroll
    for (int i = 0; i < 4; i++) {
        const int r0 = m0 + wm * 64 + i * 16 + g;
        #pragma unroll
        for (int j = 0; j < 4; j++) {
            const int c0 = n0 + wn * 32 + j * 8 + ctg * 2;
            float2 v0 = make_float2(acc[i][j][0], acc[i][j][1]);
            float2 v1 = make_float2(acc[i][j][2], acc[i][j][3]);
            *(float2*)(C + (size_t)r0 * ldc + c0)       = v0;
            *(float2*)(C + (size_t)(r0 + 8) * ldc + c0) = v1;
        }
    }
}

// ===== qkv GEMM with fused rmsnorm on the kv column block (blockIdx.x==3) =====
__global__ __launch_bounds__(512, 1)
void gemm_qkv(const __half* __restrict__ A, const __half* __restrict__ B,
              float* __restrict__ C, const float* __restrict__ wnorm,
              __half* __restrict__ kvh, __half* __restrict__ kvl, int K, int ldc) {
    extern __shared__ char smem[];
    const uint32_t sb = smem_u32(smem);
    const int tid = threadIdx.x;
    const int wid = tid >> 5, lid = tid & 31;
    const int wm = wid >> 3;
    const int wn = wid & 7;
    const int g = lid >> 2, ctg = lid & 3;
    const int mat = lid >> 3, mr = lid & 7;
    const int m0 = blockIdx.y * GM;
    const int n0 = blockIdx.x * G2N;

    float acc[4][4][4];
    #pragma unroll
    for (int i = 0; i < 4; i++)
        #pragma unroll
        for (int j = 0; j < 4; j++)
            #pragma unroll
            for (int t = 0; t < 4; t++) acc[i][j][t] = 0.0f;

    GEMM1_MAINLOOP(A, B, K)

    if (blockIdx.x == 3) {
        // fused rmsnorm: this CTA owns all LAT=256 latent columns for its rows
        __shared__ float ss[128];
        for (int i2 = tid; i2 < 128; i2 += 512) ss[i2] = 0.0f;
        __syncthreads();
        #pragma unroll
        for (int i = 0; i < 4; i++) {
            float s0 = 0.0f, s1 = 0.0f;
            #pragma unroll
            for (int j = 0; j < 4; j++) {
                s0 += acc[i][j][0] * acc[i][j][0] + acc[i][j][1] * acc[i][j][1];
                s1 += acc[i][j][2] * acc[i][j][2] + acc[i][j][3] * acc[i][j][3];
            }
            s0 += __shfl_xor_sync(0xffffffffu, s0, 1);
            s0 += __shfl_xor_sync(0xffffffffu, s0, 2);
            s1 += __shfl_xor_sync(0xffffffffu, s1, 1);
            s1 += __shfl_xor_sync(0xffffffffu, s1, 2);
            if (ctg == 0) {
                atomicAdd(&ss[wm * 64 + i * 16 + g], s0);
                atomicAdd(&ss[wm * 64 + i * 16 + g + 8], s1);
            }
        }
        __syncthreads();
        #pragma unroll
        for (int i = 0; i < 4; i++) {
            const int rl = wm * 64 + i * 16 + g;
            const float inv0 = rsqrtf(ss[rl]     * (1.0f / LAT) + 1e-5f);
            const float inv1 = rsqrtf(ss[rl + 8] * (1.0f / LAT) + 1e-5f);
            const size_t r0 = (size_t)(m0 + rl);
            #pragma unroll
            for (int j = 0; j < 4; j++) {
                const int c = wn * 32 + j * 8 + ctg * 2;   // 0..255 latent col
                const float w0 = wnorm[c], w1 = wnorm[c + 1];
                uint32_t h, l;
                splith2(acc[i][j][0] * inv0 * w0, acc[i][j][1] * inv0 * w1, h, l);
                *(uint32_t*)&kvh[r0 * LAT + c] = h;
                *(uint32_t*)&kvl[r0 * LAT + c] = l;
                splith2(acc[i][j][2] * inv1 * w0, acc[i][j][3] * inv1 * w1, h, l);
                *(uint32_t*)&kvh[(r0 + 8) * LAT + c] = h;
                *(uint32_t*)&kvl[(r0 + 8) * LAT + c] = l;
            }
        }
    } else {
        #pragma unroll
        for (int i = 0; i < 4; i++) {
            const int r0 = m0 + wm * 64 + i * 16 + g;
            #pragma unroll
            for (int j = 0; j < 4; j++) {
                const int c0 = n0 + wn * 32 + j * 8 + ctg * 2;
                float2 v0 = make_float2(acc[i][j][0], acc[i][j][1]);
                float2 v1 = make_float2(acc[i][j][2], acc[i][j][3]);
                *(float2*)(C + (size_t)r0 * ldc + c0)       = v0;
                *(float2*)(C + (size_t)(r0 + 8) * ldc + c0) = v1;
            }
        }
    }
}

// ===== kv2 GEMM (A fp16 hi/lo) with fused K/V reorg epilogue =====
#define GN 128
#define HT_A (128 * ROWB)
#define HOFF_AH 0
#define HOFF_AL (HT_A)
#define HOFF_B  (2*HT_A)
#define HSTAGE  (3*HT_A)           // 30720
#define SMEM_GEMMH (2*HSTAGE)      // 61440

__device__ __forceinline__ void stage_load_h(
    const char* Ah, const char* Al, const char* B,
    uint32_t sbase, int tid, int m0, int n0, int k0, int K)
{
    #pragma unroll
    for (int u = 0; u < 2; u++) {
        const int s   = tid * 2 + u;
        const int row = s >> 2;
        const int cc  = s & 3;
        const uint32_t so = row * ROWB + cc * 16;
        const size_t gA = ((size_t)(m0 + row) * K + k0) * 2 + cc * 16;
        const size_t gB = ((size_t)(n0 + row) * K + k0) * 2 + cc * 16;
        CP16(sbase + HOFF_AH + so, Ah + gA);
        CP16(sbase + HOFF_AL + so, Al + gA);
        CP16(sbase + HOFF_B  + so, B + gB);
    }
}

__global__ __launch_bounds__(256, 2)
void gemm_kv2(const __half* __restrict__ Ahi, const __half* __restrict__ Alo,
              const __half* __restrict__ B,
              __half* __restrict__ akh, __half* __restrict__ avh, int K) {
    extern __shared__ char smem[];
    const uint32_t sb = smem_u32(smem);
    const int tid = threadIdx.x;
    const int wid = tid >> 5, lid = tid & 31;
    const int wm = wid >> 2;
    const int wn = wid & 3;
    const int g = lid >> 2, ctg = lid & 3;
    const int mat = lid >> 3, mr = lid & 7;
    const int m0 = blockIdx.y * GM;
    const int n0 = blockIdx.x * GN;

    float acc[4][4][4];
    #pragma unroll
    for (int i = 0; i < 4; i++)
        #pragma unroll
        for (int j = 0; j < 4; j++)
            #pragma unroll
            for (int t = 0; t < 4; t++) acc[i][j][t] = 0.0f;

    const int nch = K / GK;
    stage_load_h((const char*)Ahi, (const char*)Alo, (const char*)B,
                 sb, tid, m0, n0, 0, K);
    CP_COMMIT();

    const uint32_t aoff = (uint32_t)((wm * 64 + ((mat & 1) << 3) + mr) * ROWB + ((mat >> 1) << 4));
    const uint32_t boff = (uint32_t)((wn * 32 + ((mat >> 1) << 3) + mr) * ROWB + ((mat & 1) << 4));

    for (int c = 0; c < nch; c++) {
        if (c + 1 < nch) {
            stage_load_h((const char*)Ahi, (const char*)Alo, (const char*)B,
                         sb + ((c + 1) & 1) * HSTAGE, tid, m0, n0, (c + 1) * GK, K);
            CP_COMMIT();
            CP_WAIT1();
        } else {
            CP_WAIT0();
        }
        __syncthreads();

        const uint32_t sAh = sb + (c & 1) * HSTAGE + HOFF_AH;
        const uint32_t sAl = sb + (c & 1) * HSTAGE + HOFF_AL;
        const uint32_t sB  = sb + (c & 1) * HSTAGE + HOFF_B;

        #pragma unroll
        for (int ks = 0; ks < 2; ks++) {
            uint32_t bk[4][2];
            #pragma unroll
            for (int jp = 0; jp < 2; jp++) {
                const uint32_t ba = boff + jp * 16 * ROWB + ks * 32;
                LDSM4(bk[2*jp][0], bk[2*jp][1], bk[2*jp+1][0], bk[2*jp+1][1], sB + ba);
            }
            #pragma unroll
            for (int i = 0; i < 4; i++) {
                const uint32_t aa = aoff + i * 16 * ROWB + ks * 32;
                uint32_t ah[4], al[4];
                LDSM4(ah[0], ah[1], ah[2], ah[3], sAh + aa);
                LDSM4(al[0], al[1], al[2], al[3], sAl + aa);
                #pragma unroll
                for (int j = 0; j < 4; j++) {
                    mma16816h(acc[i][j], ah, bk[j]);
                    mma16816h(acc[i][j], al, bk[j]);
                }
            }
        }
        __syncthreads();
    }

    // ---- fused reorg epilogue: K -> [b][kvh][t][hd], V -> [b][kvh][hd][t]
    #pragma unroll
    for (int i = 0; i < 4; i++) {
        const int r0 = m0 + wm * 64 + i * 16 + g;
        const int bb = r0 >> 11, t = r0 & 2047;          // r0+8 has same bb
        #pragma unroll
        for (int j = 0; j < 4; j++) {
            const int c0 = n0 + wn * 32 + j * 8 + ctg * 2;
            if (c0 < KVW) {
                const int kk = c0 / HDIM, hd = c0 % HDIM;
                const size_t base = ((size_t)(bb * NLH + kk)) * SEQ;
                *(uint32_t*)&akh[(base + t) * HDIM + hd]     = packh2(acc[i][j][0], acc[i][j][1]);
                *(uint32_t*)&akh[(base + t + 8) * HDIM + hd] = packh2(acc[i][j][2], acc[i][j][3]);
            } else {
                const int cv = c0 - KVW;
                const int kk = cv / HDIM, hd = cv % HDIM;
                const size_t base = ((size_t)(bb * NLH + kk)) * HDIM;
                avh[(base + hd) * SEQ + t]         = __float2half(acc[i][j][0]);
                avh[(base + hd + 1) * SEQ + t]     = __float2half(acc[i][j][1]);
                avh[(base + hd) * SEQ + t + 8]     = __float2half(acc[i][j][2]);
                avh[(base + hd + 1) * SEQ + t + 8] = __float2half(acc[i][j][3]);
            }
        }
    }
}

// ---------------- fp32 -> fp16 convert ----------------
__global__ __launch_bounds__(256)
void convert_h(const float* __restrict__ in, __half* __restrict__ o16, int n4) {
    int i = blockIdx.x * 256 + threadIdx.x;
    if (i >= n4) return;
    float4 v = ((const float4*)in)[i];
    ((uint32_t*)o16)[2 * i]     = packh2(v.x, v.y);
    ((uint32_t*)o16)[2 * i + 1] = packh2(v.z, v.w);
}

// ---------------- W[K,N] fp32 -> Wt[N,K] fp16 ----------------
__global__ __launch_bounds__(256)
void transpose_h(const float* __restrict__ W, __half* __restrict__ t16, int K, int N) {
    __shared__ float ts[32][33];
    const int tx = threadIdx.x;
    const int ty = threadIdx.y;
    const int x0 = blockIdx.x * 32;
    const int y0 = blockIdx.y * 32;
    #pragma unroll
    for (int j = ty; j < 32; j += 8)
        ts[j][tx] = W[(size_t)(y0 + j) * N + x0 + tx];
    __syncthreads();
    #pragma unroll
    for (int j = ty; j < 32; j += 8) {
        size_t o = (size_t)(x0 + j) * K + y0 + tx;
        t16[o] = __float2half(ts[tx][j]);
    }
}

// ---------------- tensor-core causal flash attention ----------------
#define KROWB 112
#define VROWB 144
#define A_KH 0
#define A_VH 7168
#define A_STAGE 14080
#define SMEM_ATT (3*A_STAGE)     // 42240

__device__ __forceinline__ void attn_stage(
    uint32_t sbase, const __half* kb, const __half* vb, int tid)
{
    #pragma unroll
    for (int t = 0; t < 3; t++) {
        const int c = tid + t * 256;
        if (c < 384) {
            const int r = c / 6, qd = c - r * 6;
            CP16(sbase + A_KH + r * KROWB + qd * 16, kb + r * HDIM + qd * 8);
        } else {
            const int idx = c - 384;
            const int r = idx >> 3, qd = idx & 7;
            CP16(sbase + A_VH + r * VROWB + qd * 16, vb + (size_t)r * SEQ + qd * 8);
        }
    }
}

__global__ __launch_bounds__(256, 2)
void attn_mma(const float* __restrict__ q,
              const __half* __restrict__ kh, const __half* __restrict__ vth,
              __half* __restrict__ oa) {
    extern __shared__ char smem[];
    const uint32_t sb = smem_u32(smem);

    const int qt = gridDim.x - 1 - blockIdx.x;        // longest first
    const int bh = blockIdx.y;
    const int b = bh / NH, hq = bh % NH;
    const int bkvh = b * NLH + hq / (NH / NLH);
    const int tid = threadIdx.x;
    const int wid = tid >> 5, lid = tid & 31;
    const int g = lid >> 2, cq = lid & 3;
    const int mat = lid >> 3, mr = lid & 7;
    const int qbase = qt * 128 + wid * 16;
    const float scale = rsqrtf((float)HDIM) * 1.44269504088896340736f;

    uint32_t aqh[3][4], aql[3][4];
    {
        const float* qp0 = q + ((size_t)(b * SEQ + qbase + g)) * QKVW + hq * HDIM;
        const float* qp1 = q + ((size_t)(b * SEQ + qbase + g + 8)) * QKVW + hq * HDIM;
        #pragma unroll
        for (int kk = 0; kk < 3; kk++) {
            float2 f0 = *(const float2*)(qp0 + kk * 16 + 2 * cq);
            float2 f1 = *(const float2*)(qp1 + kk * 16 + 2 * cq);
            float2 f2 = *(const float2*)(qp0 + kk * 16 + 2 * cq + 8);
            float2 f3 = *(const float2*)(qp1 + kk * 16 + 2 * cq + 8);
            splith2(f0.x * scale, f0.y * scale, aqh[kk][0], aql[kk][0]);
            splith2(f1.x * scale, f1.y * scale, aqh[kk][1], aql[kk][1]);
            splith2(f2.x * scale, f2.y * scale, aqh[kk][2], aql[kk][2]);
            splith2(f3.x * scale, f3.y * scale, aqh[kk][3], aql[kk][3]);
        }
    }

    float o[6][4];
    #pragma unroll
    for (int jn = 0; jn < 6; jn++)
        #pragma unroll
        for (int t = 0; t < 4; t++) o[jn][t] = 0.0f;
    float m0 = -1e30f, m1 = -1e30f, l0 = 0.0f, l1 = 0.0f;

    const __half* kB = kh  + (size_t)bkvh * SEQ * HDIM;
    const __half* vB = vth + (size_t)bkvh * HDIM * SEQ;

    const uint32_t kboff = (uint32_t)((((mat >> 1) << 3) + mr) * KROWB + ((mat & 1) << 4));
    const uint32_t vboff = (uint32_t)((((mat >> 1) << 3) + mr) * VROWB + ((mat & 1) << 4));

    const int nkt = 2 * qt + 2;
    attn_stage(sb, kB, vB, tid);
    CP_COMMIT();
    attn_stage(sb + A_STAGE, kB + 64 * HDIM, vB + 64, tid);
    CP_COMMIT();

    int buf = 0;
    for (int kt = 0; kt < nkt; kt++) {
        if (kt + 2 < nkt) {
            const int nb = (buf + 2) % 3;
            attn_stage(sb + nb * A_STAGE, kB + (kt + 2) * 64 * HDIM, vB + (kt + 2) * 64, tid);
            CP_COMMIT();
            CP_WAIT2();
        } else if (kt + 1 < nkt) {
            CP_WAIT1();
        } else {
            CP_WAIT0();
        }
        __syncthreads();

        const bool full_skip = (kt * 64 > qbase + 15);
        if (!full_skip) {
            const uint32_t st = sb + buf * A_STAGE;
            const uint32_t sKh = st + A_KH;
            const uint32_t sVh = st + A_VH;

            float p[8][4];
            #pragma unroll
            for (int j = 0; j < 8; j++)
                p[j][0] = p[j][1] = p[j][2] = p[j][3] = 0.0f;
            #pragma unroll
            for (int kk = 0; kk < 3; kk++) {
                #pragma unroll
                for (int jp = 0; jp < 4; jp++) {
                    const uint32_t ba = kboff + jp * 16 * KROWB + kk * 32;
                    uint32_t bk[2][2];
                    LDSM4(bk[0][0], bk[0][1], bk[1][0], bk[1][1], sKh + ba);
                    mma16816h(p[2*jp],   aqh[kk], bk[0]);
                    mma16816h(p[2*jp],   aql[kk], bk[0]);
                    mma16816h(p[2*jp+1], aqh[kk], bk[1]);
                    mma16816h(p[2*jp+1], aql[kk], bk[1]);
                }
            }

            if (kt * 64 + 63 > qbase) {
                const int qr0 = qbase + g;
                #pragma unroll
                for (int j = 0; j < 8; j++) {
                    const int key0 = kt * 64 + j * 8 + 2 * cq;
                    if (key0 > qr0)         p[j][0] = -1e30f;
                    if (key0 + 1 > qr0)     p[j][1] = -1e30f;
                    if (key0 > qr0 + 8)     p[j][2] = -1e30f;
                    if (key0 + 1 > qr0 + 8) p[j][3] = -1e30f;
                }
            }

            float mx0 = -1e30f, mx1 = -1e30f;
            #pragma unroll
            for (int j = 0; j < 8; j++) {
                mx0 = fmaxf(mx0, fmaxf(p[j][0], p[j][1]));
                mx1 = fmaxf(mx1, fmaxf(p[j][2], p[j][3]));
            }
            mx0 = fmaxf(mx0, __shfl_xor_sync(0xffffffffu, mx0, 1));
            mx0 = fmaxf(mx0, __shfl_xor_sync(0xffffffffu, mx0, 2));
            mx1 = fmaxf(mx1, __shfl_xor_sync(0xffffffffu, mx1, 1));
            mx1 = fmaxf(mx1, __shfl_xor_sync(0xffffffffu, mx1, 2));
            const float mn0 = fmaxf(m0, mx0), mn1 = fmaxf(m1, mx1);
            const float cr0 = exp2_fast(m0 - mn0), cr1 = exp2_fast(m1 - mn1);
            m0 = mn0; m1 = mn1;
            l0 *= cr0; l1 *= cr1;
            #pragma unroll
            for (int jn = 0; jn < 6; jn++) {
                o[jn][0] *= cr0; o[jn][1] *= cr0;
                o[jn][2] *= cr1; o[jn][3] *= cr1;
            }
            #pragma unroll
            for (int j = 0; j < 8; j++) {
                p[j][0] = exp2_fast(p[j][0] - m0);
                p[j][1] = exp2_fast(p[j][1] - m0);
                p[j][2] = exp2_fast(p[j][2] - m1);
                p[j][3] = exp2_fast(p[j][3] - m1);
                l0 += p[j][0] + p[j][1];
                l1 += p[j][2] + p[j][3];
            }

            #pragma unroll
            for (int kc = 0; kc < 4; kc++) {
                uint32_t aP[4];
                aP[0] = packh2(p[2 * kc][0],     p[2 * kc][1]);
                aP[1] = packh2(p[2 * kc][2],     p[2 * kc][3]);
                aP[2] = packh2(p[2 * kc + 1][0], p[2 * kc + 1][1]);
                aP[3] = packh2(p[2 * kc + 1][2], p[2 * kc + 1][3]);
                #pragma unroll
                for (int jp = 0; jp < 3; jp++) {
                    const uint32_t ba = vboff + jp * 16 * VROWB + kc * 32;
                    uint32_t bv[2][2];
                    LDSM4(bv[0][0], bv[0][1], bv[1][0], bv[1][1], sVh + ba);
                    mma16816h(o[2*jp],   aP, bv[0]);
                    mma16816h(o[2*jp+1], aP, bv[1]);
                }
            }
        }
        __syncthreads();
        buf = (buf + 1 == 3) ? 0 : (buf + 1);
    }

    l0 += __shfl_xor_sync(0xffffffffu, l0, 1);
    l0 += __shfl_xor_sync(0xffffffffu, l0, 2);
    l1 += __shfl_xor_sync(0xffffffffu, l1, 1);
    l1 += __shfl_xor_sync(0xffffffffu, l1, 2);
    const float inv0 = 1.0f / l0, inv1 = 1.0f / l1;

    const size_t base0 = ((size_t)(b * SEQ + qbase + g)) * QW + hq * HDIM;
    const size_t base1 = ((size_t)(b * SEQ + qbase + g + 8)) * QW + hq * HDIM;
    #pragma unroll
    for (int jn = 0; jn < 6; jn++) {
        *(uint32_t*)&oa[base0 + jn * 8 + 2 * cq] = packh2(o[jn][0] * inv0, o[jn][1] * inv0);
        *(uint32_t*)&oa[base1 + jn * 8 + 2 * cq] = packh2(o[jn][2] * inv1, o[jn][3] * inv1);
    }
}

// ---------------- launch ----------------
extern "C" void kernel_launch(void* const* d_in, const int* in_sizes, int n_in,
                              void* d_out, int out_size) {
    const float* x      = (const float*)d_in[0];
    const float* Wq     = (const float*)d_in[2];
    const float* Wkv    = (const float*)d_in[3];
    const float* w_norm = (const float*)d_in[4];
    const float* Wk     = (const float*)d_in[5];
    const float* Wv     = (const float*)d_in[6];
    const float* Wo     = (const float*)d_in[7];
    float* out = (float*)d_out;

    float* qkv;
    cudaGetSymbolAddress((void**)&qkv, g_qkv);

    __half *x16, *kvh, *kvl, *a16;
    __half *wqkv, *wkv2, *wo;
    __half *akh, *avh;
    cudaGetSymbolAddress((void**)&x16, g_x16);
    cudaGetSymbolAddress((void**)&kvh, g_kvh);  cudaGetSymbolAddress((void**)&kvl, g_kvl);
    cudaGetSymbolAddress((void**)&a16, g_a16);
    cudaGetSymbolAddress((void**)&wqkv, g_wqkv);
    cudaGetSymbolAddress((void**)&wkv2, g_wkv2);
    cudaGetSymbolAddress((void**)&wo,   g_wo);
    cudaGetSymbolAddress((void**)&akh, g_akh);  cudaGetSymbolAddress((void**)&avh, g_avh);

    static cudaStream_t s2 = 0;
    static cudaEvent_t evRoot = 0, evW = 0, evWo = 0;
    if (!s2) {
        cudaFuncSetAttribute(gemm1,    cudaFuncAttributeMaxDynamicSharedMemorySize, SMEM_GEMM1);
        cudaFuncSetAttribute(gemm_qkv, cudaFuncAttributeMaxDynamicSharedMemorySize, SMEM_GEMM1);
        cudaFuncSetAttribute(gemm_kv2, cudaFuncAttributeMaxDynamicSharedMemorySize, SMEM_GEMMH);
        cudaFuncSetAttribute(attn_mma, cudaFuncAttributeMaxDynamicSharedMemorySize, SMEM_ATT);
        cudaStreamCreateWithFlags(&s2, cudaStreamNonBlocking);
        cudaEventCreateWithFlags(&evRoot, cudaEventDisableTiming);
        cudaEventCreateWithFlags(&evW, cudaEventDisableTiming);
        cudaEventCreateWithFlags(&evWo, cudaEventDisableTiming);
    }

    dim3 t256(256);
    dim3 ttr(32, 8);

    // fork: weight transposes on s2, x convert on main
    cudaEventRecord(evRoot, 0);
    cudaStreamWaitEvent(s2, evRoot, 0);

    transpose_h<<<dim3(QW / 32,  DIM / 32), ttr, 0, s2>>>(Wq,  wqkv, DIM, QW);
    transpose_h<<<dim3(LAT / 32, DIM / 32), ttr, 0, s2>>>(Wkv, wqkv + (size_t)QW * DIM, DIM, LAT);
    transpose_h<<<dim3(KVW / 32, LAT / 32), ttr, 0, s2>>>(Wk, wkv2, LAT, KVW);
    transpose_h<<<dim3(KVW / 32, LAT / 32), ttr, 0, s2>>>(Wv, wkv2 + (size_t)KVW * LAT, LAT, KVW);
    cudaEventRecord(evW, s2);
    transpose_h<<<dim3(DIM / 32, QW / 32), ttr, 0, s2>>>(Wo, wo, QW, DIM);
    cudaEventRecord(evWo, s2);

    convert_h<<<(ROWS * DIM / 4 + 255) / 256, t256>>>(x, x16, ROWS * DIM / 4);

    // join for qkv weights; [q | kv] = x @ [Wq | Wkv], rmsnorm fused on kv block
    cudaStreamWaitEvent(0, evW, 0);
    gemm_qkv<<<dim3(QKVW / G2N, ROWS / GM), 512, SMEM_GEMM1>>>(
        x16, wqkv, qkv, w_norm, kvh, kvl, DIM, QKVW);

    // [k|v] = latent @ [Wk|Wv], reorg fused in epilogue
    gemm_kv2<<<dim3(KVW2 / GN, ROWS / GM), t256, SMEM_GEMMH>>>(kvh, kvl, wkv2, akh, avh, LAT);

    attn_mma<<<dim3(SEQ / 128, BATCH * NH), t256, SMEM_ATT>>>(qkv, akh, avh, a16);

    // join for Wo, then out = att @ Wo
    cudaStreamWaitEvent(0, evWo, 0);
    gemm1<<<dim3(DIM / G2N, ROWS / GM), 512, SMEM_GEMM1>>>(a16, wo, out, QW, DIM);
}